// round 3
// baseline (speedup 1.0000x reference)
#include <cuda_runtime.h>
#include <math.h>

#define Bb  2
#define Ss  2048
#define Hh  1024
#define NHh 16
#define HDd 64

// Scratch (allocation-free rule: __device__ globals)
__device__ float g_Q[(size_t)Bb * NHh * Ss * HDd];
__device__ float g_K[(size_t)Bb * NHh * Ss * HDd];
__device__ float g_V[(size_t)Bb * NHh * Ss * HDd];
__device__ float g_ctx[(size_t)Bb * Ss * Hh];
__device__ float g_gain[(size_t)Bb * Ss * NHh];

// ---------------------------------------------------------------------------
// K1: per-(b,s) gating. gain[b,s,h] = (1+sig(pros@pg_w+pg_b)[h])
//                                   * (1+0.5*sig(hs@mg_w+mg_b)) / sqrt(HD)
// ---------------------------------------------------------------------------
__global__ __launch_bounds__(256) void gate_kernel(
    const float* __restrict__ hs, const float* __restrict__ pros,
    const float* __restrict__ pg_w, const float* __restrict__ pg_b,
    const float* __restrict__ mg_w, const float* __restrict__ mg_b)
{
    int bs = blockIdx.x;                 // 0..B*S-1
    const float* x = hs + (size_t)bs * Hh;
    int tid = threadIdx.x;

    float part = 0.f;
    for (int i = tid; i < Hh; i += 256) part += x[i] * mg_w[i];
    __shared__ float red[256];
    red[tid] = part; __syncthreads();
    for (int s = 128; s > 0; s >>= 1) {
        if (tid < s) red[tid] += red[tid + s];
        __syncthreads();
    }
    float mem = 1.0f + 0.5f / (1.0f + __expf(-(red[0] + mg_b[0])));

    if (tid < NHh) {
        const float* p = pros + (size_t)bs * 4;
        float a = p[0] * pg_w[0 * NHh + tid] + p[1] * pg_w[1 * NHh + tid]
                + p[2] * pg_w[2 * NHh + tid] + p[3] * pg_w[3 * NHh + tid]
                + pg_b[tid];
        float pg = 1.0f + 1.0f / (1.0f + __expf(-a));
        g_gain[(size_t)bs * NHh + tid] = pg * mem * 0.125f;  // includes 1/sqrt(64)
    }
}

// ---------------------------------------------------------------------------
// K2: QKV projection. X[4096,1024] @ W[1024,1024] + b.
// 128x128x8 fp32 tiles, 8x8 per thread. blockIdx.z selects Q/K/V.
// Epilogue: head-major [b,h,s,d]; z==0 applies the folded gain.
// ---------------------------------------------------------------------------
__global__ __launch_bounds__(256) void qkv_gemm(
    const float* __restrict__ X,
    const float* __restrict__ Wq, const float* __restrict__ bq,
    const float* __restrict__ Wk, const float* __restrict__ bk,
    const float* __restrict__ Wv, const float* __restrict__ bv)
{
    const int z = blockIdx.z;
    const float* W    = (z == 0) ? Wq : (z == 1) ? Wk : Wv;
    const float* bias = (z == 0) ? bq : (z == 1) ? bk : bv;
    float* out        = (z == 0) ? g_Q : (z == 1) ? g_K : g_V;

    const int n0 = blockIdx.x * 128;
    const int m0 = blockIdx.y * 128;

    __shared__ float As[8][128];
    __shared__ float Bs[8][128];

    int tid = threadIdx.x;
    int ry = tid >> 4, cx = tid & 15;

    float acc[8][8];
#pragma unroll
    for (int i = 0; i < 8; i++)
#pragma unroll
        for (int j = 0; j < 8; j++) acc[i][j] = 0.f;

    for (int kt = 0; kt < 1024; kt += 8) {
        {   // A tile 128x8, transposed into As[k][m]
            int row = tid >> 1, kq = tid & 1;
            float4 v = *(const float4*)(X + (size_t)(m0 + row) * 1024 + kt + kq * 4);
            As[kq * 4 + 0][row] = v.x; As[kq * 4 + 1][row] = v.y;
            As[kq * 4 + 2][row] = v.z; As[kq * 4 + 3][row] = v.w;
        }
        {   // B tile 8x128
            int k = tid >> 5, nq = tid & 31;
            float4 v = *(const float4*)(W + (size_t)(kt + k) * 1024 + n0 + nq * 4);
            *(float4*)&Bs[k][nq * 4] = v;
        }
        __syncthreads();
#pragma unroll
        for (int k = 0; k < 8; k++) {
            float a[8], b[8];
            *(float4*)&a[0] = *(float4*)&As[k][ry * 8];
            *(float4*)&a[4] = *(float4*)&As[k][ry * 8 + 4];
            *(float4*)&b[0] = *(float4*)&Bs[k][cx * 8];
            *(float4*)&b[4] = *(float4*)&Bs[k][cx * 8 + 4];
#pragma unroll
            for (int i = 0; i < 8; i++)
#pragma unroll
                for (int j = 0; j < 8; j++) acc[i][j] += a[i] * b[j];
        }
        __syncthreads();
    }

#pragma unroll
    for (int i = 0; i < 8; i++) {
        int m = m0 + ry * 8 + i;
        int bidx = m / Ss, srow = m % Ss;
#pragma unroll
        for (int j = 0; j < 8; j++) {
            int col = n0 + cx * 8 + j;
            float v = acc[i][j] + bias[col];
            int h = col >> 6, d = col & 63;
            if (z == 0) v *= g_gain[(size_t)m * NHh + h];
            out[(((size_t)(bidx * NHh + h)) * Ss + srow) * HDd + d] = v;
        }
    }
}

// ---------------------------------------------------------------------------
// K3: raw scores, lower-triangle tiles only. 128x128 outputs per block,
// K-dim = 64 processed in two d-chunks of 32. Writes straight into d_out.
// ---------------------------------------------------------------------------
__global__ __launch_bounds__(256) void scores_kernel(float* __restrict__ attn)
{
    int kt = blockIdx.x, qt = blockIdx.y, bh = blockIdx.z;
    if (kt > qt) return;

    const float* Qg = g_Q + (size_t)bh * Ss * HDd;
    const float* Kg = g_K + (size_t)bh * Ss * HDd;

    __shared__ float Qs[32][128];
    __shared__ float Ks[32][128];

    int tid = threadIdx.x;
    int ry = tid >> 4, cx = tid & 15;
    int q0 = qt * 128, k0 = kt * 128;

    float acc[8][8];
#pragma unroll
    for (int i = 0; i < 8; i++)
#pragma unroll
        for (int j = 0; j < 8; j++) acc[i][j] = 0.f;

    for (int dc = 0; dc < 64; dc += 32) {
        for (int f = tid; f < 1024; f += 256) {
            int row = f >> 3, q4 = f & 7;
            float4 v = *(const float4*)(Qg + (size_t)(q0 + row) * HDd + dc + q4 * 4);
            Qs[q4 * 4 + 0][row] = v.x; Qs[q4 * 4 + 1][row] = v.y;
            Qs[q4 * 4 + 2][row] = v.z; Qs[q4 * 4 + 3][row] = v.w;
            float4 w = *(const float4*)(Kg + (size_t)(k0 + row) * HDd + dc + q4 * 4);
            Ks[q4 * 4 + 0][row] = w.x; Ks[q4 * 4 + 1][row] = w.y;
            Ks[q4 * 4 + 2][row] = w.z; Ks[q4 * 4 + 3][row] = w.w;
        }
        __syncthreads();
#pragma unroll 8
        for (int k = 0; k < 32; k++) {
            float a[8], b[8];
            *(float4*)&a[0] = *(float4*)&Qs[k][ry * 8];
            *(float4*)&a[4] = *(float4*)&Qs[k][ry * 8 + 4];
            *(float4*)&b[0] = *(float4*)&Ks[k][cx * 8];
            *(float4*)&b[4] = *(float4*)&Ks[k][cx * 8 + 4];
#pragma unroll
            for (int i = 0; i < 8; i++)
#pragma unroll
                for (int j = 0; j < 8; j++) acc[i][j] += a[i] * b[j];
        }
        __syncthreads();
    }

    float* abase = attn + (size_t)bh * Ss * Ss;
#pragma unroll
    for (int i = 0; i < 8; i++) {
        int gi = q0 + ry * 8 + i;
#pragma unroll
        for (int j = 0; j < 8; j++) {
            int gj = k0 + cx * 8 + j;
            abase[(size_t)gi * Ss + gj] = (gj <= gi) ? acc[i][j] : -INFINITY;
        }
    }
}

// ---------------------------------------------------------------------------
// K4: row softmax in-place + zero-fill above the diagonal.
// One block per row; row held in registers (<= 8 elems/thread).
// ---------------------------------------------------------------------------
__global__ __launch_bounds__(256) void softmax_kernel(float* __restrict__ attn)
{
    int i = blockIdx.x, h = blockIdx.y, b = blockIdx.z;
    float* row = attn + ((size_t)(b * NHh + h) * Ss + i) * Ss;
    int n = i + 1;
    int tid = threadIdx.x;

    float vals[8];
    int cnt = 0;
    float mx = -INFINITY;
    for (int j = tid; j < n; j += 256) {
        float s = row[j];
        vals[cnt++] = s;
        mx = fmaxf(mx, s);
    }

    __shared__ float red[256];
    red[tid] = mx; __syncthreads();
    for (int s = 128; s > 0; s >>= 1) {
        if (tid < s) red[tid] = fmaxf(red[tid], red[tid + s]);
        __syncthreads();
    }
    mx = red[0];
    __syncthreads();

    float sum = 0.f;
    for (int c = 0; c < cnt; c++) {
        vals[c] = __expf(vals[c] - mx);
        sum += vals[c];
    }
    red[tid] = sum; __syncthreads();
    for (int s = 128; s > 0; s >>= 1) {
        if (tid < s) red[tid] += red[tid + s];
        __syncthreads();
    }
    float inv = 1.0f / red[0];

    cnt = 0;
    for (int j = tid; j < n; j += 256) row[j] = vals[cnt++] * inv;
    for (int j = n + tid; j < Ss; j += 256) row[j] = 0.f;
}

// ---------------------------------------------------------------------------
// K5: context = attn @ V (causal: skip k-tiles beyond the diagonal).
// 128x64 outputs per block, 8x4 per thread, BK=64.
// ---------------------------------------------------------------------------
__global__ __launch_bounds__(256) void pv_kernel(const float* __restrict__ attn)
{
    int qt = blockIdx.x, bh = blockIdx.y;
    int b = bh / NHh, h = bh % NHh;
    const float* Vg = g_V + (size_t)bh * Ss * HDd;
    const float* abase = attn + (size_t)bh * Ss * Ss;

    __shared__ float As[64][128];  // [k][m]
    __shared__ float Bs[64][64];   // [k][d]

    int tid = threadIdx.x;
    int ry = tid >> 4, cx = tid & 15;
    int q0 = qt * 128;

    float acc[8][4];
#pragma unroll
    for (int i = 0; i < 8; i++)
#pragma unroll
        for (int j = 0; j < 4; j++) acc[i][j] = 0.f;

    int kend = (qt + 1) * 128;
    for (int k0 = 0; k0 < kend; k0 += 64) {
        for (int f = tid; f < 2048; f += 256) {   // 128 rows x 16 float4
            int row = f >> 4, q4 = f & 15;
            float4 v = *(const float4*)(abase + (size_t)(q0 + row) * Ss + k0 + q4 * 4);
            As[q4 * 4 + 0][row] = v.x; As[q4 * 4 + 1][row] = v.y;
            As[q4 * 4 + 2][row] = v.z; As[q4 * 4 + 3][row] = v.w;
        }
        for (int f = tid; f < 1024; f += 256) {   // 64 rows x 16 float4
            int kk = f >> 4, q4 = f & 15;
            *(float4*)&Bs[kk][q4 * 4] =
                *(const float4*)(Vg + (size_t)(k0 + kk) * HDd + q4 * 4);
        }
        __syncthreads();
#pragma unroll 8
        for (int k = 0; k < 64; k++) {
            float a[8], bvec[4];
            *(float4*)&a[0] = *(float4*)&As[k][ry * 8];
            *(float4*)&a[4] = *(float4*)&As[k][ry * 8 + 4];
            *(float4*)&bvec[0] = *(float4*)&Bs[k][cx * 4];
#pragma unroll
            for (int i = 0; i < 8; i++)
#pragma unroll
                for (int j = 0; j < 4; j++) acc[i][j] += a[i] * bvec[j];
        }
        __syncthreads();
    }

#pragma unroll
    for (int i = 0; i < 8; i++) {
        int srow = q0 + ry * 8 + i;
#pragma unroll
        for (int j = 0; j < 4; j++) {
            int d = cx * 4 + j;
            g_ctx[((size_t)b * Ss + srow) * Hh + h * 64 + d] = acc[i][j];
        }
    }
}

// ---------------------------------------------------------------------------
// K6: output projection. g_ctx[4096,1024] @ o_w + o_b -> d_out[0 : B*S*H]
// ---------------------------------------------------------------------------
__global__ __launch_bounds__(256) void out_gemm(
    const float* __restrict__ W, const float* __restrict__ bias,
    float* __restrict__ out)
{
    const float* X = g_ctx;
    const int n0 = blockIdx.x * 128;
    const int m0 = blockIdx.y * 128;

    __shared__ float As[8][128];
    __shared__ float Bs[8][128];

    int tid = threadIdx.x;
    int ry = tid >> 4, cx = tid & 15;

    float acc[8][8];
#pragma unroll
    for (int i = 0; i < 8; i++)
#pragma unroll
        for (int j = 0; j < 8; j++) acc[i][j] = 0.f;

    for (int kt = 0; kt < 1024; kt += 8) {
        {
            int row = tid >> 1, kq = tid & 1;
            float4 v = *(const float4*)(X + (size_t)(m0 + row) * 1024 + kt + kq * 4);
            As[kq * 4 + 0][row] = v.x; As[kq * 4 + 1][row] = v.y;
            As[kq * 4 + 2][row] = v.z; As[kq * 4 + 3][row] = v.w;
        }
        {
            int k = tid >> 5, nq = tid & 31;
            float4 v = *(const float4*)(W + (size_t)(kt + k) * 1024 + n0 + nq * 4);
            *(float4*)&Bs[k][nq * 4] = v;
        }
        __syncthreads();
#pragma unroll
        for (int k = 0; k < 8; k++) {
            float a[8], b[8];
            *(float4*)&a[0] = *(float4*)&As[k][ry * 8];
            *(float4*)&a[4] = *(float4*)&As[k][ry * 8 + 4];
            *(float4*)&b[0] = *(float4*)&Bs[k][cx * 8];
            *(float4*)&b[4] = *(float4*)&Bs[k][cx * 8 + 4];
#pragma unroll
            for (int i = 0; i < 8; i++)
#pragma unroll
                for (int j = 0; j < 8; j++) acc[i][j] += a[i] * b[j];
        }
        __syncthreads();
    }

#pragma unroll
    for (int i = 0; i < 8; i++) {
        int m = m0 + ry * 8 + i;
#pragma unroll
        for (int j = 0; j < 8; j++) {
            int col = n0 + cx * 8 + j;
            out[(size_t)m * Hh + col] = acc[i][j] + bias[col];
        }
    }
}

// ---------------------------------------------------------------------------
extern "C" void kernel_launch(void* const* d_in, const int* in_sizes, int n_in,
                              void* d_out, int out_size)
{
    const float* hs   = (const float*)d_in[0];
    const float* pros = (const float*)d_in[1];
    const float* q_w  = (const float*)d_in[2];
    const float* q_b  = (const float*)d_in[3];
    const float* k_w  = (const float*)d_in[4];
    const float* k_b  = (const float*)d_in[5];
    const float* v_w  = (const float*)d_in[6];
    const float* v_b  = (const float*)d_in[7];
    const float* o_w  = (const float*)d_in[8];
    const float* o_b  = (const float*)d_in[9];
    const float* pg_w = (const float*)d_in[10];
    const float* pg_b = (const float*)d_in[11];
    const float* mg_w = (const float*)d_in[12];
    const float* mg_b = (const float*)d_in[13];

    float* out  = (float*)d_out;
    float* attn = out + (size_t)Bb * Ss * Hh;

    gate_kernel<<<Bb * Ss, 256>>>(hs, pros, pg_w, pg_b, mg_w, mg_b);
    qkv_gemm<<<dim3(8, 32, 3), 256>>>(hs, q_w, q_b, k_w, k_b, v_w, v_b);
    scores_kernel<<<dim3(16, 16, 32), 256>>>(attn);
    softmax_kernel<<<dim3(Ss, NHh, Bb), 256>>>(attn);
    pv_kernel<<<dim3(16, 32), 256>>>(attn);
    out_gemm<<<dim3(8, 32), 256>>>(o_w, o_b, out);
}

// round 6
// speedup vs baseline: 2.5199x; 2.5199x over previous
#include <cuda_runtime.h>
#include <cuda_fp16.h>
#include <math.h>
#include <stdint.h>

#define Bb  2
#define Ss  2048
#define Hh  1024
#define NHh 16
#define HDd 64
#define Mtot (Bb * Ss)          // 4096

// ---------------- scratch planes (__device__ globals; no allocs) -----------
__device__ __half g_Xh[(size_t)Mtot * Hh];
__device__ __half g_Xl[(size_t)Mtot * Hh];
__device__ __half g_Wh[4][(size_t)Hh * Hh];   // transposed weights hi
__device__ __half g_Wl[4][(size_t)Hh * Hh];   // transposed weights lo
__device__ __half g_Qh[(size_t)Bb * NHh * Ss * HDd];
__device__ __half g_Ql[(size_t)Bb * NHh * Ss * HDd];
__device__ __half g_Kh[(size_t)Bb * NHh * Ss * HDd];
__device__ __half g_Kl[(size_t)Bb * NHh * Ss * HDd];
__device__ float  g_V [(size_t)Bb * NHh * Ss * HDd];
__device__ __half g_VTh[(size_t)Bb * NHh * HDd * Ss];
__device__ __half g_VTl[(size_t)Bb * NHh * HDd * Ss];
__device__ __half g_Ph[(size_t)Bb * NHh * Ss * Ss];   // prob planes (bss-zeroed)
__device__ __half g_Pl[(size_t)Bb * NHh * Ss * Ss];
__device__ __half g_Ch[(size_t)Mtot * Hh];            // ctx planes
__device__ __half g_Cl[(size_t)Mtot * Hh];
__device__ float  g_gain[(size_t)Bb * Ss * NHh];

// ---------------- helpers ---------------------------------------------------
__device__ __forceinline__ uint32_t smem_u32(const void* p) {
    uint32_t a;
    asm("{ .reg .u64 t; cvta.to.shared.u64 t, %1; cvt.u32.u64 %0, t; }" : "=r"(a) : "l"(p));
    return a;
}
__device__ __forceinline__ void split_f(float x, __half& h, __half& l) {
    h = __float2half_rn(x);
    l = __float2half_rn(x - __half2float(h));
}
__device__ __forceinline__ void ldsm4(uint32_t* r, uint32_t addr) {
    asm volatile("ldmatrix.sync.aligned.m8n8.x4.shared.b16 {%0,%1,%2,%3}, [%4];"
        : "=r"(r[0]), "=r"(r[1]), "=r"(r[2]), "=r"(r[3]) : "r"(addr));
}
__device__ __forceinline__ void mma16(float* c, const uint32_t* a, const uint32_t* b) {
    asm volatile("mma.sync.aligned.m16n8k16.row.col.f32.f16.f16.f32 "
        "{%0,%1,%2,%3},{%4,%5,%6,%7},{%8,%9},{%0,%1,%2,%3};"
        : "+f"(c[0]), "+f"(c[1]), "+f"(c[2]), "+f"(c[3])
        : "r"(a[0]), "r"(a[1]), "r"(a[2]), "r"(a[3]), "r"(b[0]), "r"(b[1]));
}
__device__ __forceinline__ void cpa16(uint32_t dst, const void* src) {
    asm volatile("cp.async.cg.shared.global [%0], [%1], 16;" :: "r"(dst), "l"(src));
}

// ---------------------------------------------------------------------------
// Split-fp16 tensor-core mainloop (3-MMA: hh + hl + lh).
// C[128 x BN] += A[128 x 64*nkc] @ Bt[BN x 64*nkc]^T
// A,B given as hi/lo fp16 planes, K-major (ld in halfs). BK=64 halfs = 128B row.
// 256 threads = 8 warps (4 M x 2 N). cp.async double-buffered, swizzled.
// ---------------------------------------------------------------------------
template<int BN>
__device__ __forceinline__ void split_mainloop(
    const __half* __restrict__ Ah, const __half* __restrict__ Al, int ldA,
    const __half* __restrict__ Bh, const __half* __restrict__ Bl, int ldB,
    int nkc, char* smem, float (*cacc)[4])
{
    constexpr int NT = BN / 16;          // 8-col n-tiles per warp
    constexpr int APL = 128 * 128;       // bytes per A plane
    constexpr int BPL = BN * 128;        // bytes per B plane
    constexpr int BUF = 2 * APL + 2 * BPL;

    const int tid = threadIdx.x, lane = tid & 31, wid = tid >> 5;
    const int m_base = (wid & 3) * 32;
    const int n_base = (wid >> 2) * (BN / 2);
    uint32_t sbase = smem_u32(smem);

    auto load = [&](int kc, int b) {
        uint32_t s0 = sbase + b * BUF;
        for (int idx = tid; idx < 1024; idx += 256) {
            int row = idx >> 3, ch = idx & 7;
            uint32_t off = row * 128 + ((ch ^ (row & 7)) << 4);
            const __half* sA = Ah + (size_t)row * ldA + kc * 64 + ch * 8;
            const __half* sAl = Al + (size_t)row * ldA + kc * 64 + ch * 8;
            cpa16(s0 + off, sA);
            cpa16(s0 + APL + off, sAl);
        }
        for (int idx = tid; idx < BN * 8; idx += 256) {
            int row = idx >> 3, ch = idx & 7;
            uint32_t off = row * 128 + ((ch ^ (row & 7)) << 4);
            cpa16(s0 + 2 * APL + off, Bh + (size_t)row * ldB + kc * 64 + ch * 8);
            cpa16(s0 + 2 * APL + BPL + off, Bl + (size_t)row * ldB + kc * 64 + ch * 8);
        }
        asm volatile("cp.async.commit_group;");
    };

    load(0, 0);

    for (int kc = 0; kc < nkc; kc++) {
        int b = kc & 1;
        if (kc + 1 < nkc) {
            load(kc + 1, b ^ 1);
            asm volatile("cp.async.wait_group 1;");
        } else {
            asm volatile("cp.async.wait_group 0;");
        }
        __syncthreads();
        uint32_t s0 = sbase + b * BUF;
#pragma unroll
        for (int ks = 0; ks < 4; ks++) {
            // A fragments: [plane][mtile][4]
            uint32_t a[2][2][4];
            {
                int row = m_base + (lane & 7) + ((lane >> 3) & 1) * 8;
                int ch  = ks * 2 + (lane >> 4);
#pragma unroll
                for (int mt = 0; mt < 2; mt++) {
                    int r2 = row + mt * 16;
                    uint32_t off = r2 * 128 + ((ch ^ (r2 & 7)) << 4);
                    ldsm4(a[0][mt], s0 + off);
                    ldsm4(a[1][mt], s0 + APL + off);
                }
            }
            // B fragments: [plane][ntile][2]
            uint32_t bf[2][NT][2];
            {
                int row = n_base + (lane & 7) + ((lane >> 4) << 3);
                int ch  = ks * 2 + ((lane >> 3) & 1);
#pragma unroll
                for (int np = 0; np < NT / 2; np++) {
                    int r2 = row + np * 16;
                    uint32_t off = r2 * 128 + ((ch ^ (r2 & 7)) << 4);
                    uint32_t t[4];
                    ldsm4(t, s0 + 2 * APL + off);
                    bf[0][2 * np][0] = t[0]; bf[0][2 * np][1] = t[1];
                    bf[0][2 * np + 1][0] = t[2]; bf[0][2 * np + 1][1] = t[3];
                    ldsm4(t, s0 + 2 * APL + BPL + off);
                    bf[1][2 * np][0] = t[0]; bf[1][2 * np][1] = t[1];
                    bf[1][2 * np + 1][0] = t[2]; bf[1][2 * np + 1][1] = t[3];
                }
            }
#pragma unroll
            for (int mt = 0; mt < 2; mt++)
#pragma unroll
                for (int nt = 0; nt < NT; nt++) {
                    float* c = cacc[mt * NT + nt];
                    mma16(c, a[0][mt], bf[0][nt]);   // hi*hi
                    mma16(c, a[0][mt], bf[1][nt]);   // hi*lo
                    mma16(c, a[1][mt], bf[0][nt]);   // lo*hi
                }
        }
        __syncthreads();
    }
}

#define SMEM_128 (2 * (2 * 128 * 128 + 2 * 128 * 128))   // 128 KB
#define SMEM_64  (2 * (2 * 128 * 128 + 2 * 64 * 128))    // 96 KB

// ---------------------------------------------------------------------------
// QKV projection (z selects Q/K/V). Epilogue: +bias; Q gain-folded; Q/K emit
// hi/lo planes head-major; V emits fp32 head-major.
// ---------------------------------------------------------------------------
__global__ __launch_bounds__(256) void gemm_qkv(
    const float* __restrict__ bq, const float* __restrict__ bk,
    const float* __restrict__ bv)
{
    extern __shared__ char smem[];
    const int z = blockIdx.z;
    const int n0 = blockIdx.x * 128, m0 = blockIdx.y * 128;
    const float* bias = (z == 0) ? bq : (z == 1) ? bk : bv;

    float c[16][4];
#pragma unroll
    for (int i = 0; i < 16; i++)
#pragma unroll
        for (int j = 0; j < 4; j++) c[i][j] = 0.f;

    split_mainloop<128>(g_Xh + (size_t)m0 * Hh, g_Xl + (size_t)m0 * Hh, Hh,
                        g_Wh[z] + (size_t)n0 * Hh, g_Wl[z] + (size_t)n0 * Hh, Hh,
                        16, smem, c);

    const int lane = threadIdx.x & 31, wid = threadIdx.x >> 5;
    const int g = lane >> 2, t = lane & 3;
    const int m_base = (wid & 3) * 32, n_base = (wid >> 2) * 64;
#pragma unroll
    for (int mt = 0; mt < 2; mt++)
#pragma unroll
        for (int nt = 0; nt < 8; nt++)
#pragma unroll
            for (int half = 0; half < 2; half++) {
                int m = m0 + m_base + mt * 16 + g + half * 8;
                int n = n0 + n_base + nt * 8 + 2 * t;
                float vx = c[mt * 8 + nt][half * 2 + 0] + bias[n];
                float vy = c[mt * 8 + nt][half * 2 + 1] + bias[n + 1];
                int h = n >> 6, d = n & 63;
                int bidx = m >> 11, srow = m & (Ss - 1);
                size_t base = (((size_t)(bidx * NHh + h)) * Ss + srow) * HDd + d;
                if (z == 2) {
                    *(float2*)(g_V + base) = make_float2(vx, vy);
                } else {
                    if (z == 0) {
                        float gs = g_gain[(size_t)m * NHh + h];
                        vx *= gs; vy *= gs;
                    }
                    __half hx, lx, hy, ly;
                    split_f(vx, hx, lx); split_f(vy, hy, ly);
                    __half* ph = (z == 0) ? g_Qh : g_Kh;
                    __half* pl = (z == 0) ? g_Ql : g_Kl;
                    *(__half2*)(ph + base) = __halves2half2(hx, hy);
                    *(__half2*)(pl + base) = __halves2half2(lx, ly);
                }
            }
}

// ---------------------------------------------------------------------------
// Output projection: ctx planes @ o_w + o_b -> d_out[:B*S*H] (fp32)
// ---------------------------------------------------------------------------
__global__ __launch_bounds__(256) void gemm_out(
    const float* __restrict__ bias, float* __restrict__ out)
{
    extern __shared__ char smem[];
    const int n0 = blockIdx.x * 128, m0 = blockIdx.y * 128;

    float c[16][4];
#pragma unroll
    for (int i = 0; i < 16; i++)
#pragma unroll
        for (int j = 0; j < 4; j++) c[i][j] = 0.f;

    split_mainloop<128>(g_Ch + (size_t)m0 * Hh, g_Cl + (size_t)m0 * Hh, Hh,
                        g_Wh[3] + (size_t)n0 * Hh, g_Wl[3] + (size_t)n0 * Hh, Hh,
                        16, smem, c);

    const int lane = threadIdx.x & 31, wid = threadIdx.x >> 5;
    const int g = lane >> 2, t = lane & 3;
    const int m_base = (wid & 3) * 32, n_base = (wid >> 2) * 64;
#pragma unroll
    for (int mt = 0; mt < 2; mt++)
#pragma unroll
        for (int nt = 0; nt < 8; nt++)
#pragma unroll
            for (int half = 0; half < 2; half++) {
                int m = m0 + m_base + mt * 16 + g + half * 8;
                int n = n0 + n_base + nt * 8 + 2 * t;
                float2 v = make_float2(c[mt * 8 + nt][half * 2] + bias[n],
                                       c[mt * 8 + nt][half * 2 + 1] + bias[n + 1]);
                *(float2*)(out + (size_t)m * Hh + n) = v;
            }
}

// ---------------------------------------------------------------------------
// Scores: logits = Q.K^T (gains folded). Lower tiles via split MMA -> fp32
// attn; strictly-upper tiles zero-filled; diagonal masks 0 above diag.
// ---------------------------------------------------------------------------
__global__ __launch_bounds__(256) void scores_mma(float* __restrict__ attn)
{
    extern __shared__ char smem[];
    const int kt = blockIdx.x, qt = blockIdx.y, bh = blockIdx.z;
    const int q0 = qt * 128, k0 = kt * 128;
    float* abase = attn + (size_t)bh * Ss * Ss;

    if (kt > qt) {
        float4 z4 = make_float4(0.f, 0.f, 0.f, 0.f);
        for (int idx = threadIdx.x; idx < 128 * 32; idx += 256) {
            int row = idx >> 5, cc = idx & 31;
            *(float4*)(abase + (size_t)(q0 + row) * Ss + k0 + cc * 4) = z4;
        }
        return;
    }

    float c[16][4];
#pragma unroll
    for (int i = 0; i < 16; i++)
#pragma unroll
        for (int j = 0; j < 4; j++) c[i][j] = 0.f;

    size_t qoff = ((size_t)bh * Ss + q0) * HDd;
    size_t koff = ((size_t)bh * Ss + k0) * HDd;
    split_mainloop<128>(g_Qh + qoff, g_Ql + qoff, HDd,
                        g_Kh + koff, g_Kl + koff, HDd, 1, smem, c);

    const int lane = threadIdx.x & 31, wid = threadIdx.x >> 5;
    const int g = lane >> 2, t = lane & 3;
    const int m_base = (wid & 3) * 32, n_base = (wid >> 2) * 64;
    const bool diag = (kt == qt);
#pragma unroll
    for (int mt = 0; mt < 2; mt++)
#pragma unroll
        for (int nt = 0; nt < 8; nt++)
#pragma unroll
            for (int half = 0; half < 2; half++) {
                int gi = q0 + m_base + mt * 16 + g + half * 8;
                int gj = k0 + n_base + nt * 8 + 2 * t;
                float vx = c[mt * 8 + nt][half * 2];
                float vy = c[mt * 8 + nt][half * 2 + 1];
                if (diag) {
                    if (gj > gi) vx = 0.f;
                    if (gj + 1 > gi) vy = 0.f;
                }
                *(float2*)(abase + (size_t)gi * Ss + gj) = make_float2(vx, vy);
            }
}

// ---------------------------------------------------------------------------
// Softmax over j<=i; writes fp32 weights (d_out) + hi/lo prob planes;
// zero-fills planes up to the 128-aligned causal boundary.
// ---------------------------------------------------------------------------
__global__ __launch_bounds__(256) void softmax_kernel(float* __restrict__ attn)
{
    int i = blockIdx.x, h = blockIdx.y, b = blockIdx.z;
    size_t roff = ((size_t)(b * NHh + h) * Ss + i) * Ss;
    float* row = attn + roff;
    __half* prh = g_Ph + roff;
    __half* prl = g_Pl + roff;
    int n = i + 1;
    int npad = ((i >> 7) + 1) << 7;
    int tid = threadIdx.x;

    float vals[8];
    int cnt = 0;
    float mx = -INFINITY;
    for (int j = tid; j < n; j += 256) {
        float s = row[j];
        vals[cnt++] = s;
        mx = fmaxf(mx, s);
    }

    __shared__ float red[256];
    red[tid] = mx; __syncthreads();
    for (int s = 128; s > 0; s >>= 1) {
        if (tid < s) red[tid] = fmaxf(red[tid], red[tid + s]);
        __syncthreads();
    }
    mx = red[0];
    __syncthreads();

    float sum = 0.f;
    for (int cx = 0; cx < cnt; cx++) {
        vals[cx] = __expf(vals[cx] - mx);
        sum += vals[cx];
    }
    red[tid] = sum; __syncthreads();
    for (int s = 128; s > 0; s >>= 1) {
        if (tid < s) red[tid] += red[tid + s];
        __syncthreads();
    }
    float inv = 1.0f / red[0];

    cnt = 0;
    for (int j = tid; j < n; j += 256) {
        float p = vals[cnt++] * inv;
        row[j] = p;
        __half hp, lp;
        split_f(p, hp, lp);
        prh[j] = hp; prl[j] = lp;
    }
    __half z = __float2half_rn(0.f);
    for (int j = n + tid; j < npad; j += 256) { prh[j] = z; prl[j] = z; }
}

// ---------------------------------------------------------------------------
// V transpose + split: g_V[bh][s][d] -> VTh/VTl[bh][d][s]
// ---------------------------------------------------------------------------
__global__ __launch_bounds__(256) void vt_kernel()
{
    int bh = blockIdx.z;
    const float* V = g_V + (size_t)bh * Ss * HDd;
    __half* VTh = g_VTh + (size_t)bh * HDd * Ss;
    __half* VTl = g_VTl + (size_t)bh * HDd * Ss;
    __shared__ float t[32][33];
    int s0 = blockIdx.x * 32, d0 = blockIdx.y * 32;
    int tx = threadIdx.x & 31, ty = threadIdx.x >> 5;
#pragma unroll
    for (int i = 0; i < 4; i++)
        t[ty + i * 8][tx] = V[(size_t)(s0 + ty + i * 8) * HDd + d0 + tx];
    __syncthreads();
#pragma unroll
    for (int i = 0; i < 4; i++) {
        __half h, l;
        split_f(t[tx][ty + i * 8], h, l);
        VTh[(size_t)(d0 + ty + i * 8) * Ss + s0 + tx] = h;
        VTl[(size_t)(d0 + ty + i * 8) * Ss + s0 + tx] = l;
    }
}

// ---------------------------------------------------------------------------
// PV: ctx = probs @ V (causal). Emits ctx hi/lo planes.
// ---------------------------------------------------------------------------
__global__ __launch_bounds__(256) void pv_mma()
{
    extern __shared__ char smem[];
    const int qt = blockIdx.x, bh = blockIdx.y;
    const int q0 = qt * 128;
    const int b = bh >> 4, h = bh & 15;

    float c[8][4];
#pragma unroll
    for (int i = 0; i < 8; i++)
#pragma unroll
        for (int j = 0; j < 4; j++) c[i][j] = 0.f;

    size_t poff = ((size_t)bh * Ss + q0) * Ss;
    size_t voff = (size_t)bh * HDd * Ss;
    split_mainloop<64>(g_Ph + poff, g_Pl + poff, Ss,
                       g_VTh + voff, g_VTl + voff, Ss,
                       (qt + 1) * 2, smem, c);

    const int lane = threadIdx.x & 31, wid = threadIdx.x >> 5;
    const int g = lane >> 2, t = lane & 3;
    const int m_base = (wid & 3) * 32, n_base = (wid >> 2) * 32;
#pragma unroll
    for (int mt = 0; mt < 2; mt++)
#pragma unroll
        for (int nt = 0; nt < 4; nt++)
#pragma unroll
            for (int half = 0; half < 2; half++) {
                int m = q0 + m_base + mt * 16 + g + half * 8;
                int d = n_base + nt * 8 + 2 * t;
                float vx = c[mt * 4 + nt][half * 2];
                float vy = c[mt * 4 + nt][half * 2 + 1];
                __half hx, lx, hy, ly;
                split_f(vx, hx, lx); split_f(vy, hy, ly);
                size_t base = ((size_t)b * Ss + m) * Hh + h * 64 + d;
                *(__half2*)(g_Ch + base) = __halves2half2(hx, hy);
                *(__half2*)(g_Cl + base) = __halves2half2(lx, ly);
            }
}

// ---------------------------------------------------------------------------
// Prep: X split planes; weight transpose + split planes.
// ---------------------------------------------------------------------------
__global__ __launch_bounds__(256) void x_conv(const float* __restrict__ hs)
{
    size_t i = ((size_t)blockIdx.x * 256 + threadIdx.x) * 4;
    float4 v = *(const float4*)(hs + i);
    __half h0, l0, h1, l1, h2, l2, h3, l3;
    split_f(v.x, h0, l0); split_f(v.y, h1, l1);
    split_f(v.z, h2, l2); split_f(v.w, h3, l3);
    *(__half2*)(g_Xh + i)     = __halves2half2(h0, h1);
    *(__half2*)(g_Xh + i + 2) = __halves2half2(h2, h3);
    *(__half2*)(g_Xl + i)     = __halves2half2(l0, l1);
    *(__half2*)(g_Xl + i + 2) = __halves2half2(l2, l3);
}

__global__ __launch_bounds__(256) void wt_kernel(
    const float* __restrict__ qw, const float* __restrict__ kw,
    const float* __restrict__ vw, const float* __restrict__ ow)
{
    int w = blockIdx.z;
    const float* W = (w == 0) ? qw : (w == 1) ? kw : (w == 2) ? vw : ow;
    __half* WTh = g_Wh[w];
    __half* WTl = g_Wl[w];
    __shared__ float t[32][33];
    int n0 = blockIdx.x * 32, k0 = blockIdx.y * 32;
    int tx = threadIdx.x & 31, ty = threadIdx.x >> 5;
#pragma unroll
    for (int i = 0; i < 4; i++)
        t[ty + i * 8][tx] = W[(size_t)(k0 + ty + i * 8) * Hh + n0 + tx];
    __syncthreads();
#pragma unroll
    for (int i = 0; i < 4; i++) {
        __half h, l;
        split_f(t[tx][ty + i * 8], h, l);
        WTh[(size_t)(n0 + ty + i * 8) * Hh + k0 + tx] = h;
        WTl[(size_t)(n0 + ty + i * 8) * Hh + k0 + tx] = l;
    }
}

// ---------------------------------------------------------------------------
// Per-(b,s) gating (1/sqrt(HD) folded)
// ---------------------------------------------------------------------------
__global__ __launch_bounds__(256) void gate_kernel(
    const float* __restrict__ hs, const float* __restrict__ pros,
    const float* __restrict__ pg_w, const float* __restrict__ pg_b,
    const float* __restrict__ mg_w, const float* __restrict__ mg_b)
{
    int bs = blockIdx.x;
    const float* x = hs + (size_t)bs * Hh;
    int tid = threadIdx.x;

    float part = 0.f;
    for (int i = tid; i < Hh; i += 256) part += x[i] * mg_w[i];
    __shared__ float red[256];
    red[tid] = part; __syncthreads();
    for (int s = 128; s > 0; s >>= 1) {
        if (tid < s) red[tid] += red[tid + s];
        __syncthreads();
    }
    float mem = 1.0f + 0.5f / (1.0f + __expf(-(red[0] + mg_b[0])));

    if (tid < NHh) {
        const float* p = pros + (size_t)bs * 4;
        float a = p[0] * pg_w[0 * NHh + tid] + p[1] * pg_w[1 * NHh + tid]
                + p[2] * pg_w[2 * NHh + tid] + p[3] * pg_w[3 * NHh + tid]
                + pg_b[tid];
        float pg = 1.0f + 1.0f / (1.0f + __expf(-a));
        g_gain[(size_t)bs * NHh + tid] = pg * mem * 0.125f;
    }
}

// ---------------------------------------------------------------------------
extern "C" void kernel_launch(void* const* d_in, const int* in_sizes, int n_in,
                              void* d_out, int out_size)
{
    const float* hs   = (const float*)d_in[0];
    const float* pros = (const float*)d_in[1];
    const float* q_w  = (const float*)d_in[2];
    const float* q_b  = (const float*)d_in[3];
    const float* k_w  = (const float*)d_in[4];
    const float* k_b  = (const float*)d_in[5];
    const float* v_w  = (const float*)d_in[6];
    const float* v_b  = (const float*)d_in[7];
    const float* o_w  = (const float*)d_in[8];
    const float* o_b  = (const float*)d_in[9];
    const float* pg_w = (const float*)d_in[10];
    const float* pg_b = (const float*)d_in[11];
    const float* mg_w = (const float*)d_in[12];
    const float* mg_b = (const float*)d_in[13];

    float* out  = (float*)d_out;
    float* attn = out + (size_t)Bb * Ss * Hh;

    static int attr_done = 0;
    if (!attr_done) {
        cudaFuncSetAttribute(gemm_qkv,  cudaFuncAttributeMaxDynamicSharedMemorySize, SMEM_128);
        cudaFuncSetAttribute(gemm_out,  cudaFuncAttributeMaxDynamicSharedMemorySize, SMEM_128);
        cudaFuncSetAttribute(scores_mma, cudaFuncAttributeMaxDynamicSharedMemorySize, SMEM_128);
        cudaFuncSetAttribute(pv_mma,    cudaFuncAttributeMaxDynamicSharedMemorySize, SMEM_64);
        attr_done = 1;
    }

    gate_kernel<<<Bb * Ss, 256>>>(hs, pros, pg_w, pg_b, mg_w, mg_b);
    x_conv<<<(Mtot * Hh) / (256 * 4), 256>>>(hs);
    wt_kernel<<<dim3(32, 32, 4), 256>>>(q_w, k_w, v_w, o_w);

    gemm_qkv<<<dim3(8, 32, 3), 256, SMEM_128>>>(q_b, k_b, v_b);
    vt_kernel<<<dim3(64, 2, 32), 256>>>();

    scores_mma<<<dim3(16, 16, 32), 256, SMEM_128>>>(attn);
    softmax_kernel<<<dim3(Ss, NHh, Bb), 256>>>(attn);
    pv_mma<<<dim3(16, 32), 256, SMEM_64>>>();

    gemm_out<<<dim3(8, 32), 256, SMEM_128>>>(o_b, out);
}

// round 7
// speedup vs baseline: 2.6637x; 1.0570x over previous
#include <cuda_runtime.h>
#include <cuda_fp16.h>
#include <math.h>
#include <stdint.h>

#define Bb  2
#define Ss  2048
#define Hh  1024
#define NHh 16
#define HDd 64
#define Mtot (Bb * Ss)          // 4096

// ---------------- scratch planes (__device__ globals; no allocs) -----------
__device__ __half g_Xh[(size_t)Mtot * Hh];
__device__ __half g_Xl[(size_t)Mtot * Hh];
__device__ __half g_Wh[4][(size_t)Hh * Hh];   // transposed weights hi
__device__ __half g_Wl[4][(size_t)Hh * Hh];   // transposed weights lo
__device__ __half g_Qh[(size_t)Bb * NHh * Ss * HDd];
__device__ __half g_Ql[(size_t)Bb * NHh * Ss * HDd];
__device__ __half g_Kh[(size_t)Bb * NHh * Ss * HDd];
__device__ __half g_Kl[(size_t)Bb * NHh * Ss * HDd];
__device__ float  g_V [(size_t)Bb * NHh * Ss * HDd];
__device__ __half g_VTh[(size_t)Bb * NHh * HDd * Ss];
__device__ __half g_VTl[(size_t)Bb * NHh * HDd * Ss];
__device__ __half g_Ph[(size_t)Bb * NHh * Ss * Ss];   // prob planes
__device__ __half g_Pl[(size_t)Bb * NHh * Ss * Ss];   // (pad region stays 0 from init)
__device__ __half g_Ch[(size_t)Mtot * Hh];            // ctx planes
__device__ __half g_Cl[(size_t)Mtot * Hh];
__device__ float  g_gain[(size_t)Bb * Ss * NHh];

// ---------------- helpers ---------------------------------------------------
__device__ __forceinline__ uint32_t smem_u32(const void* p) {
    uint32_t a;
    asm("{ .reg .u64 t; cvta.to.shared.u64 t, %1; cvt.u32.u64 %0, t; }" : "=r"(a) : "l"(p));
    return a;
}
__device__ __forceinline__ void split_f(float x, __half& h, __half& l) {
    h = __float2half_rn(x);
    l = __float2half_rn(x - __half2float(h));
}
__device__ __forceinline__ void ldsm4(uint32_t* r, uint32_t addr) {
    asm volatile("ldmatrix.sync.aligned.m8n8.x4.shared.b16 {%0,%1,%2,%3}, [%4];"
        : "=r"(r[0]), "=r"(r[1]), "=r"(r[2]), "=r"(r[3]) : "r"(addr));
}
__device__ __forceinline__ void mma16(float* c, const uint32_t* a, const uint32_t* b) {
    asm volatile("mma.sync.aligned.m16n8k16.row.col.f32.f16.f16.f32 "
        "{%0,%1,%2,%3},{%4,%5,%6,%7},{%8,%9},{%0,%1,%2,%3};"
        : "+f"(c[0]), "+f"(c[1]), "+f"(c[2]), "+f"(c[3])
        : "r"(a[0]), "r"(a[1]), "r"(a[2]), "r"(a[3]), "r"(b[0]), "r"(b[1]));
}
__device__ __forceinline__ void cpa16(uint32_t dst, const void* src) {
    asm volatile("cp.async.cg.shared.global [%0], [%1], 16;" :: "r"(dst), "l"(src));
}

// ---------------------------------------------------------------------------
// Split-fp16 tensor-core mainloop (3-MMA: hh + hl + lh).
// C[128 x BN] += A[128 x 64*nkc] @ Bt[BN x 64*nkc]^T
// A,B as hi/lo fp16 planes, K-major (ld in halfs). BK=64 halfs = 128B rows.
// 256 threads = 8 warps (4 M x 2 N). cp.async double-buffered, swizzled.
// For nkc==1 only buffer 0 is touched (callers may allocate 1 stage).
// ---------------------------------------------------------------------------
template<int BN>
__device__ __forceinline__ void split_mainloop(
    const __half* __restrict__ Ah, const __half* __restrict__ Al, int ldA,
    const __half* __restrict__ Bh, const __half* __restrict__ Bl, int ldB,
    int nkc, char* smem, float (*cacc)[4])
{
    constexpr int NT = BN / 16;          // 8-col n-tiles per warp
    constexpr int APL = 128 * 128;       // bytes per A plane
    constexpr int BPL = BN * 128;        // bytes per B plane
    constexpr int BUF = 2 * APL + 2 * BPL;

    const int tid = threadIdx.x, lane = tid & 31, wid = tid >> 5;
    const int m_base = (wid & 3) * 32;
    const int n_base = (wid >> 2) * (BN / 2);
    uint32_t sbase = smem_u32(smem);

    auto load = [&](int kc, int b) {
        uint32_t s0 = sbase + b * BUF;
        for (int idx = tid; idx < 1024; idx += 256) {
            int row = idx >> 3, ch = idx & 7;
            uint32_t off = row * 128 + ((ch ^ (row & 7)) << 4);
            cpa16(s0 + off,       Ah + (size_t)row * ldA + kc * 64 + ch * 8);
            cpa16(s0 + APL + off, Al + (size_t)row * ldA + kc * 64 + ch * 8);
        }
        for (int idx = tid; idx < BN * 8; idx += 256) {
            int row = idx >> 3, ch = idx & 7;
            uint32_t off = row * 128 + ((ch ^ (row & 7)) << 4);
            cpa16(s0 + 2 * APL + off,       Bh + (size_t)row * ldB + kc * 64 + ch * 8);
            cpa16(s0 + 2 * APL + BPL + off, Bl + (size_t)row * ldB + kc * 64 + ch * 8);
        }
        asm volatile("cp.async.commit_group;");
    };

    load(0, 0);

    for (int kc = 0; kc < nkc; kc++) {
        int b = kc & 1;
        if (kc + 1 < nkc) {
            load(kc + 1, b ^ 1);
            asm volatile("cp.async.wait_group 1;");
        } else {
            asm volatile("cp.async.wait_group 0;");
        }
        __syncthreads();
        uint32_t s0 = sbase + b * BUF;
#pragma unroll
        for (int ks = 0; ks < 4; ks++) {
            uint32_t a[2][2][4];
            {
                int row = m_base + (lane & 7) + ((lane >> 3) & 1) * 8;
                int ch  = ks * 2 + (lane >> 4);
#pragma unroll
                for (int mt = 0; mt < 2; mt++) {
                    int r2 = row + mt * 16;
                    uint32_t off = r2 * 128 + ((ch ^ (r2 & 7)) << 4);
                    ldsm4(a[0][mt], s0 + off);
                    ldsm4(a[1][mt], s0 + APL + off);
                }
            }
            uint32_t bf[2][NT][2];
            {
                int row = n_base + (lane & 7) + ((lane >> 4) << 3);
                int ch  = ks * 2 + ((lane >> 3) & 1);
#pragma unroll
                for (int np = 0; np < NT / 2; np++) {
                    int r2 = row + np * 16;
                    uint32_t off = r2 * 128 + ((ch ^ (r2 & 7)) << 4);
                    uint32_t t[4];
                    ldsm4(t, s0 + 2 * APL + off);
                    bf[0][2 * np][0] = t[0]; bf[0][2 * np][1] = t[1];
                    bf[0][2 * np + 1][0] = t[2]; bf[0][2 * np + 1][1] = t[3];
                    ldsm4(t, s0 + 2 * APL + BPL + off);
                    bf[1][2 * np][0] = t[0]; bf[1][2 * np][1] = t[1];
                    bf[1][2 * np + 1][0] = t[2]; bf[1][2 * np + 1][1] = t[3];
                }
            }
#pragma unroll
            for (int mt = 0; mt < 2; mt++)
#pragma unroll
                for (int nt = 0; nt < NT; nt++) {
                    float* c = cacc[mt * NT + nt];
                    mma16(c, a[0][mt], bf[0][nt]);   // hi*hi
                    mma16(c, a[0][mt], bf[1][nt]);   // hi*lo
                    mma16(c, a[1][mt], bf[0][nt]);   // lo*hi
                }
        }
        __syncthreads();
    }
}

#define BUF64   (2 * 128 * 128 + 2 * 64 * 128)   // 48 KB per stage (BN=64)
#define SMEM_DB (2 * BUF64)                      // 96 KB double-buffered
#define SMEM_SB (BUF64)                          // 48 KB single stage

// ---------------------------------------------------------------------------
// QKV projection (z selects Q/K/V). BM=128, BN=64 (one head per block).
// ---------------------------------------------------------------------------
__global__ __launch_bounds__(256, 2) void gemm_qkv(
    const float* __restrict__ bq, const float* __restrict__ bk,
    const float* __restrict__ bv)
{
    extern __shared__ char smem[];
    const int z = blockIdx.z;
    const int n0 = blockIdx.x * 64, m0 = blockIdx.y * 128;
    const float* bias = (z == 0) ? bq : (z == 1) ? bk : bv;

    float c[8][4];
#pragma unroll
    for (int i = 0; i < 8; i++)
#pragma unroll
        for (int j = 0; j < 4; j++) c[i][j] = 0.f;

    split_mainloop<64>(g_Xh + (size_t)m0 * Hh, g_Xl + (size_t)m0 * Hh, Hh,
                       g_Wh[z] + (size_t)n0 * Hh, g_Wl[z] + (size_t)n0 * Hh, Hh,
                       16, smem, c);

    const int lane = threadIdx.x & 31, wid = threadIdx.x >> 5;
    const int g = lane >> 2, t = lane & 3;
    const int m_base = (wid & 3) * 32, n_base = (wid >> 2) * 32;
    const int h = n0 >> 6;          // whole block inside one head
#pragma unroll
    for (int mt = 0; mt < 2; mt++)
#pragma unroll
        for (int nt = 0; nt < 4; nt++)
#pragma unroll
            for (int half = 0; half < 2; half++) {
                int m = m0 + m_base + mt * 16 + g + half * 8;
                int n = n0 + n_base + nt * 8 + 2 * t;
                float vx = c[mt * 4 + nt][half * 2 + 0] + bias[n];
                float vy = c[mt * 4 + nt][half * 2 + 1] + bias[n + 1];
                int d = n & 63;
                int bidx = m >> 11, srow = m & (Ss - 1);
                size_t base = (((size_t)(bidx * NHh + h)) * Ss + srow) * HDd + d;
                if (z == 2) {
                    *(float2*)(g_V + base) = make_float2(vx, vy);
                } else {
                    if (z == 0) {
                        float gs = g_gain[(size_t)m * NHh + h];
                        vx *= gs; vy *= gs;
                    }
                    __half hx, lx, hy, ly;
                    split_f(vx, hx, lx); split_f(vy, hy, ly);
                    __half* ph = (z == 0) ? g_Qh : g_Kh;
                    __half* pl = (z == 0) ? g_Ql : g_Kl;
                    *(__half2*)(ph + base) = __halves2half2(hx, hy);
                    *(__half2*)(pl + base) = __halves2half2(lx, ly);
                }
            }
}

// ---------------------------------------------------------------------------
// Output projection: ctx planes @ o_w + o_b -> d_out[:B*S*H] (fp32)
// ---------------------------------------------------------------------------
__global__ __launch_bounds__(256, 2) void gemm_out(
    const float* __restrict__ bias, float* __restrict__ out)
{
    extern __shared__ char smem[];
    const int n0 = blockIdx.x * 64, m0 = blockIdx.y * 128;

    float c[8][4];
#pragma unroll
    for (int i = 0; i < 8; i++)
#pragma unroll
        for (int j = 0; j < 4; j++) c[i][j] = 0.f;

    split_mainloop<64>(g_Ch + (size_t)m0 * Hh, g_Cl + (size_t)m0 * Hh, Hh,
                       g_Wh[3] + (size_t)n0 * Hh, g_Wl[3] + (size_t)n0 * Hh, Hh,
                       16, smem, c);

    const int lane = threadIdx.x & 31, wid = threadIdx.x >> 5;
    const int g = lane >> 2, t = lane & 3;
    const int m_base = (wid & 3) * 32, n_base = (wid >> 2) * 32;
#pragma unroll
    for (int mt = 0; mt < 2; mt++)
#pragma unroll
        for (int nt = 0; nt < 4; nt++)
#pragma unroll
            for (int half = 0; half < 2; half++) {
                int m = m0 + m_base + mt * 16 + g + half * 8;
                int n = n0 + n_base + nt * 8 + 2 * t;
                float2 v = make_float2(c[mt * 4 + nt][half * 2] + bias[n],
                                       c[mt * 4 + nt][half * 2 + 1] + bias[n + 1]);
                *(float2*)(out + (size_t)m * Hh + n) = v;
            }
}

// ---------------------------------------------------------------------------
// Scores: 128 q-rows x 64 k-cols per block. Upper tiles zero-fill; tiles
// crossing the diagonal mask per element. Single-stage smem (K=64 -> nkc=1).
// ---------------------------------------------------------------------------
__global__ __launch_bounds__(256, 2) void scores_mma(float* __restrict__ attn)
{
    extern __shared__ char smem[];
    const int kt = blockIdx.x, qt = blockIdx.y, bh = blockIdx.z;
    const int q0 = qt * 128, k0 = kt * 64;
    float* abase = attn + (size_t)bh * Ss * Ss;

    if (k0 > q0 + 127) {     // fully above diagonal
        float4 z4 = make_float4(0.f, 0.f, 0.f, 0.f);
        for (int idx = threadIdx.x; idx < 128 * 16; idx += 256) {
            int row = idx >> 4, cc = idx & 15;
            *(float4*)(abase + (size_t)(q0 + row) * Ss + k0 + cc * 4) = z4;
        }
        return;
    }

    float c[8][4];
#pragma unroll
    for (int i = 0; i < 8; i++)
#pragma unroll
        for (int j = 0; j < 4; j++) c[i][j] = 0.f;

    size_t qoff = ((size_t)bh * Ss + q0) * HDd;
    size_t koff = ((size_t)bh * Ss + k0) * HDd;
    split_mainloop<64>(g_Qh + qoff, g_Ql + qoff, HDd,
                       g_Kh + koff, g_Kl + koff, HDd, 1, smem, c);

    const int lane = threadIdx.x & 31, wid = threadIdx.x >> 5;
    const int g = lane >> 2, t = lane & 3;
    const int m_base = (wid & 3) * 32, n_base = (wid >> 2) * 32;
    const bool diag = (k0 + 63 > q0);
#pragma unroll
    for (int mt = 0; mt < 2; mt++)
#pragma unroll
        for (int nt = 0; nt < 4; nt++)
#pragma unroll
            for (int half = 0; half < 2; half++) {
                int gi = q0 + m_base + mt * 16 + g + half * 8;
                int gj = k0 + n_base + nt * 8 + 2 * t;
                float vx = c[mt * 4 + nt][half * 2];
                float vy = c[mt * 4 + nt][half * 2 + 1];
                if (diag) {
                    if (gj > gi) vx = 0.f;
                    if (gj + 1 > gi) vy = 0.f;
                }
                *(float2*)(abase + (size_t)gi * Ss + gj) = make_float2(vx, vy);
            }
}

// ---------------------------------------------------------------------------
// Softmax over j<=i; writes fp32 weights (d_out) + hi/lo prob planes.
// Pad region of the planes is never written (globals stay zero-initialized).
// ---------------------------------------------------------------------------
__global__ __launch_bounds__(256) void softmax_kernel(float* __restrict__ attn)
{
    int i = blockIdx.x, h = blockIdx.y, b = blockIdx.z;
    size_t roff = ((size_t)(b * NHh + h) * Ss + i) * Ss;
    float* row = attn + roff;
    __half* prh = g_Ph + roff;
    __half* prl = g_Pl + roff;
    int n = i + 1;
    int tid = threadIdx.x;

    float vals[8];
    int cnt = 0;
    float mx = -INFINITY;
    for (int j = tid; j < n; j += 256) {
        float s = row[j];
        vals[cnt++] = s;
        mx = fmaxf(mx, s);
    }

    __shared__ float red[256];
    red[tid] = mx; __syncthreads();
    for (int s = 128; s > 0; s >>= 1) {
        if (tid < s) red[tid] = fmaxf(red[tid], red[tid + s]);
        __syncthreads();
    }
    mx = red[0];
    __syncthreads();

    float sum = 0.f;
    for (int cx = 0; cx < cnt; cx++) {
        vals[cx] = __expf(vals[cx] - mx);
        sum += vals[cx];
    }
    red[tid] = sum; __syncthreads();
    for (int s = 128; s > 0; s >>= 1) {
        if (tid < s) red[tid] += red[tid + s];
        __syncthreads();
    }
    float inv = 1.0f / red[0];

    cnt = 0;
    for (int j = tid; j < n; j += 256) {
        float p = vals[cnt++] * inv;
        row[j] = p;
        __half hp, lp;
        split_f(p, hp, lp);
        prh[j] = hp; prl[j] = lp;
    }
}

// ---------------------------------------------------------------------------
// V transpose + split: g_V[bh][s][d] -> VTh/VTl[bh][d][s]
// ---------------------------------------------------------------------------
__global__ __launch_bounds__(256) void vt_kernel()
{
    int bh = blockIdx.z;
    const float* V = g_V + (size_t)bh * Ss * HDd;
    __half* VTh = g_VTh + (size_t)bh * HDd * Ss;
    __half* VTl = g_VTl + (size_t)bh * HDd * Ss;
    __shared__ float t[32][33];
    int s0 = blockIdx.x * 32, d0 = blockIdx.y * 32;
    int tx = threadIdx.x & 31, ty = threadIdx.x >> 5;
#pragma unroll
    for (int i = 0; i < 4; i++)
        t[ty + i * 8][tx] = V[(size_t)(s0 + ty + i * 8) * HDd + d0 + tx];
    __syncthreads();
#pragma unroll
    for (int i = 0; i < 4; i++) {
        __half h, l;
        split_f(t[tx][ty + i * 8], h, l);
        VTh[(size_t)(d0 + ty + i * 8) * Ss + s0 + tx] = h;
        VTl[(size_t)(d0 + ty + i * 8) * Ss + s0 + tx] = l;
    }
}

// ---------------------------------------------------------------------------
// PV: ctx = probs @ V (causal). Emits ctx hi/lo planes.
// ---------------------------------------------------------------------------
__global__ __launch_bounds__(256, 2) void pv_mma()
{
    extern __shared__ char smem[];
    const int qt = blockIdx.x, bh = blockIdx.y;
    const int q0 = qt * 128;
    const int b = bh >> 4, h = bh & 15;

    float c[8][4];
#pragma unroll
    for (int i = 0; i < 8; i++)
#pragma unroll
        for (int j = 0; j < 4; j++) c[i][j] = 0.f;

    size_t poff = ((size_t)bh * Ss + q0) * Ss;
    size_t voff = (size_t)bh * HDd * Ss;
    split_mainloop<64>(g_Ph + poff, g_Pl + poff, Ss,
                       g_VTh + voff, g_VTl + voff, Ss,
                       (qt + 1) * 2, smem, c);

    const int lane = threadIdx.x & 31, wid = threadIdx.x >> 5;
    const int g = lane >> 2, t = lane & 3;
    const int m_base = (wid & 3) * 32, n_base = (wid >> 2) * 32;
#pragma unroll
    for (int mt = 0; mt < 2; mt++)
#pragma unroll
        for (int nt = 0; nt < 4; nt++)
#pragma unroll
            for (int half = 0; half < 2; half++) {
                int m = q0 + m_base + mt * 16 + g + half * 8;
                int d = n_base + nt * 8 + 2 * t;
                float vx = c[mt * 4 + nt][half * 2];
                float vy = c[mt * 4 + nt][half * 2 + 1];
                __half hx, lx, hy, ly;
                split_f(vx, hx, lx); split_f(vy, hy, ly);
                size_t base = ((size_t)b * Ss + m) * Hh + h * 64 + d;
                *(__half2*)(g_Ch + base) = __halves2half2(hx, hy);
                *(__half2*)(g_Cl + base) = __halves2half2(lx, ly);
            }
}

// ---------------------------------------------------------------------------
// Prep: X split planes; weight transpose + split planes.
// ---------------------------------------------------------------------------
__global__ __launch_bounds__(256) void x_conv(const float* __restrict__ hs)
{
    size_t i = ((size_t)blockIdx.x * 256 + threadIdx.x) * 4;
    float4 v = *(const float4*)(hs + i);
    __half h0, l0, h1, l1, h2, l2, h3, l3;
    split_f(v.x, h0, l0); split_f(v.y, h1, l1);
    split_f(v.z, h2, l2); split_f(v.w, h3, l3);
    *(__half2*)(g_Xh + i)     = __halves2half2(h0, h1);
    *(__half2*)(g_Xh + i + 2) = __halves2half2(h2, h3);
    *(__half2*)(g_Xl + i)     = __halves2half2(l0, l1);
    *(__half2*)(g_Xl + i + 2) = __halves2half2(l2, l3);
}

__global__ __launch_bounds__(256) void wt_kernel(
    const float* __restrict__ qw, const float* __restrict__ kw,
    const float* __restrict__ vw, const float* __restrict__ ow)
{
    int w = blockIdx.z;
    const float* W = (w == 0) ? qw : (w == 1) ? kw : (w == 2) ? vw : ow;
    __half* WTh = g_Wh[w];
    __half* WTl = g_Wl[w];
    __shared__ float t[32][33];
    int n0 = blockIdx.x * 32, k0 = blockIdx.y * 32;
    int tx = threadIdx.x & 31, ty = threadIdx.x >> 5;
#pragma unroll
    for (int i = 0; i < 4; i++)
        t[ty + i * 8][tx] = W[(size_t)(k0 + ty + i * 8) * Hh + n0 + tx];
    __syncthreads();
#pragma unroll
    for (int i = 0; i < 4; i++) {
        __half h, l;
        split_f(t[tx][ty + i * 8], h, l);
        WTh[(size_t)(n0 + ty + i * 8) * Hh + k0 + tx] = h;
        WTl[(size_t)(n0 + ty + i * 8) * Hh + k0 + tx] = l;
    }
}

// ---------------------------------------------------------------------------
// Per-(b,s) gating (1/sqrt(HD) folded)
// ---------------------------------------------------------------------------
__global__ __launch_bounds__(256) void gate_kernel(
    const float* __restrict__ hs, const float* __restrict__ pros,
    const float* __restrict__ pg_w, const float* __restrict__ pg_b,
    const float* __restrict__ mg_w, const float* __restrict__ mg_b)
{
    int bs = blockIdx.x;
    const float* x = hs + (size_t)bs * Hh;
    int tid = threadIdx.x;

    float part = 0.f;
    for (int i = tid; i < Hh; i += 256) part += x[i] * mg_w[i];
    __shared__ float red[256];
    red[tid] = part; __syncthreads();
    for (int s = 128; s > 0; s >>= 1) {
        if (tid < s) red[tid] += red[tid + s];
        __syncthreads();
    }
    float mem = 1.0f + 0.5f / (1.0f + __expf(-(red[0] + mg_b[0])));

    if (tid < NHh) {
        const float* p = pros + (size_t)bs * 4;
        float a = p[0] * pg_w[0 * NHh + tid] + p[1] * pg_w[1 * NHh + tid]
                + p[2] * pg_w[2 * NHh + tid] + p[3] * pg_w[3 * NHh + tid]
                + pg_b[tid];
        float pg = 1.0f + 1.0f / (1.0f + __expf(-a));
        g_gain[(size_t)bs * NHh + tid] = pg * mem * 0.125f;
    }
}

// ---------------------------------------------------------------------------
extern "C" void kernel_launch(void* const* d_in, const int* in_sizes, int n_in,
                              void* d_out, int out_size)
{
    const float* hs   = (const float*)d_in[0];
    const float* pros = (const float*)d_in[1];
    const float* q_w  = (const float*)d_in[2];
    const float* q_b  = (const float*)d_in[3];
    const float* k_w  = (const float*)d_in[4];
    const float* k_b  = (const float*)d_in[5];
    const float* v_w  = (const float*)d_in[6];
    const float* v_b  = (const float*)d_in[7];
    const float* o_w  = (const float*)d_in[8];
    const float* o_b  = (const float*)d_in[9];
    const float* pg_w = (const float*)d_in[10];
    const float* pg_b = (const float*)d_in[11];
    const float* mg_w = (const float*)d_in[12];
    const float* mg_b = (const float*)d_in[13];

    float* out  = (float*)d_out;
    float* attn = out + (size_t)Bb * Ss * Hh;

    static int attr_done = 0;
    if (!attr_done) {
        cudaFuncSetAttribute(gemm_qkv,   cudaFuncAttributeMaxDynamicSharedMemorySize, SMEM_DB);
        cudaFuncSetAttribute(gemm_out,   cudaFuncAttributeMaxDynamicSharedMemorySize, SMEM_DB);
        cudaFuncSetAttribute(scores_mma, cudaFuncAttributeMaxDynamicSharedMemorySize, SMEM_SB);
        cudaFuncSetAttribute(pv_mma,     cudaFuncAttributeMaxDynamicSharedMemorySize, SMEM_DB);
        attr_done = 1;
    }

    gate_kernel<<<Bb * Ss, 256>>>(hs, pros, pg_w, pg_b, mg_w, mg_b);
    x_conv<<<(Mtot * Hh) / (256 * 4), 256>>>(hs);
    wt_kernel<<<dim3(32, 32, 4), 256>>>(q_w, k_w, v_w, o_w);

    gemm_qkv<<<dim3(16, 32, 3), 256, SMEM_DB>>>(q_b, k_b, v_b);
    vt_kernel<<<dim3(64, 2, 32), 256>>>();

    scores_mma<<<dim3(32, 16, 32), 256, SMEM_SB>>>(attn);
    softmax_kernel<<<dim3(Ss, NHh, Bb), 256>>>(attn);
    pv_mma<<<dim3(16, 32), 256, SMEM_DB>>>();

    gemm_out<<<dim3(16, 32), 256, SMEM_DB>>>(o_b, out);
}

// round 8
// speedup vs baseline: 2.8331x; 1.0636x over previous
#include <cuda_runtime.h>
#include <cuda_fp16.h>
#include <math.h>
#include <stdint.h>

#define Bb  2
#define Ss  2048
#define Hh  1024
#define NHh 16
#define HDd 64
#define Mtot (Bb * Ss)          // 4096

// ---------------- scratch planes (__device__ globals; no allocs) -----------
__device__ __half g_Xh[(size_t)Mtot * Hh];
__device__ __half g_Xl[(size_t)Mtot * Hh];
__device__ __half g_Wh[4][(size_t)Hh * Hh];   // transposed weights hi
__device__ __half g_Wl[4][(size_t)Hh * Hh];   // transposed weights lo
__device__ __half g_Qh[(size_t)Bb * NHh * Ss * HDd];
__device__ __half g_Ql[(size_t)Bb * NHh * Ss * HDd];
__device__ __half g_Kh[(size_t)Bb * NHh * Ss * HDd];
__device__ __half g_Kl[(size_t)Bb * NHh * Ss * HDd];
__device__ float  g_V [(size_t)Bb * NHh * Ss * HDd];
__device__ __half g_VTh[(size_t)Bb * NHh * HDd * Ss];
__device__ __half g_VTl[(size_t)Bb * NHh * HDd * Ss];
__device__ __half g_Ph[(size_t)Bb * NHh * Ss * Ss];   // prob hi plane
__device__ __half g_Ch[(size_t)Mtot * Hh];            // ctx planes
__device__ __half g_Cl[(size_t)Mtot * Hh];
__device__ float  g_gain[(size_t)Bb * Ss * NHh];

// ---------------- helpers ---------------------------------------------------
__device__ __forceinline__ uint32_t smem_u32(const void* p) {
    uint32_t a;
    asm("{ .reg .u64 t; cvta.to.shared.u64 t, %1; cvt.u32.u64 %0, t; }" : "=r"(a) : "l"(p));
    return a;
}
__device__ __forceinline__ void split_f(float x, __half& h, __half& l) {
    h = __float2half_rn(x);
    l = __float2half_rn(x - __half2float(h));
}
__device__ __forceinline__ void ldsm4(uint32_t* r, uint32_t addr) {
    asm volatile("ldmatrix.sync.aligned.m8n8.x4.shared.b16 {%0,%1,%2,%3}, [%4];"
        : "=r"(r[0]), "=r"(r[1]), "=r"(r[2]), "=r"(r[3]) : "r"(addr));
}
__device__ __forceinline__ void mma16(float* c, const uint32_t* a, const uint32_t* b) {
    asm volatile("mma.sync.aligned.m16n8k16.row.col.f32.f16.f16.f32 "
        "{%0,%1,%2,%3},{%4,%5,%6,%7},{%8,%9},{%0,%1,%2,%3};"
        : "+f"(c[0]), "+f"(c[1]), "+f"(c[2]), "+f"(c[3])
        : "r"(a[0]), "r"(a[1]), "r"(a[2]), "r"(a[3]), "r"(b[0]), "r"(b[1]));
}
__device__ __forceinline__ void cpa16(uint32_t dst, const void* src) {
    asm volatile("cp.async.cg.shared.global [%0], [%1], 16;" :: "r"(dst), "l"(src));
}

// ---------------------------------------------------------------------------
// Split-fp16 tensor-core mainloop.
// AP = #A planes (2: hh+hl+lh, 3 MMAs ; 1: hh+hl, 2 MMAs).
// C[128 x BN] += A[128 x 64*nkc] @ Bt[BN x 64*nkc]^T
// A,B hi/lo fp16 planes, K-major (ld in halfs). BK=64 halfs = 128B rows.
// 256 threads = 8 warps (4 M x 2 N). cp.async double-buffered, swizzled.
// ---------------------------------------------------------------------------
template<int BN, int AP>
__device__ __forceinline__ void split_mainloop(
    const __half* __restrict__ Ah, const __half* __restrict__ Al, int ldA,
    const __half* __restrict__ Bh, const __half* __restrict__ Bl, int ldB,
    int nkc, char* smem, float (*cacc)[4])
{
    constexpr int NT = BN / 16;          // 8-col n-tiles per warp
    constexpr int APL = 128 * 128;       // bytes per A plane
    constexpr int BPL = BN * 128;        // bytes per B plane
    constexpr int BUF = AP * APL + 2 * BPL;

    const int tid = threadIdx.x, lane = tid & 31, wid = tid >> 5;
    const int m_base = (wid & 3) * 32;
    const int n_base = (wid >> 2) * (BN / 2);
    uint32_t sbase = smem_u32(smem);

    auto load = [&](int kc, int b) {
        uint32_t s0 = sbase + b * BUF;
        for (int idx = tid; idx < 1024; idx += 256) {
            int row = idx >> 3, ch = idx & 7;
            uint32_t off = row * 128 + ((ch ^ (row & 7)) << 4);
            cpa16(s0 + off, Ah + (size_t)row * ldA + kc * 64 + ch * 8);
            if (AP == 2)
                cpa16(s0 + APL + off, Al + (size_t)row * ldA + kc * 64 + ch * 8);
        }
        for (int idx = tid; idx < BN * 8; idx += 256) {
            int row = idx >> 3, ch = idx & 7;
            uint32_t off = row * 128 + ((ch ^ (row & 7)) << 4);
            cpa16(s0 + AP * APL + off,       Bh + (size_t)row * ldB + kc * 64 + ch * 8);
            cpa16(s0 + AP * APL + BPL + off, Bl + (size_t)row * ldB + kc * 64 + ch * 8);
        }
        asm volatile("cp.async.commit_group;");
    };

    load(0, 0);

    for (int kc = 0; kc < nkc; kc++) {
        int b = kc & 1;
        if (kc + 1 < nkc) {
            load(kc + 1, b ^ 1);
            asm volatile("cp.async.wait_group 1;");
        } else {
            asm volatile("cp.async.wait_group 0;");
        }
        __syncthreads();
        uint32_t s0 = sbase + b * BUF;
#pragma unroll
        for (int ks = 0; ks < 4; ks++) {
            uint32_t a[AP][2][4];
            {
                int row = m_base + (lane & 7) + ((lane >> 3) & 1) * 8;
                int ch  = ks * 2 + (lane >> 4);
#pragma unroll
                for (int mt = 0; mt < 2; mt++) {
                    int r2 = row + mt * 16;
                    uint32_t off = r2 * 128 + ((ch ^ (r2 & 7)) << 4);
                    ldsm4(a[0][mt], s0 + off);
                    if (AP == 2) ldsm4(a[1][mt], s0 + APL + off);
                }
            }
            uint32_t bf[2][NT][2];
            {
                int row = n_base + (lane & 7) + ((lane >> 4) << 3);
                int ch  = ks * 2 + ((lane >> 3) & 1);
#pragma unroll
                for (int np = 0; np < NT / 2; np++) {
                    int r2 = row + np * 16;
                    uint32_t off = r2 * 128 + ((ch ^ (r2 & 7)) << 4);
                    uint32_t t[4];
                    ldsm4(t, s0 + AP * APL + off);
                    bf[0][2 * np][0] = t[0]; bf[0][2 * np][1] = t[1];
                    bf[0][2 * np + 1][0] = t[2]; bf[0][2 * np + 1][1] = t[3];
                    ldsm4(t, s0 + AP * APL + BPL + off);
                    bf[1][2 * np][0] = t[0]; bf[1][2 * np][1] = t[1];
                    bf[1][2 * np + 1][0] = t[2]; bf[1][2 * np + 1][1] = t[3];
                }
            }
#pragma unroll
            for (int mt = 0; mt < 2; mt++)
#pragma unroll
                for (int nt = 0; nt < NT; nt++) {
                    float* c = cacc[mt * NT + nt];
                    mma16(c, a[0][mt], bf[0][nt]);                 // hi*hi
                    mma16(c, a[0][mt], bf[1][nt]);                 // hi*lo
                    if (AP == 2) mma16(c, a[1][mt], bf[0][nt]);    // lo*hi
                }
        }
        __syncthreads();
    }
}

#define BUF64_2  (2 * 128 * 128 + 2 * 64 * 128)   // 48 KB (AP=2, BN=64)
#define BUF64_1  (1 * 128 * 128 + 2 * 64 * 128)   // 32 KB (AP=1, BN=64)
#define SMEM_DB2 (2 * BUF64_2)                    // 96 KB
#define SMEM_SB2 (BUF64_2)                        // 48 KB
#define SMEM_DB1 (2 * BUF64_1)                    // 64 KB

// ---------------------------------------------------------------------------
// QKV projection (z selects Q/K/V). BM=128, BN=64 (one head per block).
// ---------------------------------------------------------------------------
__global__ __launch_bounds__(256, 2) void gemm_qkv(
    const float* __restrict__ bq, const float* __restrict__ bk,
    const float* __restrict__ bv)
{
    extern __shared__ char smem[];
    const int z = blockIdx.z;
    const int n0 = blockIdx.x * 64, m0 = blockIdx.y * 128;
    const float* bias = (z == 0) ? bq : (z == 1) ? bk : bv;

    float c[8][4];
#pragma unroll
    for (int i = 0; i < 8; i++)
#pragma unroll
        for (int j = 0; j < 4; j++) c[i][j] = 0.f;

    split_mainloop<64, 2>(g_Xh + (size_t)m0 * Hh, g_Xl + (size_t)m0 * Hh, Hh,
                          g_Wh[z] + (size_t)n0 * Hh, g_Wl[z] + (size_t)n0 * Hh, Hh,
                          16, smem, c);

    const int lane = threadIdx.x & 31, wid = threadIdx.x >> 5;
    const int g = lane >> 2, t = lane & 3;
    const int m_base = (wid & 3) * 32, n_base = (wid >> 2) * 32;
    const int h = n0 >> 6;
#pragma unroll
    for (int mt = 0; mt < 2; mt++)
#pragma unroll
        for (int nt = 0; nt < 4; nt++)
#pragma unroll
            for (int half = 0; half < 2; half++) {
                int m = m0 + m_base + mt * 16 + g + half * 8;
                int n = n0 + n_base + nt * 8 + 2 * t;
                float vx = c[mt * 4 + nt][half * 2 + 0] + bias[n];
                float vy = c[mt * 4 + nt][half * 2 + 1] + bias[n + 1];
                int d = n & 63;
                int bidx = m >> 11, srow = m & (Ss - 1);
                size_t base = (((size_t)(bidx * NHh + h)) * Ss + srow) * HDd + d;
                if (z == 2) {
                    *(float2*)(g_V + base) = make_float2(vx, vy);
                } else {
                    if (z == 0) {
                        float gs = g_gain[(size_t)m * NHh + h];
                        vx *= gs; vy *= gs;
                    }
                    __half hx, lx, hy, ly;
                    split_f(vx, hx, lx); split_f(vy, hy, ly);
                    __half* ph = (z == 0) ? g_Qh : g_Kh;
                    __half* pl = (z == 0) ? g_Ql : g_Kl;
                    *(__half2*)(ph + base) = __halves2half2(hx, hy);
                    *(__half2*)(pl + base) = __halves2half2(lx, ly);
                }
            }
}

// ---------------------------------------------------------------------------
// Output projection: ctx planes @ o_w + o_b -> d_out[:B*S*H] (fp32)
// ---------------------------------------------------------------------------
__global__ __launch_bounds__(256, 2) void gemm_out(
    const float* __restrict__ bias, float* __restrict__ out)
{
    extern __shared__ char smem[];
    const int n0 = blockIdx.x * 64, m0 = blockIdx.y * 128;

    float c[8][4];
#pragma unroll
    for (int i = 0; i < 8; i++)
#pragma unroll
        for (int j = 0; j < 4; j++) c[i][j] = 0.f;

    split_mainloop<64, 2>(g_Ch + (size_t)m0 * Hh, g_Cl + (size_t)m0 * Hh, Hh,
                          g_Wh[3] + (size_t)n0 * Hh, g_Wl[3] + (size_t)n0 * Hh, Hh,
                          16, smem, c);

    const int lane = threadIdx.x & 31, wid = threadIdx.x >> 5;
    const int g = lane >> 2, t = lane & 3;
    const int m_base = (wid & 3) * 32, n_base = (wid >> 2) * 32;
#pragma unroll
    for (int mt = 0; mt < 2; mt++)
#pragma unroll
        for (int nt = 0; nt < 4; nt++)
#pragma unroll
            for (int half = 0; half < 2; half++) {
                int m = m0 + m_base + mt * 16 + g + half * 8;
                int n = n0 + n_base + nt * 8 + 2 * t;
                float2 v = make_float2(c[mt * 4 + nt][half * 2] + bias[n],
                                       c[mt * 4 + nt][half * 2 + 1] + bias[n + 1]);
                *(float2*)(out + (size_t)m * Hh + n) = v;
            }
}

// ---------------------------------------------------------------------------
// Scores: 128 q-rows x 64 k-cols per block. Upper tiles zero-fill; diagonal
// tiles mask per element. Single-stage smem (K=64 -> nkc=1).
// ---------------------------------------------------------------------------
__global__ __launch_bounds__(256, 2) void scores_mma(float* __restrict__ attn)
{
    extern __shared__ char smem[];
    const int kt = blockIdx.x, qt = blockIdx.y, bh = blockIdx.z;
    const int q0 = qt * 128, k0 = kt * 64;
    float* abase = attn + (size_t)bh * Ss * Ss;

    if (k0 > q0 + 127) {
        float4 z4 = make_float4(0.f, 0.f, 0.f, 0.f);
        for (int idx = threadIdx.x; idx < 128 * 16; idx += 256) {
            int row = idx >> 4, cc = idx & 15;
            *(float4*)(abase + (size_t)(q0 + row) * Ss + k0 + cc * 4) = z4;
        }
        return;
    }

    float c[8][4];
#pragma unroll
    for (int i = 0; i < 8; i++)
#pragma unroll
        for (int j = 0; j < 4; j++) c[i][j] = 0.f;

    size_t qoff = ((size_t)bh * Ss + q0) * HDd;
    size_t koff = ((size_t)bh * Ss + k0) * HDd;
    split_mainloop<64, 2>(g_Qh + qoff, g_Ql + qoff, HDd,
                          g_Kh + koff, g_Kl + koff, HDd, 1, smem, c);

    const int lane = threadIdx.x & 31, wid = threadIdx.x >> 5;
    const int g = lane >> 2, t = lane & 3;
    const int m_base = (wid & 3) * 32, n_base = (wid >> 2) * 32;
    const bool diag = (k0 + 63 > q0);
#pragma unroll
    for (int mt = 0; mt < 2; mt++)
#pragma unroll
        for (int nt = 0; nt < 4; nt++)
#pragma unroll
            for (int half = 0; half < 2; half++) {
                int gi = q0 + m_base + mt * 16 + g + half * 8;
                int gj = k0 + n_base + nt * 8 + 2 * t;
                float vx = c[mt * 4 + nt][half * 2];
                float vy = c[mt * 4 + nt][half * 2 + 1];
                if (diag) {
                    if (gj > gi) vx = 0.f;
                    if (gj + 1 > gi) vy = 0.f;
                }
                *(float2*)(abase + (size_t)gi * Ss + gj) = make_float2(vx, vy);
            }
}

// ---------------------------------------------------------------------------
// Softmax over j<=i; writes fp32 weights (d_out) + hi prob plane only.
// Pad region of the plane is never written (globals stay zero-initialized).
// ---------------------------------------------------------------------------
__global__ __launch_bounds__(256) void softmax_kernel(float* __restrict__ attn)
{
    int i = blockIdx.x, h = blockIdx.y, b = blockIdx.z;
    size_t roff = ((size_t)(b * NHh + h) * Ss + i) * Ss;
    float* row = attn + roff;
    __half* prh = g_Ph + roff;
    int n = i + 1;
    int tid = threadIdx.x;

    float vals[8];
    int cnt = 0;
    float mx = -INFINITY;
    for (int j = tid; j < n; j += 256) {
        float s = row[j];
        vals[cnt++] = s;
        mx = fmaxf(mx, s);
    }

    __shared__ float red[256];
    red[tid] = mx; __syncthreads();
    for (int s = 128; s > 0; s >>= 1) {
        if (tid < s) red[tid] = fmaxf(red[tid], red[tid + s]);
        __syncthreads();
    }
    mx = red[0];
    __syncthreads();

    float sum = 0.f;
    for (int cx = 0; cx < cnt; cx++) {
        vals[cx] = __expf(vals[cx] - mx);
        sum += vals[cx];
    }
    red[tid] = sum; __syncthreads();
    for (int s = 128; s > 0; s >>= 1) {
        if (tid < s) red[tid] += red[tid + s];
        __syncthreads();
    }
    float inv = 1.0f / red[0];

    cnt = 0;
    for (int j = tid; j < n; j += 256) {
        float p = vals[cnt++] * inv;
        row[j] = p;
        prh[j] = __float2half_rn(p);
    }
}

// ---------------------------------------------------------------------------
// V transpose + split: g_V[bh][s][d] -> VTh/VTl[bh][d][s]
// ---------------------------------------------------------------------------
__global__ __launch_bounds__(256) void vt_kernel()
{
    int bh = blockIdx.z;
    const float* V = g_V + (size_t)bh * Ss * HDd;
    __half* VTh = g_VTh + (size_t)bh * HDd * Ss;
    __half* VTl = g_VTl + (size_t)bh * HDd * Ss;
    __shared__ float t[32][33];
    int s0 = blockIdx.x * 32, d0 = blockIdx.y * 32;
    int tx = threadIdx.x & 31, ty = threadIdx.x >> 5;
#pragma unroll
    for (int i = 0; i < 4; i++)
        t[ty + i * 8][tx] = V[(size_t)(s0 + ty + i * 8) * HDd + d0 + tx];
    __syncthreads();
#pragma unroll
    for (int i = 0; i < 4; i++) {
        __half h, l;
        split_f(t[tx][ty + i * 8], h, l);
        VTh[(size_t)(d0 + ty + i * 8) * Ss + s0 + tx] = h;
        VTl[(size_t)(d0 + ty + i * 8) * Ss + s0 + tx] = l;
    }
}

// ---------------------------------------------------------------------------
// PV: ctx = probs @ V (causal). probs hi-plane only (AP=1, 2 MMAs: p*vh + p*vl).
// ---------------------------------------------------------------------------
__global__ __launch_bounds__(256, 2) void pv_mma()
{
    extern __shared__ char smem[];
    const int qt = blockIdx.x, bh = blockIdx.y;
    const int q0 = qt * 128;
    const int b = bh >> 4, h = bh & 15;

    float c[8][4];
#pragma unroll
    for (int i = 0; i < 8; i++)
#pragma unroll
        for (int j = 0; j < 4; j++) c[i][j] = 0.f;

    size_t poff = ((size_t)bh * Ss + q0) * Ss;
    size_t voff = (size_t)bh * HDd * Ss;
    split_mainloop<64, 1>(g_Ph + poff, (const __half*)nullptr, Ss,
                          g_VTh + voff, g_VTl + voff, Ss,
                          (qt + 1) * 2, smem, c);

    const int lane = threadIdx.x & 31, wid = threadIdx.x >> 5;
    const int g = lane >> 2, t = lane & 3;
    const int m_base = (wid & 3) * 32, n_base = (wid >> 2) * 32;
#pragma unroll
    for (int mt = 0; mt < 2; mt++)
#pragma unroll
        for (int nt = 0; nt < 4; nt++)
#pragma unroll
            for (int half = 0; half < 2; half++) {
                int m = q0 + m_base + mt * 16 + g + half * 8;
                int d = n_base + nt * 8 + 2 * t;
                float vx = c[mt * 4 + nt][half * 2];
                float vy = c[mt * 4 + nt][half * 2 + 1];
                __half hx, lx, hy, ly;
                split_f(vx, hx, lx); split_f(vy, hy, ly);
                size_t base = ((size_t)b * Ss + m) * Hh + h * 64 + d;
                *(__half2*)(g_Ch + base) = __halves2half2(hx, hy);
                *(__half2*)(g_Cl + base) = __halves2half2(lx, ly);
            }
}

// ---------------------------------------------------------------------------
// Prep: X split planes; weight transpose + split planes.
// ---------------------------------------------------------------------------
__global__ __launch_bounds__(256) void x_conv(const float* __restrict__ hs)
{
    size_t i = ((size_t)blockIdx.x * 256 + threadIdx.x) * 4;
    float4 v = *(const float4*)(hs + i);
    __half h0, l0, h1, l1, h2, l2, h3, l3;
    split_f(v.x, h0, l0); split_f(v.y, h1, l1);
    split_f(v.z, h2, l2); split_f(v.w, h3, l3);
    *(__half2*)(g_Xh + i)     = __halves2half2(h0, h1);
    *(__half2*)(g_Xh + i + 2) = __halves2half2(h2, h3);
    *(__half2*)(g_Xl + i)     = __halves2half2(l0, l1);
    *(__half2*)(g_Xl + i + 2) = __halves2half2(l2, l3);
}

__global__ __launch_bounds__(256) void wt_kernel(
    const float* __restrict__ qw, const float* __restrict__ kw,
    const float* __restrict__ vw, const float* __restrict__ ow)
{
    int w = blockIdx.z;
    const float* W = (w == 0) ? qw : (w == 1) ? kw : (w == 2) ? vw : ow;
    __half* WTh = g_Wh[w];
    __half* WTl = g_Wl[w];
    __shared__ float t[32][33];
    int n0 = blockIdx.x * 32, k0 = blockIdx.y * 32;
    int tx = threadIdx.x & 31, ty = threadIdx.x >> 5;
#pragma unroll
    for (int i = 0; i < 4; i++)
        t[ty + i * 8][tx] = W[(size_t)(k0 + ty + i * 8) * Hh + n0 + tx];
    __syncthreads();
#pragma unroll
    for (int i = 0; i < 4; i++) {
        __half h, l;
        split_f(t[tx][ty + i * 8], h, l);
        WTh[(size_t)(n0 + ty + i * 8) * Hh + k0 + tx] = h;
        WTl[(size_t)(n0 + ty + i * 8) * Hh + k0 + tx] = l;
    }
}

// ---------------------------------------------------------------------------
// Per-(b,s) gating (1/sqrt(HD) folded)
// ---------------------------------------------------------------------------
__global__ __launch_bounds__(256) void gate_kernel(
    const float* __restrict__ hs, const float* __restrict__ pros,
    const float* __restrict__ pg_w, const float* __restrict__ pg_b,
    const float* __restrict__ mg_w, const float* __restrict__ mg_b)
{
    int bs = blockIdx.x;
    const float* x = hs + (size_t)bs * Hh;
    int tid = threadIdx.x;

    float part = 0.f;
    for (int i = tid; i < Hh; i += 256) part += x[i] * mg_w[i];
    __shared__ float red[256];
    red[tid] = part; __syncthreads();
    for (int s = 128; s > 0; s >>= 1) {
        if (tid < s) red[tid] += red[tid + s];
        __syncthreads();
    }
    float mem = 1.0f + 0.5f / (1.0f + __expf(-(red[0] + mg_b[0])));

    if (tid < NHh) {
        const float* p = pros + (size_t)bs * 4;
        float a = p[0] * pg_w[0 * NHh + tid] + p[1] * pg_w[1 * NHh + tid]
                + p[2] * pg_w[2 * NHh + tid] + p[3] * pg_w[3 * NHh + tid]
                + pg_b[tid];
        float pg = 1.0f + 1.0f / (1.0f + __expf(-a));
        g_gain[(size_t)bs * NHh + tid] = pg * mem * 0.125f;
    }
}

// ---------------------------------------------------------------------------
extern "C" void kernel_launch(void* const* d_in, const int* in_sizes, int n_in,
                              void* d_out, int out_size)
{
    const float* hs   = (const float*)d_in[0];
    const float* pros = (const float*)d_in[1];
    const float* q_w  = (const float*)d_in[2];
    const float* q_b  = (const float*)d_in[3];
    const float* k_w  = (const float*)d_in[4];
    const float* k_b  = (const float*)d_in[5];
    const float* v_w  = (const float*)d_in[6];
    const float* v_b  = (const float*)d_in[7];
    const float* o_w  = (const float*)d_in[8];
    const float* o_b  = (const float*)d_in[9];
    const float* pg_w = (const float*)d_in[10];
    const float* pg_b = (const float*)d_in[11];
    const float* mg_w = (const float*)d_in[12];
    const float* mg_b = (const float*)d_in[13];

    float* out  = (float*)d_out;
    float* attn = out + (size_t)Bb * Ss * Hh;

    static int attr_done = 0;
    if (!attr_done) {
        cudaFuncSetAttribute(gemm_qkv,   cudaFuncAttributeMaxDynamicSharedMemorySize, SMEM_DB2);
        cudaFuncSetAttribute(gemm_out,   cudaFuncAttributeMaxDynamicSharedMemorySize, SMEM_DB2);
        cudaFuncSetAttribute(scores_mma, cudaFuncAttributeMaxDynamicSharedMemorySize, SMEM_SB2);
        cudaFuncSetAttribute(pv_mma,     cudaFuncAttributeMaxDynamicSharedMemorySize, SMEM_DB1);
        attr_done = 1;
    }

    gate_kernel<<<Bb * Ss, 256>>>(hs, pros, pg_w, pg_b, mg_w, mg_b);
    x_conv<<<(Mtot * Hh) / (256 * 4), 256>>>(hs);
    wt_kernel<<<dim3(32, 32, 4), 256>>>(q_w, k_w, v_w, o_w);

    gemm_qkv<<<dim3(16, 32, 3), 256, SMEM_DB2>>>(q_b, k_b, v_b);
    vt_kernel<<<dim3(64, 2, 32), 256>>>();

    scores_mma<<<dim3(32, 16, 32), 256, SMEM_SB2>>>(attn);
    softmax_kernel<<<dim3(Ss, NHh, Bb), 256>>>(attn);
    pv_mma<<<dim3(16, 32), 256, SMEM_DB1>>>();

    gemm_out<<<dim3(16, 32), 256, SMEM_DB2>>>(o_b, out);
}

// round 9
// speedup vs baseline: 3.1838x; 1.1238x over previous
#include <cuda_runtime.h>
#include <cuda_fp16.h>
#include <math.h>
#include <stdint.h>

#define Bb  2
#define Ss  2048
#define Hh  1024
#define NHh 16
#define HDd 64
#define Mtot (Bb * Ss)          // 4096

// ---------------- scratch planes (__device__ globals; no allocs) -----------
__device__ __half g_Xh[(size_t)Mtot * Hh];            // fp16-rounded X
__device__ __half g_Wh[4][(size_t)Hh * Hh];           // transposed weights hi
__device__ __half g_Wl[4][(size_t)Hh * Hh];           // transposed weights lo
__device__ __half g_Qh[(size_t)Bb * NHh * Ss * HDd];
__device__ __half g_Ql[(size_t)Bb * NHh * Ss * HDd];
__device__ __half g_Kh[(size_t)Bb * NHh * Ss * HDd];
__device__ __half g_Kl[(size_t)Bb * NHh * Ss * HDd];
__device__ float  g_V [(size_t)Bb * NHh * Ss * HDd];
__device__ __half g_VTh[(size_t)Bb * NHh * HDd * Ss];
__device__ __half g_VTl[(size_t)Bb * NHh * HDd * Ss];
__device__ __half g_Ph[(size_t)Bb * NHh * Ss * Ss];   // prob hi plane (pad stays 0)
__device__ __half g_Ch[(size_t)Mtot * Hh];            // fp16 ctx
__device__ float  g_gain[(size_t)Bb * Ss * NHh];

// ---------------- helpers ---------------------------------------------------
__device__ __forceinline__ uint32_t smem_u32(const void* p) {
    uint32_t a;
    asm("{ .reg .u64 t; cvta.to.shared.u64 t, %1; cvt.u32.u64 %0, t; }" : "=r"(a) : "l"(p));
    return a;
}
__device__ __forceinline__ void split_f(float x, __half& h, __half& l) {
    h = __float2half_rn(x);
    l = __float2half_rn(x - __half2float(h));
}
__device__ __forceinline__ void ldsm4(uint32_t* r, uint32_t addr) {
    asm volatile("ldmatrix.sync.aligned.m8n8.x4.shared.b16 {%0,%1,%2,%3}, [%4];"
        : "=r"(r[0]), "=r"(r[1]), "=r"(r[2]), "=r"(r[3]) : "r"(addr));
}
__device__ __forceinline__ void mma16(float* c, const uint32_t* a, const uint32_t* b) {
    asm volatile("mma.sync.aligned.m16n8k16.row.col.f32.f16.f16.f32 "
        "{%0,%1,%2,%3},{%4,%5,%6,%7},{%8,%9},{%0,%1,%2,%3};"
        : "+f"(c[0]), "+f"(c[1]), "+f"(c[2]), "+f"(c[3])
        : "r"(a[0]), "r"(a[1]), "r"(a[2]), "r"(a[3]), "r"(b[0]), "r"(b[1]));
}
__device__ __forceinline__ void cpa16(uint32_t dst, const void* src) {
    asm volatile("cp.async.cg.shared.global [%0], [%1], 16;" :: "r"(dst), "l"(src));
}
template<int N>
__device__ __forceinline__ void cp_wait() {
    asm volatile("cp.async.wait_group %0;" :: "n"(N));
}

// ---------------------------------------------------------------------------
// Split-fp16 tensor-core mainloop.
// AP = #A planes: 2 -> 3 MMAs (hh+hl+lh), 1 -> 2 MMAs (A*Bh + A*Bl).
// NS = pipeline stages (cp.async multi-buffer).
// C[128 x BN] += A[128 x 64*nkc] @ Bt[BN x 64*nkc]^T, K-major planes.
// 256 threads = 8 warps (4 M x 2 N). BK=64 halfs = 128B rows, swizzled.
// ---------------------------------------------------------------------------
template<int BN, int AP, int NS>
__device__ __forceinline__ void split_mainloop(
    const __half* __restrict__ Ah, const __half* __restrict__ Al, int ldA,
    const __half* __restrict__ Bh, const __half* __restrict__ Bl, int ldB,
    int nkc, char* smem, float (*cacc)[4])
{
    constexpr int NT = BN / 16;
    constexpr int APL = 128 * 128;       // bytes per A plane
    constexpr int BPL = BN * 128;        // bytes per B plane
    constexpr int BUF = AP * APL + 2 * BPL;

    const int tid = threadIdx.x, lane = tid & 31, wid = tid >> 5;
    const int m_base = (wid & 3) * 32;
    const int n_base = (wid >> 2) * (BN / 2);
    uint32_t sbase = smem_u32(smem);

    auto load = [&](int kc, int b) {
        uint32_t s0 = sbase + b * BUF;
        for (int idx = tid; idx < 1024; idx += 256) {
            int row = idx >> 3, ch = idx & 7;
            uint32_t off = row * 128 + ((ch ^ (row & 7)) << 4);
            cpa16(s0 + off, Ah + (size_t)row * ldA + kc * 64 + ch * 8);
            if (AP == 2)
                cpa16(s0 + APL + off, Al + (size_t)row * ldA + kc * 64 + ch * 8);
        }
        for (int idx = tid; idx < BN * 8; idx += 256) {
            int row = idx >> 3, ch = idx & 7;
            uint32_t off = row * 128 + ((ch ^ (row & 7)) << 4);
            cpa16(s0 + AP * APL + off,       Bh + (size_t)row * ldB + kc * 64 + ch * 8);
            cpa16(s0 + AP * APL + BPL + off, Bl + (size_t)row * ldB + kc * 64 + ch * 8);
        }
        asm volatile("cp.async.commit_group;");
    };

#pragma unroll
    for (int s = 0; s < NS - 1; s++)
        if (s < nkc) load(s, s);

    for (int kc = 0; kc < nkc; kc++) {
        int b = kc % NS;
        if (kc + NS - 1 < nkc) {
            load(kc + NS - 1, (kc + NS - 1) % NS);
            cp_wait<NS - 1>();
        } else {
            cp_wait<0>();
        }
        __syncthreads();
        uint32_t s0 = sbase + b * BUF;
#pragma unroll
        for (int ks = 0; ks < 4; ks++) {
            uint32_t a[AP][2][4];
            {
                int row = m_base + (lane & 7) + ((lane >> 3) & 1) * 8;
                int ch  = ks * 2 + (lane >> 4);
#pragma unroll
                for (int mt = 0; mt < 2; mt++) {
                    int r2 = row + mt * 16;
                    uint32_t off = r2 * 128 + ((ch ^ (r2 & 7)) << 4);
                    ldsm4(a[0][mt], s0 + off);
                    if (AP == 2) ldsm4(a[1][mt], s0 + APL + off);
                }
            }
            uint32_t bf[2][NT][2];
            {
                int row = n_base + (lane & 7) + ((lane >> 4) << 3);
                int ch  = ks * 2 + ((lane >> 3) & 1);
#pragma unroll
                for (int np = 0; np < NT / 2; np++) {
                    int r2 = row + np * 16;
                    uint32_t off = r2 * 128 + ((ch ^ (r2 & 7)) << 4);
                    uint32_t t[4];
                    ldsm4(t, s0 + AP * APL + off);
                    bf[0][2 * np][0] = t[0]; bf[0][2 * np][1] = t[1];
                    bf[0][2 * np + 1][0] = t[2]; bf[0][2 * np + 1][1] = t[3];
                    ldsm4(t, s0 + AP * APL + BPL + off);
                    bf[1][2 * np][0] = t[0]; bf[1][2 * np][1] = t[1];
                    bf[1][2 * np + 1][0] = t[2]; bf[1][2 * np + 1][1] = t[3];
                }
            }
#pragma unroll
            for (int mt = 0; mt < 2; mt++)
#pragma unroll
                for (int nt = 0; nt < NT; nt++) {
                    float* c = cacc[mt * NT + nt];
                    mma16(c, a[0][mt], bf[0][nt]);                 // A*Bh
                    mma16(c, a[0][mt], bf[1][nt]);                 // A*Bl
                    if (AP == 2) mma16(c, a[1][mt], bf[0][nt]);    // Al*Bh
                }
        }
        __syncthreads();
    }
}

#define BUF64_2  (2 * 128 * 128 + 2 * 64 * 128)   // 48 KB (AP=2)
#define BUF64_1  (1 * 128 * 128 + 2 * 64 * 128)   // 32 KB (AP=1)
#define SMEM_T3  (3 * BUF64_1)                    // 96 KB (AP=1, 3 stages)
#define SMEM_SB2 (BUF64_2)                        // 48 KB (AP=2, nkc=1)

// ---------------------------------------------------------------------------
// QKV projection (z selects Q/K/V). BM=128, BN=64 (one head per block).
// A = fp16 X (single plane), B = Wh/Wl -> 2 MMAs.
// ---------------------------------------------------------------------------
__global__ __launch_bounds__(256, 2) void gemm_qkv(
    const float* __restrict__ bq, const float* __restrict__ bk,
    const float* __restrict__ bv)
{
    extern __shared__ char smem[];
    const int z = blockIdx.z;
    const int n0 = blockIdx.x * 64, m0 = blockIdx.y * 128;
    const float* bias = (z == 0) ? bq : (z == 1) ? bk : bv;

    float c[8][4];
#pragma unroll
    for (int i = 0; i < 8; i++)
#pragma unroll
        for (int j = 0; j < 4; j++) c[i][j] = 0.f;

    split_mainloop<64, 1, 3>(g_Xh + (size_t)m0 * Hh, nullptr, Hh,
                             g_Wh[z] + (size_t)n0 * Hh, g_Wl[z] + (size_t)n0 * Hh, Hh,
                             16, smem, c);

    const int lane = threadIdx.x & 31, wid = threadIdx.x >> 5;
    const int g = lane >> 2, t = lane & 3;
    const int m_base = (wid & 3) * 32, n_base = (wid >> 2) * 32;
    const int h = n0 >> 6;
#pragma unroll
    for (int mt = 0; mt < 2; mt++)
#pragma unroll
        for (int nt = 0; nt < 4; nt++)
#pragma unroll
            for (int half = 0; half < 2; half++) {
                int m = m0 + m_base + mt * 16 + g + half * 8;
                int n = n0 + n_base + nt * 8 + 2 * t;
                float vx = c[mt * 4 + nt][half * 2 + 0] + bias[n];
                float vy = c[mt * 4 + nt][half * 2 + 1] + bias[n + 1];
                int d = n & 63;
                int bidx = m >> 11, srow = m & (Ss - 1);
                size_t base = (((size_t)(bidx * NHh + h)) * Ss + srow) * HDd + d;
                if (z == 2) {
                    *(float2*)(g_V + base) = make_float2(vx, vy);
                } else {
                    if (z == 0) {
                        float gs = g_gain[(size_t)m * NHh + h];
                        vx *= gs; vy *= gs;
                    }
                    __half hx, lx, hy, ly;
                    split_f(vx, hx, lx); split_f(vy, hy, ly);
                    __half* ph = (z == 0) ? g_Qh : g_Kh;
                    __half* pl = (z == 0) ? g_Ql : g_Kl;
                    *(__half2*)(ph + base) = __halves2half2(hx, hy);
                    *(__half2*)(pl + base) = __halves2half2(lx, ly);
                }
            }
}

// ---------------------------------------------------------------------------
// Output projection: fp16 ctx @ o_w + o_b -> d_out[:B*S*H] (fp32). 2 MMAs.
// ---------------------------------------------------------------------------
__global__ __launch_bounds__(256, 2) void gemm_out(
    const float* __restrict__ bias, float* __restrict__ out)
{
    extern __shared__ char smem[];
    const int n0 = blockIdx.x * 64, m0 = blockIdx.y * 128;

    float c[8][4];
#pragma unroll
    for (int i = 0; i < 8; i++)
#pragma unroll
        for (int j = 0; j < 4; j++) c[i][j] = 0.f;

    split_mainloop<64, 1, 3>(g_Ch + (size_t)m0 * Hh, nullptr, Hh,
                             g_Wh[3] + (size_t)n0 * Hh, g_Wl[3] + (size_t)n0 * Hh, Hh,
                             16, smem, c);

    const int lane = threadIdx.x & 31, wid = threadIdx.x >> 5;
    const int g = lane >> 2, t = lane & 3;
    const int m_base = (wid & 3) * 32, n_base = (wid >> 2) * 32;
#pragma unroll
    for (int mt = 0; mt < 2; mt++)
#pragma unroll
        for (int nt = 0; nt < 4; nt++)
#pragma unroll
            for (int half = 0; half < 2; half++) {
                int m = m0 + m_base + mt * 16 + g + half * 8;
                int n = n0 + n_base + nt * 8 + 2 * t;
                float2 v = make_float2(c[mt * 4 + nt][half * 2] + bias[n],
                                       c[mt * 4 + nt][half * 2 + 1] + bias[n + 1]);
                *(float2*)(out + (size_t)m * Hh + n) = v;
            }
}

// ---------------------------------------------------------------------------
// Scores: 128 q-rows x 64 k-cols per block; full 3-MMA precision.
// Upper tiles zero-fill; diagonal tiles mask per element.
// ---------------------------------------------------------------------------
__global__ __launch_bounds__(256, 2) void scores_mma(float* __restrict__ attn)
{
    extern __shared__ char smem[];
    const int kt = blockIdx.x, qt = blockIdx.y, bh = blockIdx.z;
    const int q0 = qt * 128, k0 = kt * 64;
    float* abase = attn + (size_t)bh * Ss * Ss;

    if (k0 > q0 + 127) {
        float4 z4 = make_float4(0.f, 0.f, 0.f, 0.f);
        for (int idx = threadIdx.x; idx < 128 * 16; idx += 256) {
            int row = idx >> 4, cc = idx & 15;
            *(float4*)(abase + (size_t)(q0 + row) * Ss + k0 + cc * 4) = z4;
        }
        return;
    }

    float c[8][4];
#pragma unroll
    for (int i = 0; i < 8; i++)
#pragma unroll
        for (int j = 0; j < 4; j++) c[i][j] = 0.f;

    size_t qoff = ((size_t)bh * Ss + q0) * HDd;
    size_t koff = ((size_t)bh * Ss + k0) * HDd;
    split_mainloop<64, 2, 2>(g_Qh + qoff, g_Ql + qoff, HDd,
                             g_Kh + koff, g_Kl + koff, HDd, 1, smem, c);

    const int lane = threadIdx.x & 31, wid = threadIdx.x >> 5;
    const int g = lane >> 2, t = lane & 3;
    const int m_base = (wid & 3) * 32, n_base = (wid >> 2) * 32;
    const bool diag = (k0 + 63 > q0);
#pragma unroll
    for (int mt = 0; mt < 2; mt++)
#pragma unroll
        for (int nt = 0; nt < 4; nt++)
#pragma unroll
            for (int half = 0; half < 2; half++) {
                int gi = q0 + m_base + mt * 16 + g + half * 8;
                int gj = k0 + n_base + nt * 8 + 2 * t;
                float vx = c[mt * 4 + nt][half * 2];
                float vy = c[mt * 4 + nt][half * 2 + 1];
                if (diag) {
                    if (gj > gi) vx = 0.f;
                    if (gj + 1 > gi) vy = 0.f;
                }
                *(float2*)(abase + (size_t)gi * Ss + gj) = make_float2(vx, vy);
            }
}

// ---------------------------------------------------------------------------
// Softmax over j<=i; writes fp32 weights (d_out) + hi prob plane.
// ---------------------------------------------------------------------------
__global__ __launch_bounds__(256) void softmax_kernel(float* __restrict__ attn)
{
    int i = blockIdx.x, h = blockIdx.y, b = blockIdx.z;
    size_t roff = ((size_t)(b * NHh + h) * Ss + i) * Ss;
    float* row = attn + roff;
    __half* prh = g_Ph + roff;
    int n = i + 1;
    int tid = threadIdx.x;

    float vals[8];
    int cnt = 0;
    float mx = -INFINITY;
    for (int j = tid; j < n; j += 256) {
        float s = row[j];
        vals[cnt++] = s;
        mx = fmaxf(mx, s);
    }

    __shared__ float red[256];
    red[tid] = mx; __syncthreads();
    for (int s = 128; s > 0; s >>= 1) {
        if (tid < s) red[tid] = fmaxf(red[tid], red[tid + s]);
        __syncthreads();
    }
    mx = red[0];
    __syncthreads();

    float sum = 0.f;
    for (int cx = 0; cx < cnt; cx++) {
        vals[cx] = __expf(vals[cx] - mx);
        sum += vals[cx];
    }
    red[tid] = sum; __syncthreads();
    for (int s = 128; s > 0; s >>= 1) {
        if (tid < s) red[tid] += red[tid + s];
        __syncthreads();
    }
    float inv = 1.0f / red[0];

    cnt = 0;
    for (int j = tid; j < n; j += 256) {
        float p = vals[cnt++] * inv;
        row[j] = p;
        prh[j] = __float2half_rn(p);
    }
}

// ---------------------------------------------------------------------------
// V transpose + split: g_V[bh][s][d] -> VTh/VTl[bh][d][s]
// ---------------------------------------------------------------------------
__global__ __launch_bounds__(256) void vt_kernel()
{
    int bh = blockIdx.z;
    const float* V = g_V + (size_t)bh * Ss * HDd;
    __half* VTh = g_VTh + (size_t)bh * HDd * Ss;
    __half* VTl = g_VTl + (size_t)bh * HDd * Ss;
    __shared__ float t[32][33];
    int s0 = blockIdx.x * 32, d0 = blockIdx.y * 32;
    int tx = threadIdx.x & 31, ty = threadIdx.x >> 5;
#pragma unroll
    for (int i = 0; i < 4; i++)
        t[ty + i * 8][tx] = V[(size_t)(s0 + ty + i * 8) * HDd + d0 + tx];
    __syncthreads();
#pragma unroll
    for (int i = 0; i < 4; i++) {
        __half h, l;
        split_f(t[tx][ty + i * 8], h, l);
        VTh[(size_t)(d0 + ty + i * 8) * Ss + s0 + tx] = h;
        VTl[(size_t)(d0 + ty + i * 8) * Ss + s0 + tx] = l;
    }
}

// ---------------------------------------------------------------------------
// PV: ctx = probs @ V (causal). probs hi-plane only; ctx written fp16.
// ---------------------------------------------------------------------------
__global__ __launch_bounds__(256, 2) void pv_mma()
{
    extern __shared__ char smem[];
    const int qt = blockIdx.x, bh = blockIdx.y;
    const int q0 = qt * 128;
    const int b = bh >> 4, h = bh & 15;

    float c[8][4];
#pragma unroll
    for (int i = 0; i < 8; i++)
#pragma unroll
        for (int j = 0; j < 4; j++) c[i][j] = 0.f;

    size_t poff = ((size_t)bh * Ss + q0) * Ss;
    size_t voff = (size_t)bh * HDd * Ss;
    split_mainloop<64, 1, 3>(g_Ph + poff, nullptr, Ss,
                             g_VTh + voff, g_VTl + voff, Ss,
                             (qt + 1) * 2, smem, c);

    const int lane = threadIdx.x & 31, wid = threadIdx.x >> 5;
    const int g = lane >> 2, t = lane & 3;
    const int m_base = (wid & 3) * 32, n_base = (wid >> 2) * 32;
#pragma unroll
    for (int mt = 0; mt < 2; mt++)
#pragma unroll
        for (int nt = 0; nt < 4; nt++)
#pragma unroll
            for (int half = 0; half < 2; half++) {
                int m = q0 + m_base + mt * 16 + g + half * 8;
                int d = n_base + nt * 8 + 2 * t;
                __half hx = __float2half_rn(c[mt * 4 + nt][half * 2]);
                __half hy = __float2half_rn(c[mt * 4 + nt][half * 2 + 1]);
                size_t base = ((size_t)b * Ss + m) * Hh + h * 64 + d;
                *(__half2*)(g_Ch + base) = __halves2half2(hx, hy);
            }
}

// ---------------------------------------------------------------------------
// Prep: X fp16 plane; weight transpose + split planes.
// ---------------------------------------------------------------------------
__global__ __launch_bounds__(256) void x_conv(const float* __restrict__ hs)
{
    size_t i = ((size_t)blockIdx.x * 256 + threadIdx.x) * 4;
    float4 v = *(const float4*)(hs + i);
    *(__half2*)(g_Xh + i)     = __halves2half2(__float2half_rn(v.x), __float2half_rn(v.y));
    *(__half2*)(g_Xh + i + 2) = __halves2half2(__float2half_rn(v.z), __float2half_rn(v.w));
}

__global__ __launch_bounds__(256) void wt_kernel(
    const float* __restrict__ qw, const float* __restrict__ kw,
    const float* __restrict__ vw, const float* __restrict__ ow)
{
    int w = blockIdx.z;
    const float* W = (w == 0) ? qw : (w == 1) ? kw : (w == 2) ? vw : ow;
    __half* WTh = g_Wh[w];
    __half* WTl = g_Wl[w];
    __shared__ float t[32][33];
    int n0 = blockIdx.x * 32, k0 = blockIdx.y * 32;
    int tx = threadIdx.x & 31, ty = threadIdx.x >> 5;
#pragma unroll
    for (int i = 0; i < 4; i++)
        t[ty + i * 8][tx] = W[(size_t)(k0 + ty + i * 8) * Hh + n0 + tx];
    __syncthreads();
#pragma unroll
    for (int i = 0; i < 4; i++) {
        __half h, l;
        split_f(t[tx][ty + i * 8], h, l);
        WTh[(size_t)(n0 + ty + i * 8) * Hh + k0 + tx] = h;
        WTl[(size_t)(n0 + ty + i * 8) * Hh + k0 + tx] = l;
    }
}

// ---------------------------------------------------------------------------
// Per-(b,s) gating (1/sqrt(HD) folded)
// ---------------------------------------------------------------------------
__global__ __launch_bounds__(256) void gate_kernel(
    const float* __restrict__ hs, const float* __restrict__ pros,
    const float* __restrict__ pg_w, const float* __restrict__ pg_b,
    const float* __restrict__ mg_w, const float* __restrict__ mg_b)
{
    int bs = blockIdx.x;
    const float* x = hs + (size_t)bs * Hh;
    int tid = threadIdx.x;

    float part = 0.f;
    for (int i = tid; i < Hh; i += 256) part += x[i] * mg_w[i];
    __shared__ float red[256];
    red[tid] = part; __syncthreads();
    for (int s = 128; s > 0; s >>= 1) {
        if (tid < s) red[tid] += red[tid + s];
        __syncthreads();
    }
    float mem = 1.0f + 0.5f / (1.0f + __expf(-(red[0] + mg_b[0])));

    if (tid < NHh) {
        const float* p = pros + (size_t)bs * 4;
        float a = p[0] * pg_w[0 * NHh + tid] + p[1] * pg_w[1 * NHh + tid]
                + p[2] * pg_w[2 * NHh + tid] + p[3] * pg_w[3 * NHh + tid]
                + pg_b[tid];
        float pg = 1.0f + 1.0f / (1.0f + __expf(-a));
        g_gain[(size_t)bs * NHh + tid] = pg * mem * 0.125f;
    }
}

// ---------------------------------------------------------------------------
extern "C" void kernel_launch(void* const* d_in, const int* in_sizes, int n_in,
                              void* d_out, int out_size)
{
    const float* hs   = (const float*)d_in[0];
    const float* pros = (const float*)d_in[1];
    const float* q_w  = (const float*)d_in[2];
    const float* q_b  = (const float*)d_in[3];
    const float* k_w  = (const float*)d_in[4];
    const float* k_b  = (const float*)d_in[5];
    const float* v_w  = (const float*)d_in[6];
    const float* v_b  = (const float*)d_in[7];
    const float* o_w  = (const float*)d_in[8];
    const float* o_b  = (const float*)d_in[9];
    const float* pg_w = (const float*)d_in[10];
    const float* pg_b = (const float*)d_in[11];
    const float* mg_w = (const float*)d_in[12];
    const float* mg_b = (const float*)d_in[13];

    float* out  = (float*)d_out;
    float* attn = out + (size_t)Bb * Ss * Hh;

    static int attr_done = 0;
    if (!attr_done) {
        cudaFuncSetAttribute(gemm_qkv,   cudaFuncAttributeMaxDynamicSharedMemorySize, SMEM_T3);
        cudaFuncSetAttribute(gemm_out,   cudaFuncAttributeMaxDynamicSharedMemorySize, SMEM_T3);
        cudaFuncSetAttribute(scores_mma, cudaFuncAttributeMaxDynamicSharedMemorySize, SMEM_SB2);
        cudaFuncSetAttribute(pv_mma,     cudaFuncAttributeMaxDynamicSharedMemorySize, SMEM_T3);
        attr_done = 1;
    }

    gate_kernel<<<Bb * Ss, 256>>>(hs, pros, pg_w, pg_b, mg_w, mg_b);
    x_conv<<<(Mtot * Hh) / (256 * 4), 256>>>(hs);
    wt_kernel<<<dim3(32, 32, 4), 256>>>(q_w, k_w, v_w, o_w);

    gemm_qkv<<<dim3(16, 32, 3), 256, SMEM_T3>>>(q_b, k_b, v_b);
    vt_kernel<<<dim3(64, 2, 32), 256>>>();

    scores_mma<<<dim3(32, 16, 32), 256, SMEM_SB2>>>(attn);
    softmax_kernel<<<dim3(Ss, NHh, Bb), 256>>>(attn);
    pv_mma<<<dim3(16, 32), 256, SMEM_T3>>>();

    gemm_out<<<dim3(16, 32), 256, SMEM_T3>>>(o_b, out);
}

// round 10
// speedup vs baseline: 3.5249x; 1.1071x over previous
#include <cuda_runtime.h>
#include <cuda_fp16.h>
#include <math.h>
#include <stdint.h>

#define Bb  2
#define Ss  2048
#define Hh  1024
#define NHh 16
#define HDd 64
#define Mtot (Bb * Ss)          // 4096

// ---------------- scratch planes (__device__ globals; no allocs) -----------
__device__ __half g_Xh[(size_t)Mtot * Hh];            // fp16-rounded X
__device__ __half g_Wh[4][(size_t)Hh * Hh];           // transposed weights hi
__device__ __half g_Wl[4][(size_t)Hh * Hh];           // transposed weights lo
__device__ __half g_Qh[(size_t)Bb * NHh * Ss * HDd];
__device__ __half g_Ql[(size_t)Bb * NHh * Ss * HDd];
__device__ __half g_Kh[(size_t)Bb * NHh * Ss * HDd];
__device__ __half g_Kl[(size_t)Bb * NHh * Ss * HDd];
__device__ float  g_V [(size_t)Bb * NHh * Ss * HDd];
__device__ __half g_VTh[(size_t)Bb * NHh * HDd * Ss];
__device__ __half g_VTl[(size_t)Bb * NHh * HDd * Ss];
__device__ __half g_Ph[(size_t)Bb * NHh * Ss * Ss];   // prob hi plane (pad stays 0)
__device__ __half g_Ch[(size_t)Mtot * Hh];            // fp16 ctx
__device__ float  g_gain[(size_t)Bb * Ss * NHh];

// ---------------- helpers ---------------------------------------------------
__device__ __forceinline__ uint32_t smem_u32(const void* p) {
    uint32_t a;
    asm("{ .reg .u64 t; cvta.to.shared.u64 t, %1; cvt.u32.u64 %0, t; }" : "=r"(a) : "l"(p));
    return a;
}
__device__ __forceinline__ void split_f(float x, __half& h, __half& l) {
    h = __float2half_rn(x);
    l = __float2half_rn(x - __half2float(h));
}
__device__ __forceinline__ void ldsm4(uint32_t* r, uint32_t addr) {
    asm volatile("ldmatrix.sync.aligned.m8n8.x4.shared.b16 {%0,%1,%2,%3}, [%4];"
        : "=r"(r[0]), "=r"(r[1]), "=r"(r[2]), "=r"(r[3]) : "r"(addr));
}
__device__ __forceinline__ void mma16(float* c, const uint32_t* a, const uint32_t* b) {
    asm volatile("mma.sync.aligned.m16n8k16.row.col.f32.f16.f16.f32 "
        "{%0,%1,%2,%3},{%4,%5,%6,%7},{%8,%9},{%0,%1,%2,%3};"
        : "+f"(c[0]), "+f"(c[1]), "+f"(c[2]), "+f"(c[3])
        : "r"(a[0]), "r"(a[1]), "r"(a[2]), "r"(a[3]), "r"(b[0]), "r"(b[1]));
}
__device__ __forceinline__ void cpa16(uint32_t dst, const void* src) {
    asm volatile("cp.async.cg.shared.global [%0], [%1], 16;" :: "r"(dst), "l"(src));
}
template<int N>
__device__ __forceinline__ void cp_wait() {
    asm volatile("cp.async.wait_group %0;" :: "n"(N));
}

// ---------------------------------------------------------------------------
// Split-fp16 tensor-core mainloop.
// AP = #A planes: 2 -> 3 MMAs (hh+hl+lh), 1 -> 2 MMAs (A*Bh + A*Bl).
// NS = pipeline stages. ONE __syncthreads per k-chunk:
//   cp_wait (chunk kc visible) -> sync (all threads done with kc-1 MMAs)
//   -> prefetch chunk kc+NS-1 (buffer freed in kc-1) -> MMAs on chunk kc.
// ---------------------------------------------------------------------------
template<int BN, int AP, int NS>
__device__ __forceinline__ void split_mainloop(
    const __half* __restrict__ Ah, const __half* __restrict__ Al, int ldA,
    const __half* __restrict__ Bh, const __half* __restrict__ Bl, int ldB,
    int nkc, char* smem, float (*cacc)[4])
{
    constexpr int NT = BN / 16;
    constexpr int APL = 128 * 128;       // bytes per A plane
    constexpr int BPL = BN * 128;        // bytes per B plane
    constexpr int BUF = AP * APL + 2 * BPL;

    const int tid = threadIdx.x, lane = tid & 31, wid = tid >> 5;
    const int m_base = (wid & 3) * 32;
    const int n_base = (wid >> 2) * (BN / 2);
    uint32_t sbase = smem_u32(smem);

    auto load = [&](int kc, int b) {
        uint32_t s0 = sbase + b * BUF;
        for (int idx = tid; idx < 1024; idx += 256) {
            int row = idx >> 3, ch = idx & 7;
            uint32_t off = row * 128 + ((ch ^ (row & 7)) << 4);
            cpa16(s0 + off, Ah + (size_t)row * ldA + kc * 64 + ch * 8);
            if (AP == 2)
                cpa16(s0 + APL + off, Al + (size_t)row * ldA + kc * 64 + ch * 8);
        }
        for (int idx = tid; idx < BN * 8; idx += 256) {
            int row = idx >> 3, ch = idx & 7;
            uint32_t off = row * 128 + ((ch ^ (row & 7)) << 4);
            cpa16(s0 + AP * APL + off,       Bh + (size_t)row * ldB + kc * 64 + ch * 8);
            cpa16(s0 + AP * APL + BPL + off, Bl + (size_t)row * ldB + kc * 64 + ch * 8);
        }
        asm volatile("cp.async.commit_group;");
    };

#pragma unroll
    for (int s = 0; s < NS - 1; s++)
        if (s < nkc) load(s, s);

    for (int kc = 0; kc < nkc; kc++) {
        int b = kc % NS;
        // committed groups so far = min(kc + NS - 1, nkc).
        if (kc + NS - 1 < nkc) cp_wait<NS - 2>();   // completed >= kc+1 -> chunk kc ready
        else                   cp_wait<0>();
        __syncthreads();
        if (kc + NS - 1 < nkc) load(kc + NS - 1, (kc + NS - 1) % NS);
        uint32_t s0 = sbase + b * BUF;
#pragma unroll
        for (int ks = 0; ks < 4; ks++) {
            uint32_t a[AP][2][4];
            {
                int row = m_base + (lane & 7) + ((lane >> 3) & 1) * 8;
                int ch  = ks * 2 + (lane >> 4);
#pragma unroll
                for (int mt = 0; mt < 2; mt++) {
                    int r2 = row + mt * 16;
                    uint32_t off = r2 * 128 + ((ch ^ (r2 & 7)) << 4);
                    ldsm4(a[0][mt], s0 + off);
                    if (AP == 2) ldsm4(a[1][mt], s0 + APL + off);
                }
            }
            uint32_t bf[2][NT][2];
            {
                int row = n_base + (lane & 7) + ((lane >> 4) << 3);
                int ch  = ks * 2 + ((lane >> 3) & 1);
#pragma unroll
                for (int np = 0; np < NT / 2; np++) {
                    int r2 = row + np * 16;
                    uint32_t off = r2 * 128 + ((ch ^ (r2 & 7)) << 4);
                    uint32_t t[4];
                    ldsm4(t, s0 + AP * APL + off);
                    bf[0][2 * np][0] = t[0]; bf[0][2 * np][1] = t[1];
                    bf[0][2 * np + 1][0] = t[2]; bf[0][2 * np + 1][1] = t[3];
                    ldsm4(t, s0 + AP * APL + BPL + off);
                    bf[1][2 * np][0] = t[0]; bf[1][2 * np][1] = t[1];
                    bf[1][2 * np + 1][0] = t[2]; bf[1][2 * np + 1][1] = t[3];
                }
            }
#pragma unroll
            for (int mt = 0; mt < 2; mt++)
#pragma unroll
                for (int nt = 0; nt < NT; nt++) {
                    float* c = cacc[mt * NT + nt];
                    mma16(c, a[0][mt], bf[0][nt]);                 // A*Bh
                    mma16(c, a[0][mt], bf[1][nt]);                 // A*Bl
                    if (AP == 2) mma16(c, a[1][mt], bf[0][nt]);    // Al*Bh
                }
        }
    }
}

#define BUF64_2  (2 * 128 * 128 + 2 * 64 * 128)   // 48 KB (AP=2)
#define BUF64_1  (1 * 128 * 128 + 2 * 64 * 128)   // 32 KB (AP=1)
#define SMEM_T3  (3 * BUF64_1)                    // 96 KB (AP=1, 3 stages)
#define SMEM_SB2 (BUF64_2)                        // 48 KB (AP=2, nkc=1)

// ---------------------------------------------------------------------------
// QKV projection (z selects Q/K/V). BM=128, BN=64 (one head per block).
// ---------------------------------------------------------------------------
__global__ __launch_bounds__(256, 2) void gemm_qkv(
    const float* __restrict__ bq, const float* __restrict__ bk,
    const float* __restrict__ bv)
{
    extern __shared__ char smem[];
    const int z = blockIdx.z;
    const int n0 = blockIdx.x * 64, m0 = blockIdx.y * 128;
    const float* bias = (z == 0) ? bq : (z == 1) ? bk : bv;

    float c[8][4];
#pragma unroll
    for (int i = 0; i < 8; i++)
#pragma unroll
        for (int j = 0; j < 4; j++) c[i][j] = 0.f;

    split_mainloop<64, 1, 3>(g_Xh + (size_t)m0 * Hh, nullptr, Hh,
                             g_Wh[z] + (size_t)n0 * Hh, g_Wl[z] + (size_t)n0 * Hh, Hh,
                             16, smem, c);

    const int lane = threadIdx.x & 31, wid = threadIdx.x >> 5;
    const int g = lane >> 2, t = lane & 3;
    const int m_base = (wid & 3) * 32, n_base = (wid >> 2) * 32;
    const int h = n0 >> 6;
#pragma unroll
    for (int mt = 0; mt < 2; mt++)
#pragma unroll
        for (int nt = 0; nt < 4; nt++)
#pragma unroll
            for (int half = 0; half < 2; half++) {
                int m = m0 + m_base + mt * 16 + g + half * 8;
                int n = n0 + n_base + nt * 8 + 2 * t;
                float vx = c[mt * 4 + nt][half * 2 + 0] + bias[n];
                float vy = c[mt * 4 + nt][half * 2 + 1] + bias[n + 1];
                int d = n & 63;
                int bidx = m >> 11, srow = m & (Ss - 1);
                size_t base = (((size_t)(bidx * NHh + h)) * Ss + srow) * HDd + d;
                if (z == 2) {
                    *(float2*)(g_V + base) = make_float2(vx, vy);
                } else {
                    if (z == 0) {
                        float gs = g_gain[(size_t)m * NHh + h];
                        vx *= gs; vy *= gs;
                    }
                    __half hx, lx, hy, ly;
                    split_f(vx, hx, lx); split_f(vy, hy, ly);
                    __half* ph = (z == 0) ? g_Qh : g_Kh;
                    __half* pl = (z == 0) ? g_Ql : g_Kl;
                    *(__half2*)(ph + base) = __halves2half2(hx, hy);
                    *(__half2*)(pl + base) = __halves2half2(lx, ly);
                }
            }
}

// ---------------------------------------------------------------------------
// Output projection: fp16 ctx @ o_w + o_b -> d_out[:B*S*H] (fp32). 2 MMAs.
// ---------------------------------------------------------------------------
__global__ __launch_bounds__(256, 2) void gemm_out(
    const float* __restrict__ bias, float* __restrict__ out)
{
    extern __shared__ char smem[];
    const int n0 = blockIdx.x * 64, m0 = blockIdx.y * 128;

    float c[8][4];
#pragma unroll
    for (int i = 0; i < 8; i++)
#pragma unroll
        for (int j = 0; j < 4; j++) c[i][j] = 0.f;

    split_mainloop<64, 1, 3>(g_Ch + (size_t)m0 * Hh, nullptr, Hh,
                             g_Wh[3] + (size_t)n0 * Hh, g_Wl[3] + (size_t)n0 * Hh, Hh,
                             16, smem, c);

    const int lane = threadIdx.x & 31, wid = threadIdx.x >> 5;
    const int g = lane >> 2, t = lane & 3;
    const int m_base = (wid & 3) * 32, n_base = (wid >> 2) * 32;
#pragma unroll
    for (int mt = 0; mt < 2; mt++)
#pragma unroll
        for (int nt = 0; nt < 4; nt++)
#pragma unroll
            for (int half = 0; half < 2; half++) {
                int m = m0 + m_base + mt * 16 + g + half * 8;
                int n = n0 + n_base + nt * 8 + 2 * t;
                float2 v = make_float2(c[mt * 4 + nt][half * 2] + bias[n],
                                       c[mt * 4 + nt][half * 2 + 1] + bias[n + 1]);
                *(float2*)(out + (size_t)m * Hh + n) = v;
            }
}

// ---------------------------------------------------------------------------
// Scores: 128 q-rows x 64 k-cols per block; full 3-MMA precision.
// Upper tiles zero-fill; diagonal tiles mask per element.
// ---------------------------------------------------------------------------
__global__ __launch_bounds__(256, 2) void scores_mma(float* __restrict__ attn)
{
    extern __shared__ char smem[];
    const int kt = blockIdx.x, qt = blockIdx.y, bh = blockIdx.z;
    const int q0 = qt * 128, k0 = kt * 64;
    float* abase = attn + (size_t)bh * Ss * Ss;

    if (k0 > q0 + 127) {
        float4 z4 = make_float4(0.f, 0.f, 0.f, 0.f);
        for (int idx = threadIdx.x; idx < 128 * 16; idx += 256) {
            int row = idx >> 4, cc = idx & 15;
            *(float4*)(abase + (size_t)(q0 + row) * Ss + k0 + cc * 4) = z4;
        }
        return;
    }

    float c[8][4];
#pragma unroll
    for (int i = 0; i < 8; i++)
#pragma unroll
        for (int j = 0; j < 4; j++) c[i][j] = 0.f;

    size_t qoff = ((size_t)bh * Ss + q0) * HDd;
    size_t koff = ((size_t)bh * Ss + k0) * HDd;
    split_mainloop<64, 2, 2>(g_Qh + qoff, g_Ql + qoff, HDd,
                             g_Kh + koff, g_Kl + koff, HDd, 1, smem, c);

    const int lane = threadIdx.x & 31, wid = threadIdx.x >> 5;
    const int g = lane >> 2, t = lane & 3;
    const int m_base = (wid & 3) * 32, n_base = (wid >> 2) * 32;
    const bool diag = (k0 + 63 > q0);
#pragma unroll
    for (int mt = 0; mt < 2; mt++)
#pragma unroll
        for (int nt = 0; nt < 4; nt++)
#pragma unroll
            for (int half = 0; half < 2; half++) {
                int gi = q0 + m_base + mt * 16 + g + half * 8;
                int gj = k0 + n_base + nt * 8 + 2 * t;
                float vx = c[mt * 4 + nt][half * 2];
                float vy = c[mt * 4 + nt][half * 2 + 1];
                if (diag) {
                    if (gj > gi) vx = 0.f;
                    if (gj + 1 > gi) vy = 0.f;
                }
                *(float2*)(abase + (size_t)gi * Ss + gj) = make_float2(vx, vy);
            }
}

// ---------------------------------------------------------------------------
// Softmax over j<=i. float4 loads/stores, shfl warp reductions, 2 barriers.
// Writes fp32 weights (d_out) + fp16 prob plane.
// ---------------------------------------------------------------------------
__global__ __launch_bounds__(256) void softmax_kernel(float* __restrict__ attn)
{
    int i = blockIdx.x, h = blockIdx.y, b = blockIdx.z;
    size_t roff = ((size_t)(b * NHh + h) * Ss + i) * Ss;
    float* row = attn + roff;
    __half* prh = g_Ph + roff;
    const int n = i + 1;
    const int n4 = n & ~3;
    const int tail = n - n4;
    const int tid = threadIdx.x, lane = tid & 31, wrp = tid >> 5;

    float vals[9];
    int cnt = 0;
    float mx = -INFINITY;
    for (int j = tid * 4; j < n4; j += 1024) {
        float4 v = *(const float4*)(row + j);
        vals[cnt++] = v.x; vals[cnt++] = v.y; vals[cnt++] = v.z; vals[cnt++] = v.w;
        mx = fmaxf(mx, fmaxf(fmaxf(v.x, v.y), fmaxf(v.z, v.w)));
    }
    if (tid < tail) {
        float s = row[n4 + tid];
        vals[cnt++] = s;
        mx = fmaxf(mx, s);
    }

#pragma unroll
    for (int o = 16; o; o >>= 1) mx = fmaxf(mx, __shfl_xor_sync(0xffffffffu, mx, o));
    __shared__ float rmax[8], rsum[8];
    if (lane == 0) rmax[wrp] = mx;
    __syncthreads();
    mx = rmax[0];
#pragma unroll
    for (int w = 1; w < 8; w++) mx = fmaxf(mx, rmax[w]);

    float sum = 0.f;
    for (int c2 = 0; c2 < cnt; c2++) {
        vals[c2] = __expf(vals[c2] - mx);
        sum += vals[c2];
    }
#pragma unroll
    for (int o = 16; o; o >>= 1) sum += __shfl_xor_sync(0xffffffffu, sum, o);
    if (lane == 0) rsum[wrp] = sum;
    __syncthreads();
    sum = 0.f;
#pragma unroll
    for (int w = 0; w < 8; w++) sum += rsum[w];
    float inv = 1.0f / sum;

    cnt = 0;
    for (int j = tid * 4; j < n4; j += 1024) {
        float4 v;
        v.x = vals[cnt++] * inv; v.y = vals[cnt++] * inv;
        v.z = vals[cnt++] * inv; v.w = vals[cnt++] * inv;
        *(float4*)(row + j) = v;
        *(__half2*)(prh + j)     = __halves2half2(__float2half_rn(v.x), __float2half_rn(v.y));
        *(__half2*)(prh + j + 2) = __halves2half2(__float2half_rn(v.z), __float2half_rn(v.w));
    }
    if (tid < tail) {
        float p = vals[cnt++] * inv;
        row[n4 + tid] = p;
        prh[n4 + tid] = __float2half_rn(p);
    }
}

// ---------------------------------------------------------------------------
// V transpose + split: g_V[bh][s][d] -> VTh/VTl[bh][d][s]
// ---------------------------------------------------------------------------
__global__ __launch_bounds__(256) void vt_kernel()
{
    int bh = blockIdx.z;
    const float* V = g_V + (size_t)bh * Ss * HDd;
    __half* VTh = g_VTh + (size_t)bh * HDd * Ss;
    __half* VTl = g_VTl + (size_t)bh * HDd * Ss;
    __shared__ float t[32][33];
    int s0 = blockIdx.x * 32, d0 = blockIdx.y * 32;
    int tx = threadIdx.x & 31, ty = threadIdx.x >> 5;
#pragma unroll
    for (int i = 0; i < 4; i++)
        t[ty + i * 8][tx] = V[(size_t)(s0 + ty + i * 8) * HDd + d0 + tx];
    __syncthreads();
#pragma unroll
    for (int i = 0; i < 4; i++) {
        __half h, l;
        split_f(t[tx][ty + i * 8], h, l);
        VTh[(size_t)(d0 + ty + i * 8) * Ss + s0 + tx] = h;
        VTl[(size_t)(d0 + ty + i * 8) * Ss + s0 + tx] = l;
    }
}

// ---------------------------------------------------------------------------
// PV: ctx = probs @ V (causal). probs hi-plane only; ctx written fp16.
// ---------------------------------------------------------------------------
__global__ __launch_bounds__(256, 2) void pv_mma()
{
    extern __shared__ char smem[];
    const int qt = blockIdx.x, bh = blockIdx.y;
    const int q0 = qt * 128;
    const int b = bh >> 4, h = bh & 15;

    float c[8][4];
#pragma unroll
    for (int i = 0; i < 8; i++)
#pragma unroll
        for (int j = 0; j < 4; j++) c[i][j] = 0.f;

    size_t poff = ((size_t)bh * Ss + q0) * Ss;
    size_t voff = (size_t)bh * HDd * Ss;
    split_mainloop<64, 1, 3>(g_Ph + poff, nullptr, Ss,
                             g_VTh + voff, g_VTl + voff, Ss,
                             (qt + 1) * 2, smem, c);

    const int lane = threadIdx.x & 31, wid = threadIdx.x >> 5;
    const int g = lane >> 2, t = lane & 3;
    const int m_base = (wid & 3) * 32, n_base = (wid >> 2) * 32;
#pragma unroll
    for (int mt = 0; mt < 2; mt++)
#pragma unroll
        for (int nt = 0; nt < 4; nt++)
#pragma unroll
            for (int half = 0; half < 2; half++) {
                int m = q0 + m_base + mt * 16 + g + half * 8;
                int d = n_base + nt * 8 + 2 * t;
                __half hx = __float2half_rn(c[mt * 4 + nt][half * 2]);
                __half hy = __float2half_rn(c[mt * 4 + nt][half * 2 + 1]);
                size_t base = ((size_t)b * Ss + m) * Hh + h * 64 + d;
                *(__half2*)(g_Ch + base) = __halves2half2(hx, hy);
            }
}

// ---------------------------------------------------------------------------
// Prep: X fp16 plane; weight transpose + split planes.
// ---------------------------------------------------------------------------
__global__ __launch_bounds__(256) void x_conv(const float* __restrict__ hs)
{
    size_t i = ((size_t)blockIdx.x * 256 + threadIdx.x) * 4;
    float4 v = *(const float4*)(hs + i);
    *(__half2*)(g_Xh + i)     = __halves2half2(__float2half_rn(v.x), __float2half_rn(v.y));
    *(__half2*)(g_Xh + i + 2) = __halves2half2(__float2half_rn(v.z), __float2half_rn(v.w));
}

__global__ __launch_bounds__(256) void wt_kernel(
    const float* __restrict__ qw, const float* __restrict__ kw,
    const float* __restrict__ vw, const float* __restrict__ ow)
{
    int w = blockIdx.z;
    const float* W = (w == 0) ? qw : (w == 1) ? kw : (w == 2) ? vw : ow;
    __half* WTh = g_Wh[w];
    __half* WTl = g_Wl[w];
    __shared__ float t[32][33];
    int n0 = blockIdx.x * 32, k0 = blockIdx.y * 32;
    int tx = threadIdx.x & 31, ty = threadIdx.x >> 5;
#pragma unroll
    for (int i = 0; i < 4; i++)
        t[ty + i * 8][tx] = W[(size_t)(k0 + ty + i * 8) * Hh + n0 + tx];
    __syncthreads();
#pragma unroll
    for (int i = 0; i < 4; i++) {
        __half h, l;
        split_f(t[tx][ty + i * 8], h, l);
        WTh[(size_t)(n0 + ty + i * 8) * Hh + k0 + tx] = h;
        WTl[(size_t)(n0 + ty + i * 8) * Hh + k0 + tx] = l;
    }
}

// ---------------------------------------------------------------------------
// Per-(b,s) gating (1/sqrt(HD) folded)
// ---------------------------------------------------------------------------
__global__ __launch_bounds__(256) void gate_kernel(
    const float* __restrict__ hs, const float* __restrict__ pros,
    const float* __restrict__ pg_w, const float* __restrict__ pg_b,
    const float* __restrict__ mg_w, const float* __restrict__ mg_b)
{
    int bs = blockIdx.x;
    const float* x = hs + (size_t)bs * Hh;
    int tid = threadIdx.x, lane = tid & 31, wrp = tid >> 5;

    float part = 0.f;
    for (int i = tid; i < Hh; i += 256) part += x[i] * mg_w[i];
#pragma unroll
    for (int o = 16; o; o >>= 1) part += __shfl_xor_sync(0xffffffffu, part, o);
    __shared__ float red[8];
    if (lane == 0) red[wrp] = part;
    __syncthreads();
    float tot = 0.f;
#pragma unroll
    for (int w = 0; w < 8; w++) tot += red[w];
    float mem = 1.0f + 0.5f / (1.0f + __expf(-(tot + mg_b[0])));

    if (tid < NHh) {
        const float* p = pros + (size_t)bs * 4;
        float a = p[0] * pg_w[0 * NHh + tid] + p[1] * pg_w[1 * NHh + tid]
                + p[2] * pg_w[2 * NHh + tid] + p[3] * pg_w[3 * NHh + tid]
                + pg_b[tid];
        float pg = 1.0f + 1.0f / (1.0f + __expf(-a));
        g_gain[(size_t)bs * NHh + tid] = pg * mem * 0.125f;
    }
}

// ---------------------------------------------------------------------------
extern "C" void kernel_launch(void* const* d_in, const int* in_sizes, int n_in,
                              void* d_out, int out_size)
{
    const float* hs   = (const float*)d_in[0];
    const float* pros = (const float*)d_in[1];
    const float* q_w  = (const float*)d_in[2];
    const float* q_b  = (const float*)d_in[3];
    const float* k_w  = (const float*)d_in[4];
    const float* k_b  = (const float*)d_in[5];
    const float* v_w  = (const float*)d_in[6];
    const float* v_b  = (const float*)d_in[7];
    const float* o_w  = (const float*)d_in[8];
    const float* o_b  = (const float*)d_in[9];
    const float* pg_w = (const float*)d_in[10];
    const float* pg_b = (const float*)d_in[11];
    const float* mg_w = (const float*)d_in[12];
    const float* mg_b = (const float*)d_in[13];

    float* out  = (float*)d_out;
    float* attn = out + (size_t)Bb * Ss * Hh;

    static int attr_done = 0;
    if (!attr_done) {
        cudaFuncSetAttribute(gemm_qkv,   cudaFuncAttributeMaxDynamicSharedMemorySize, SMEM_T3);
        cudaFuncSetAttribute(gemm_out,   cudaFuncAttributeMaxDynamicSharedMemorySize, SMEM_T3);
        cudaFuncSetAttribute(scores_mma, cudaFuncAttributeMaxDynamicSharedMemorySize, SMEM_SB2);
        cudaFuncSetAttribute(pv_mma,     cudaFuncAttributeMaxDynamicSharedMemorySize, SMEM_T3);
        attr_done = 1;
    }

    gate_kernel<<<Bb * Ss, 256>>>(hs, pros, pg_w, pg_b, mg_w, mg_b);
    x_conv<<<(Mtot * Hh) / (256 * 4), 256>>>(hs);
    wt_kernel<<<dim3(32, 32, 4), 256>>>(q_w, k_w, v_w, o_w);

    gemm_qkv<<<dim3(16, 32, 3), 256, SMEM_T3>>>(q_b, k_b, v_b);
    vt_kernel<<<dim3(64, 2, 32), 256>>>();

    scores_mma<<<dim3(32, 16, 32), 256, SMEM_SB2>>>(attn);
    softmax_kernel<<<dim3(Ss, NHh, Bb), 256>>>(attn);
    pv_mma<<<dim3(16, 32), 256, SMEM_T3>>>();

    gemm_out<<<dim3(16, 32), 256, SMEM_T3>>>(o_b, out);
}

// round 11
// speedup vs baseline: 3.7630x; 1.0676x over previous
#include <cuda_runtime.h>
#include <cuda_fp16.h>
#include <math.h>
#include <stdint.h>

#define Bb  2
#define Ss  2048
#define Hh  1024
#define NHh 16
#define HDd 64
#define Mtot (Bb * Ss)          // 4096

// ---------------- scratch planes (__device__ globals; no allocs) -----------
__device__ __half g_Xh[(size_t)Mtot * Hh];            // fp16-rounded X
__device__ __half g_Wh[4][(size_t)Hh * Hh];           // transposed weights hi
__device__ __half g_Wl[4][(size_t)Hh * Hh];           // transposed weights lo
__device__ __half g_Qh[(size_t)Bb * NHh * Ss * HDd];  // Q hi (gain folded)
__device__ __half g_Kh[(size_t)Bb * NHh * Ss * HDd];
__device__ __half g_Kl[(size_t)Bb * NHh * Ss * HDd];
__device__ float  g_V [(size_t)Bb * NHh * Ss * HDd];
__device__ __half g_VTh[(size_t)Bb * NHh * HDd * Ss];
__device__ __half g_Ph[(size_t)Bb * NHh * Ss * Ss];   // prob hi plane (pad stays 0)
__device__ __half g_Ch[(size_t)Mtot * Hh];            // fp16 ctx
__device__ float  g_gain[(size_t)Bb * Ss * NHh];

// ---------------- helpers ---------------------------------------------------
__device__ __forceinline__ uint32_t smem_u32(const void* p) {
    uint32_t a;
    asm("{ .reg .u64 t; cvta.to.shared.u64 t, %1; cvt.u32.u64 %0, t; }" : "=r"(a) : "l"(p));
    return a;
}
__device__ __forceinline__ void split_f(float x, __half& h, __half& l) {
    h = __float2half_rn(x);
    l = __float2half_rn(x - __half2float(h));
}
__device__ __forceinline__ void ldsm4(uint32_t* r, uint32_t addr) {
    asm volatile("ldmatrix.sync.aligned.m8n8.x4.shared.b16 {%0,%1,%2,%3}, [%4];"
        : "=r"(r[0]), "=r"(r[1]), "=r"(r[2]), "=r"(r[3]) : "r"(addr));
}
__device__ __forceinline__ void mma16(float* c, const uint32_t* a, const uint32_t* b) {
    asm volatile("mma.sync.aligned.m16n8k16.row.col.f32.f16.f16.f32 "
        "{%0,%1,%2,%3},{%4,%5,%6,%7},{%8,%9},{%0,%1,%2,%3};"
        : "+f"(c[0]), "+f"(c[1]), "+f"(c[2]), "+f"(c[3])
        : "r"(a[0]), "r"(a[1]), "r"(a[2]), "r"(a[3]), "r"(b[0]), "r"(b[1]));
}
__device__ __forceinline__ void cpa16(uint32_t dst, const void* src) {
    asm volatile("cp.async.cg.shared.global [%0], [%1], 16;" :: "r"(dst), "l"(src));
}
template<int N>
__device__ __forceinline__ void cp_wait() {
    asm volatile("cp.async.wait_group %0;" :: "n"(N < 0 ? 0 : N));
}

// ---------------------------------------------------------------------------
// Split-fp16 tensor-core mainloop.
// AP/BP = #planes for A/B. MMAs per tile: A0*B0 [+ A0*B1 if BP=2] [+ A1*B0 if AP=2].
// NS = pipeline stages, ONE __syncthreads per k-chunk.
// C[128 x BN] += A[128 x 64*nkc] @ Bt[BN x 64*nkc]^T, K-major planes.
// ---------------------------------------------------------------------------
template<int BN, int AP, int BP, int NS>
__device__ __forceinline__ void split_mainloop(
    const __half* __restrict__ Ah, const __half* __restrict__ Al, int ldA,
    const __half* __restrict__ Bh, const __half* __restrict__ Bl, int ldB,
    int nkc, char* smem, float (*cacc)[4])
{
    constexpr int NT = BN / 16;
    constexpr int APL = 128 * 128;       // bytes per A plane
    constexpr int BPL = BN * 128;        // bytes per B plane
    constexpr int BUF = AP * APL + BP * BPL;

    const int tid = threadIdx.x, lane = tid & 31, wid = tid >> 5;
    const int m_base = (wid & 3) * 32;
    const int n_base = (wid >> 2) * (BN / 2);
    uint32_t sbase = smem_u32(smem);

    auto load = [&](int kc, int b) {
        uint32_t s0 = sbase + b * BUF;
        for (int idx = tid; idx < 1024; idx += 256) {
            int row = idx >> 3, ch = idx & 7;
            uint32_t off = row * 128 + ((ch ^ (row & 7)) << 4);
            cpa16(s0 + off, Ah + (size_t)row * ldA + kc * 64 + ch * 8);
            if (AP == 2)
                cpa16(s0 + APL + off, Al + (size_t)row * ldA + kc * 64 + ch * 8);
        }
        for (int idx = tid; idx < BN * 8; idx += 256) {
            int row = idx >> 3, ch = idx & 7;
            uint32_t off = row * 128 + ((ch ^ (row & 7)) << 4);
            cpa16(s0 + AP * APL + off, Bh + (size_t)row * ldB + kc * 64 + ch * 8);
            if (BP == 2)
                cpa16(s0 + AP * APL + BPL + off, Bl + (size_t)row * ldB + kc * 64 + ch * 8);
        }
        asm volatile("cp.async.commit_group;");
    };

#pragma unroll
    for (int s = 0; s < NS - 1; s++)
        if (s < nkc) load(s, s);

    for (int kc = 0; kc < nkc; kc++) {
        int b = kc % NS;
        if (kc + NS - 1 < nkc) cp_wait<NS - 2>();
        else                   cp_wait<0>();
        __syncthreads();
        if (kc + NS - 1 < nkc) load(kc + NS - 1, (kc + NS - 1) % NS);
        uint32_t s0 = sbase + b * BUF;
#pragma unroll
        for (int ks = 0; ks < 4; ks++) {
            uint32_t a[AP][2][4];
            {
                int row = m_base + (lane & 7) + ((lane >> 3) & 1) * 8;
                int ch  = ks * 2 + (lane >> 4);
#pragma unroll
                for (int mt = 0; mt < 2; mt++) {
                    int r2 = row + mt * 16;
                    uint32_t off = r2 * 128 + ((ch ^ (r2 & 7)) << 4);
                    ldsm4(a[0][mt], s0 + off);
                    if (AP == 2) ldsm4(a[1][mt], s0 + APL + off);
                }
            }
            uint32_t bf[BP][NT][2];
            {
                int row = n_base + (lane & 7) + ((lane >> 4) << 3);
                int ch  = ks * 2 + ((lane >> 3) & 1);
#pragma unroll
                for (int np = 0; np < NT / 2; np++) {
                    int r2 = row + np * 16;
                    uint32_t off = r2 * 128 + ((ch ^ (r2 & 7)) << 4);
                    uint32_t t[4];
                    ldsm4(t, s0 + AP * APL + off);
                    bf[0][2 * np][0] = t[0]; bf[0][2 * np][1] = t[1];
                    bf[0][2 * np + 1][0] = t[2]; bf[0][2 * np + 1][1] = t[3];
                    if (BP == 2) {
                        ldsm4(t, s0 + AP * APL + BPL + off);
                        bf[1][2 * np][0] = t[0]; bf[1][2 * np][1] = t[1];
                        bf[1][2 * np + 1][0] = t[2]; bf[1][2 * np + 1][1] = t[3];
                    }
                }
            }
#pragma unroll
            for (int mt = 0; mt < 2; mt++)
#pragma unroll
                for (int nt = 0; nt < NT; nt++) {
                    float* c = cacc[mt * NT + nt];
                    mma16(c, a[0][mt], bf[0][nt]);
                    if (BP == 2) mma16(c, a[0][mt], bf[1][nt]);
                    if (AP == 2) mma16(c, a[1][mt], bf[0][nt]);
                }
        }
    }
}

#define BUF_12 (128 * 128 + 2 * 64 * 128)   // 32 KB (AP=1, BP=2)
#define BUF_11 (128 * 128 + 1 * 64 * 128)   // 24 KB (AP=1, BP=1)
#define SMEM_QKV (3 * BUF_12)               // 96 KB
#define SMEM_SC  (BUF_12)                   // 32 KB (nkc=1, only buffer 0 used)
#define SMEM_PV  (3 * BUF_11)               // 72 KB

// ---------------------------------------------------------------------------
// QKV projection (z selects Q/K/V). BM=128, BN=64 (one head per block).
// Q emits hi plane only; K emits hi+lo; V emits fp32.
// ---------------------------------------------------------------------------
__global__ __launch_bounds__(256, 2) void gemm_qkv(
    const float* __restrict__ bq, const float* __restrict__ bk,
    const float* __restrict__ bv)
{
    extern __shared__ char smem[];
    const int z = blockIdx.z;
    const int n0 = blockIdx.x * 64, m0 = blockIdx.y * 128;
    const float* bias = (z == 0) ? bq : (z == 1) ? bk : bv;

    float c[8][4];
#pragma unroll
    for (int i = 0; i < 8; i++)
#pragma unroll
        for (int j = 0; j < 4; j++) c[i][j] = 0.f;

    split_mainloop<64, 1, 2, 3>(g_Xh + (size_t)m0 * Hh, nullptr, Hh,
                                g_Wh[z] + (size_t)n0 * Hh, g_Wl[z] + (size_t)n0 * Hh, Hh,
                                16, smem, c);

    const int lane = threadIdx.x & 31, wid = threadIdx.x >> 5;
    const int g = lane >> 2, t = lane & 3;
    const int m_base = (wid & 3) * 32, n_base = (wid >> 2) * 32;
    const int h = n0 >> 6;
#pragma unroll
    for (int mt = 0; mt < 2; mt++)
#pragma unroll
        for (int nt = 0; nt < 4; nt++)
#pragma unroll
            for (int half = 0; half < 2; half++) {
                int m = m0 + m_base + mt * 16 + g + half * 8;
                int n = n0 + n_base + nt * 8 + 2 * t;
                float vx = c[mt * 4 + nt][half * 2 + 0] + bias[n];
                float vy = c[mt * 4 + nt][half * 2 + 1] + bias[n + 1];
                int d = n & 63;
                int bidx = m >> 11, srow = m & (Ss - 1);
                size_t base = (((size_t)(bidx * NHh + h)) * Ss + srow) * HDd + d;
                if (z == 2) {
                    *(float2*)(g_V + base) = make_float2(vx, vy);
                } else if (z == 0) {
                    float gs = g_gain[(size_t)m * NHh + h];
                    vx *= gs; vy *= gs;
                    *(__half2*)(g_Qh + base) =
                        __halves2half2(__float2half_rn(vx), __float2half_rn(vy));
                } else {
                    __half hx, lx, hy, ly;
                    split_f(vx, hx, lx); split_f(vy, hy, ly);
                    *(__half2*)(g_Kh + base) = __halves2half2(hx, hy);
                    *(__half2*)(g_Kl + base) = __halves2half2(lx, ly);
                }
            }
}

// ---------------------------------------------------------------------------
// Output projection: fp16 ctx @ o_w + o_b -> d_out[:B*S*H] (fp32). 2 MMAs.
// ---------------------------------------------------------------------------
__global__ __launch_bounds__(256, 2) void gemm_out(
    const float* __restrict__ bias, float* __restrict__ out)
{
    extern __shared__ char smem[];
    const int n0 = blockIdx.x * 64, m0 = blockIdx.y * 128;

    float c[8][4];
#pragma unroll
    for (int i = 0; i < 8; i++)
#pragma unroll
        for (int j = 0; j < 4; j++) c[i][j] = 0.f;

    split_mainloop<64, 1, 2, 3>(g_Ch + (size_t)m0 * Hh, nullptr, Hh,
                                g_Wh[3] + (size_t)n0 * Hh, g_Wl[3] + (size_t)n0 * Hh, Hh,
                                16, smem, c);

    const int lane = threadIdx.x & 31, wid = threadIdx.x >> 5;
    const int g = lane >> 2, t = lane & 3;
    const int m_base = (wid & 3) * 32, n_base = (wid >> 2) * 32;
#pragma unroll
    for (int mt = 0; mt < 2; mt++)
#pragma unroll
        for (int nt = 0; nt < 4; nt++)
#pragma unroll
            for (int half = 0; half < 2; half++) {
                int m = m0 + m_base + mt * 16 + g + half * 8;
                int n = n0 + n_base + nt * 8 + 2 * t;
                float2 v = make_float2(c[mt * 4 + nt][half * 2] + bias[n],
                                       c[mt * 4 + nt][half * 2 + 1] + bias[n + 1]);
                *(float2*)(out + (size_t)m * Hh + n) = v;
            }
}

// ---------------------------------------------------------------------------
// Scores: 128 q-rows x 64 k-cols per block; 2-MMA (Qh*Kh + Qh*Kl).
// Upper tiles zero-fill; diagonal tiles mask per element.
// ---------------------------------------------------------------------------
__global__ __launch_bounds__(256, 2) void scores_mma(float* __restrict__ attn)
{
    extern __shared__ char smem[];
    const int kt = blockIdx.x, qt = blockIdx.y, bh = blockIdx.z;
    const int q0 = qt * 128, k0 = kt * 64;
    float* abase = attn + (size_t)bh * Ss * Ss;

    if (k0 > q0 + 127) {
        float4 z4 = make_float4(0.f, 0.f, 0.f, 0.f);
        for (int idx = threadIdx.x; idx < 128 * 16; idx += 256) {
            int row = idx >> 4, cc = idx & 15;
            *(float4*)(abase + (size_t)(q0 + row) * Ss + k0 + cc * 4) = z4;
        }
        return;
    }

    float c[8][4];
#pragma unroll
    for (int i = 0; i < 8; i++)
#pragma unroll
        for (int j = 0; j < 4; j++) c[i][j] = 0.f;

    size_t qoff = ((size_t)bh * Ss + q0) * HDd;
    size_t koff = ((size_t)bh * Ss + k0) * HDd;
    split_mainloop<64, 1, 2, 2>(g_Qh + qoff, nullptr, HDd,
                                g_Kh + koff, g_Kl + koff, HDd, 1, smem, c);

    const int lane = threadIdx.x & 31, wid = threadIdx.x >> 5;
    const int g = lane >> 2, t = lane & 3;
    const int m_base = (wid & 3) * 32, n_base = (wid >> 2) * 32;
    const bool diag = (k0 + 63 > q0);
#pragma unroll
    for (int mt = 0; mt < 2; mt++)
#pragma unroll
        for (int nt = 0; nt < 4; nt++)
#pragma unroll
            for (int half = 0; half < 2; half++) {
                int gi = q0 + m_base + mt * 16 + g + half * 8;
                int gj = k0 + n_base + nt * 8 + 2 * t;
                float vx = c[mt * 4 + nt][half * 2];
                float vy = c[mt * 4 + nt][half * 2 + 1];
                if (diag) {
                    if (gj > gi) vx = 0.f;
                    if (gj + 1 > gi) vy = 0.f;
                }
                *(float2*)(abase + (size_t)gi * Ss + gj) = make_float2(vx, vy);
            }
}

// ---------------------------------------------------------------------------
// Softmax over j<=i. float4 loads/stores, shfl warp reductions, 2 barriers.
// Writes fp32 weights (d_out) + fp16 prob plane.
// ---------------------------------------------------------------------------
__global__ __launch_bounds__(256) void softmax_kernel(float* __restrict__ attn)
{
    int i = blockIdx.x, h = blockIdx.y, b = blockIdx.z;
    size_t roff = ((size_t)(b * NHh + h) * Ss + i) * Ss;
    float* row = attn + roff;
    __half* prh = g_Ph + roff;
    const int n = i + 1;
    const int n4 = n & ~3;
    const int tail = n - n4;
    const int tid = threadIdx.x, lane = tid & 31, wrp = tid >> 5;

    float vals[9];
    int cnt = 0;
    float mx = -INFINITY;
    for (int j = tid * 4; j < n4; j += 1024) {
        float4 v = *(const float4*)(row + j);
        vals[cnt++] = v.x; vals[cnt++] = v.y; vals[cnt++] = v.z; vals[cnt++] = v.w;
        mx = fmaxf(mx, fmaxf(fmaxf(v.x, v.y), fmaxf(v.z, v.w)));
    }
    if (tid < tail) {
        float s = row[n4 + tid];
        vals[cnt++] = s;
        mx = fmaxf(mx, s);
    }

#pragma unroll
    for (int o = 16; o; o >>= 1) mx = fmaxf(mx, __shfl_xor_sync(0xffffffffu, mx, o));
    __shared__ float rmax[8], rsum[8];
    if (lane == 0) rmax[wrp] = mx;
    __syncthreads();
    mx = rmax[0];
#pragma unroll
    for (int w = 1; w < 8; w++) mx = fmaxf(mx, rmax[w]);

    float sum = 0.f;
    for (int c2 = 0; c2 < cnt; c2++) {
        vals[c2] = __expf(vals[c2] - mx);
        sum += vals[c2];
    }
#pragma unroll
    for (int o = 16; o; o >>= 1) sum += __shfl_xor_sync(0xffffffffu, sum, o);
    if (lane == 0) rsum[wrp] = sum;
    __syncthreads();
    sum = 0.f;
#pragma unroll
    for (int w = 0; w < 8; w++) sum += rsum[w];
    float inv = 1.0f / sum;

    cnt = 0;
    for (int j = tid * 4; j < n4; j += 1024) {
        float4 v;
        v.x = vals[cnt++] * inv; v.y = vals[cnt++] * inv;
        v.z = vals[cnt++] * inv; v.w = vals[cnt++] * inv;
        *(float4*)(row + j) = v;
        *(__half2*)(prh + j)     = __halves2half2(__float2half_rn(v.x), __float2half_rn(v.y));
        *(__half2*)(prh + j + 2) = __halves2half2(__float2half_rn(v.z), __float2half_rn(v.w));
    }
    if (tid < tail) {
        float p = vals[cnt++] * inv;
        row[n4 + tid] = p;
        prh[n4 + tid] = __float2half_rn(p);
    }
}

// ---------------------------------------------------------------------------
// V transpose: g_V[bh][s][d] -> VTh[bh][d][s] (fp16 hi only)
// ---------------------------------------------------------------------------
__global__ __launch_bounds__(256) void vt_kernel()
{
    int bh = blockIdx.z;
    const float* V = g_V + (size_t)bh * Ss * HDd;
    __half* VTh = g_VTh + (size_t)bh * HDd * Ss;
    __shared__ float t[32][33];
    int s0 = blockIdx.x * 32, d0 = blockIdx.y * 32;
    int tx = threadIdx.x & 31, ty = threadIdx.x >> 5;
#pragma unroll
    for (int i = 0; i < 4; i++)
        t[ty + i * 8][tx] = V[(size_t)(s0 + ty + i * 8) * HDd + d0 + tx];
    __syncthreads();
#pragma unroll
    for (int i = 0; i < 4; i++)
        VTh[(size_t)(d0 + ty + i * 8) * Ss + s0 + tx] =
            __float2half_rn(t[tx][ty + i * 8]);
}

// ---------------------------------------------------------------------------
// PV: ctx = probs @ V (causal). Single-plane both sides -> 1 MMA per tile.
// ---------------------------------------------------------------------------
__global__ __launch_bounds__(256, 2) void pv_mma()
{
    extern __shared__ char smem[];
    const int qt = blockIdx.x, bh = blockIdx.y;
    const int q0 = qt * 128;
    const int b = bh >> 4, h = bh & 15;

    float c[8][4];
#pragma unroll
    for (int i = 0; i < 8; i++)
#pragma unroll
        for (int j = 0; j < 4; j++) c[i][j] = 0.f;

    size_t poff = ((size_t)bh * Ss + q0) * Ss;
    size_t voff = (size_t)bh * HDd * Ss;
    split_mainloop<64, 1, 1, 3>(g_Ph + poff, nullptr, Ss,
                                g_VTh + voff, nullptr, Ss,
                                (qt + 1) * 2, smem, c);

    const int lane = threadIdx.x & 31, wid = threadIdx.x >> 5;
    const int g = lane >> 2, t = lane & 3;
    const int m_base = (wid & 3) * 32, n_base = (wid >> 2) * 32;
#pragma unroll
    for (int mt = 0; mt < 2; mt++)
#pragma unroll
        for (int nt = 0; nt < 4; nt++)
#pragma unroll
            for (int half = 0; half < 2; half++) {
                int m = q0 + m_base + mt * 16 + g + half * 8;
                int d = n_base + nt * 8 + 2 * t;
                __half hx = __float2half_rn(c[mt * 4 + nt][half * 2]);
                __half hy = __float2half_rn(c[mt * 4 + nt][half * 2 + 1]);
                size_t base = ((size_t)b * Ss + m) * Hh + h * 64 + d;
                *(__half2*)(g_Ch + base) = __halves2half2(hx, hy);
            }
}

// ---------------------------------------------------------------------------
// Prep: X fp16 plane; weight transpose + split planes.
// ---------------------------------------------------------------------------
__global__ __launch_bounds__(256) void x_conv(const float* __restrict__ hs)
{
    size_t i = ((size_t)blockIdx.x * 256 + threadIdx.x) * 4;
    float4 v = *(const float4*)(hs + i);
    *(__half2*)(g_Xh + i)     = __halves2half2(__float2half_rn(v.x), __float2half_rn(v.y));
    *(__half2*)(g_Xh + i + 2) = __halves2half2(__float2half_rn(v.z), __float2half_rn(v.w));
}

__global__ __launch_bounds__(256) void wt_kernel(
    const float* __restrict__ qw, const float* __restrict__ kw,
    const float* __restrict__ vw, const float* __restrict__ ow)
{
    int w = blockIdx.z;
    const float* W = (w == 0) ? qw : (w == 1) ? kw : (w == 2) ? vw : ow;
    __half* WTh = g_Wh[w];
    __half* WTl = g_Wl[w];
    __shared__ float t[32][33];
    int n0 = blockIdx.x * 32, k0 = blockIdx.y * 32;
    int tx = threadIdx.x & 31, ty = threadIdx.x >> 5;
#pragma unroll
    for (int i = 0; i < 4; i++)
        t[ty + i * 8][tx] = W[(size_t)(k0 + ty + i * 8) * Hh + n0 + tx];
    __syncthreads();
#pragma unroll
    for (int i = 0; i < 4; i++) {
        __half h, l;
        split_f(t[tx][ty + i * 8], h, l);
        WTh[(size_t)(n0 + ty + i * 8) * Hh + k0 + tx] = h;
        WTl[(size_t)(n0 + ty + i * 8) * Hh + k0 + tx] = l;
    }
}

// ---------------------------------------------------------------------------
// Per-(b,s) gating (1/sqrt(HD) folded)
// ---------------------------------------------------------------------------
__global__ __launch_bounds__(256) void gate_kernel(
    const float* __restrict__ hs, const float* __restrict__ pros,
    const float* __restrict__ pg_w, const float* __restrict__ pg_b,
    const float* __restrict__ mg_w, const float* __restrict__ mg_b)
{
    int bs = blockIdx.x;
    const float* x = hs + (size_t)bs * Hh;
    int tid = threadIdx.x, lane = tid & 31, wrp = tid >> 5;

    float part = 0.f;
    for (int i = tid; i < Hh; i += 256) part += x[i] * mg_w[i];
#pragma unroll
    for (int o = 16; o; o >>= 1) part += __shfl_xor_sync(0xffffffffu, part, o);
    __shared__ float red[8];
    if (lane == 0) red[wrp] = part;
    __syncthreads();
    float tot = 0.f;
#pragma unroll
    for (int w = 0; w < 8; w++) tot += red[w];
    float mem = 1.0f + 0.5f / (1.0f + __expf(-(tot + mg_b[0])));

    if (tid < NHh) {
        const float* p = pros + (size_t)bs * 4;
        float a = p[0] * pg_w[0 * NHh + tid] + p[1] * pg_w[1 * NHh + tid]
                + p[2] * pg_w[2 * NHh + tid] + p[3] * pg_w[3 * NHh + tid]
                + pg_b[tid];
        float pg = 1.0f + 1.0f / (1.0f + __expf(-a));
        g_gain[(size_t)bs * NHh + tid] = pg * mem * 0.125f;
    }
}

// ---------------------------------------------------------------------------
extern "C" void kernel_launch(void* const* d_in, const int* in_sizes, int n_in,
                              void* d_out, int out_size)
{
    const float* hs   = (const float*)d_in[0];
    const float* pros = (const float*)d_in[1];
    const float* q_w  = (const float*)d_in[2];
    const float* q_b  = (const float*)d_in[3];
    const float* k_w  = (const float*)d_in[4];
    const float* k_b  = (const float*)d_in[5];
    const float* v_w  = (const float*)d_in[6];
    const float* v_b  = (const float*)d_in[7];
    const float* o_w  = (const float*)d_in[8];
    const float* o_b  = (const float*)d_in[9];
    const float* pg_w = (const float*)d_in[10];
    const float* pg_b = (const float*)d_in[11];
    const float* mg_w = (const float*)d_in[12];
    const float* mg_b = (const float*)d_in[13];

    float* out  = (float*)d_out;
    float* attn = out + (size_t)Bb * Ss * Hh;

    static int attr_done = 0;
    if (!attr_done) {
        cudaFuncSetAttribute(gemm_qkv,   cudaFuncAttributeMaxDynamicSharedMemorySize, SMEM_QKV);
        cudaFuncSetAttribute(gemm_out,   cudaFuncAttributeMaxDynamicSharedMemorySize, SMEM_QKV);
        cudaFuncSetAttribute(scores_mma, cudaFuncAttributeMaxDynamicSharedMemorySize, SMEM_SC);
        cudaFuncSetAttribute(pv_mma,     cudaFuncAttributeMaxDynamicSharedMemorySize, SMEM_PV);
        attr_done = 1;
    }

    gate_kernel<<<Bb * Ss, 256>>>(hs, pros, pg_w, pg_b, mg_w, mg_b);
    x_conv<<<(Mtot * Hh) / (256 * 4), 256>>>(hs);
    wt_kernel<<<dim3(32, 32, 4), 256>>>(q_w, k_w, v_w, o_w);

    gemm_qkv<<<dim3(16, 32, 3), 256, SMEM_QKV>>>(q_b, k_b, v_b);
    vt_kernel<<<dim3(64, 2, 32), 256>>>();

    scores_mma<<<dim3(32, 16, 32), 256, SMEM_SC>>>(attn);
    softmax_kernel<<<dim3(Ss, NHh, Bb), 256>>>(attn);
    pv_mma<<<dim3(16, 32), 256, SMEM_PV>>>();

    gemm_out<<<dim3(16, 32), 256, SMEM_QKV>>>(o_b, out);
}

// round 12
// speedup vs baseline: 4.2152x; 1.1202x over previous
#include <cuda_runtime.h>
#include <cuda_fp16.h>
#include <math.h>
#include <stdint.h>

#define Bb  2
#define Ss  2048
#define Hh  1024
#define NHh 16
#define HDd 64
#define Mtot (Bb * Ss)          // 4096

// ---------------- scratch planes (__device__ globals; no allocs) -----------
__device__ __half g_Xh[(size_t)Mtot * Hh];            // fp16-rounded X
__device__ __half g_Wh[4][(size_t)Hh * Hh];           // transposed weights hi
__device__ __half g_Wl[(size_t)Hh * Hh];              // o_w lo plane only
__device__ __half g_Qh[(size_t)Bb * NHh * Ss * HDd];  // Q hi (gain folded)
__device__ __half g_Kh[(size_t)Bb * NHh * Ss * HDd];
__device__ float  g_V [(size_t)Bb * NHh * Ss * HDd];
__device__ __half g_VTh[(size_t)Bb * NHh * HDd * Ss];
__device__ __half g_Ph[(size_t)Bb * NHh * Ss * Ss];   // prob hi plane (pad stays 0)
__device__ __half g_Ch[(size_t)Mtot * Hh];            // fp16 ctx
__device__ float  g_gain[(size_t)Bb * Ss * NHh];

// ---------------- helpers ---------------------------------------------------
__device__ __forceinline__ uint32_t smem_u32(const void* p) {
    uint32_t a;
    asm("{ .reg .u64 t; cvta.to.shared.u64 t, %1; cvt.u32.u64 %0, t; }" : "=r"(a) : "l"(p));
    return a;
}
__device__ __forceinline__ void split_f(float x, __half& h, __half& l) {
    h = __float2half_rn(x);
    l = __float2half_rn(x - __half2float(h));
}
__device__ __forceinline__ void ldsm4(uint32_t* r, uint32_t addr) {
    asm volatile("ldmatrix.sync.aligned.m8n8.x4.shared.b16 {%0,%1,%2,%3}, [%4];"
        : "=r"(r[0]), "=r"(r[1]), "=r"(r[2]), "=r"(r[3]) : "r"(addr));
}
__device__ __forceinline__ void mma16(float* c, const uint32_t* a, const uint32_t* b) {
    asm volatile("mma.sync.aligned.m16n8k16.row.col.f32.f16.f16.f32 "
        "{%0,%1,%2,%3},{%4,%5,%6,%7},{%8,%9},{%0,%1,%2,%3};"
        : "+f"(c[0]), "+f"(c[1]), "+f"(c[2]), "+f"(c[3])
        : "r"(a[0]), "r"(a[1]), "r"(a[2]), "r"(a[3]), "r"(b[0]), "r"(b[1]));
}
__device__ __forceinline__ void cpa16(uint32_t dst, const void* src) {
    asm volatile("cp.async.cg.shared.global [%0], [%1], 16;" :: "r"(dst), "l"(src));
}
template<int N>
__device__ __forceinline__ void cp_wait() {
    asm volatile("cp.async.wait_group %0;" :: "n"(N < 0 ? 0 : N));
}

// ---------------------------------------------------------------------------
// Split-fp16 tensor-core mainloop.
// AP/BP = #planes for A/B. MMAs per tile: A0*B0 [+ A0*B1 if BP=2] [+ A1*B0 if AP=2].
// NS = pipeline stages, ONE __syncthreads per k-chunk.
// C[128 x BN] += A[128 x 64*nkc] @ Bt[BN x 64*nkc]^T, K-major planes.
// ---------------------------------------------------------------------------
template<int BN, int AP, int BP, int NS>
__device__ __forceinline__ void split_mainloop(
    const __half* __restrict__ Ah, const __half* __restrict__ Al, int ldA,
    const __half* __restrict__ Bh, const __half* __restrict__ Bl, int ldB,
    int nkc, char* smem, float (*cacc)[4])
{
    constexpr int NT = BN / 16;
    constexpr int APL = 128 * 128;       // bytes per A plane
    constexpr int BPL = BN * 128;        // bytes per B plane
    constexpr int BUF = AP * APL + BP * BPL;

    const int tid = threadIdx.x, lane = tid & 31, wid = tid >> 5;
    const int m_base = (wid & 3) * 32;
    const int n_base = (wid >> 2) * (BN / 2);
    uint32_t sbase = smem_u32(smem);

    auto load = [&](int kc, int b) {
        uint32_t s0 = sbase + b * BUF;
        for (int idx = tid; idx < 1024; idx += 256) {
            int row = idx >> 3, ch = idx & 7;
            uint32_t off = row * 128 + ((ch ^ (row & 7)) << 4);
            cpa16(s0 + off, Ah + (size_t)row * ldA + kc * 64 + ch * 8);
            if (AP == 2)
                cpa16(s0 + APL + off, Al + (size_t)row * ldA + kc * 64 + ch * 8);
        }
        for (int idx = tid; idx < BN * 8; idx += 256) {
            int row = idx >> 3, ch = idx & 7;
            uint32_t off = row * 128 + ((ch ^ (row & 7)) << 4);
            cpa16(s0 + AP * APL + off, Bh + (size_t)row * ldB + kc * 64 + ch * 8);
            if (BP == 2)
                cpa16(s0 + AP * APL + BPL + off, Bl + (size_t)row * ldB + kc * 64 + ch * 8);
        }
        asm volatile("cp.async.commit_group;");
    };

#pragma unroll
    for (int s = 0; s < NS - 1; s++)
        if (s < nkc) load(s, s);

    for (int kc = 0; kc < nkc; kc++) {
        int b = kc % NS;
        if (kc + NS - 1 < nkc) cp_wait<NS - 2>();
        else                   cp_wait<0>();
        __syncthreads();
        if (kc + NS - 1 < nkc) load(kc + NS - 1, (kc + NS - 1) % NS);
        uint32_t s0 = sbase + b * BUF;
#pragma unroll
        for (int ks = 0; ks < 4; ks++) {
            uint32_t a[AP][2][4];
            {
                int row = m_base + (lane & 7) + ((lane >> 3) & 1) * 8;
                int ch  = ks * 2 + (lane >> 4);
#pragma unroll
                for (int mt = 0; mt < 2; mt++) {
                    int r2 = row + mt * 16;
                    uint32_t off = r2 * 128 + ((ch ^ (r2 & 7)) << 4);
                    ldsm4(a[0][mt], s0 + off);
                    if (AP == 2) ldsm4(a[1][mt], s0 + APL + off);
                }
            }
            uint32_t bf[BP][NT][2];
            {
                int row = n_base + (lane & 7) + ((lane >> 4) << 3);
                int ch  = ks * 2 + ((lane >> 3) & 1);
#pragma unroll
                for (int np = 0; np < NT / 2; np++) {
                    int r2 = row + np * 16;
                    uint32_t off = r2 * 128 + ((ch ^ (r2 & 7)) << 4);
                    uint32_t t[4];
                    ldsm4(t, s0 + AP * APL + off);
                    bf[0][2 * np][0] = t[0]; bf[0][2 * np][1] = t[1];
                    bf[0][2 * np + 1][0] = t[2]; bf[0][2 * np + 1][1] = t[3];
                    if (BP == 2) {
                        ldsm4(t, s0 + AP * APL + BPL + off);
                        bf[1][2 * np][0] = t[0]; bf[1][2 * np][1] = t[1];
                        bf[1][2 * np + 1][0] = t[2]; bf[1][2 * np + 1][1] = t[3];
                    }
                }
            }
#pragma unroll
            for (int mt = 0; mt < 2; mt++)
#pragma unroll
                for (int nt = 0; nt < NT; nt++) {
                    float* c = cacc[mt * NT + nt];
                    mma16(c, a[0][mt], bf[0][nt]);
                    if (BP == 2) mma16(c, a[0][mt], bf[1][nt]);
                    if (AP == 2) mma16(c, a[1][mt], bf[0][nt]);
                }
        }
    }
}

#define BUF_12 (128 * 128 + 2 * 64 * 128)   // 32 KB (AP=1, BP=2)
#define BUF_11 (128 * 128 + 1 * 64 * 128)   // 24 KB (AP=1, BP=1)
#define SMEM_QKV (3 * BUF_11)               // 72 KB
#define SMEM_OUT (3 * BUF_12)               // 96 KB
#define SMEM_SC  (BUF_11)                   // 24 KB (nkc=1)
#define SMEM_PV  (3 * BUF_11)               // 72 KB

// ---------------------------------------------------------------------------
// QKV projection (z selects Q/K/V). BM=128, BN=64 (one head per block).
// Plain fp16 GEMM (1 MMA/tile). Q gain folded; V emits fp32.
// ---------------------------------------------------------------------------
__global__ __launch_bounds__(256, 2) void gemm_qkv(
    const float* __restrict__ bq, const float* __restrict__ bk,
    const float* __restrict__ bv)
{
    extern __shared__ char smem[];
    const int z = blockIdx.z;
    const int n0 = blockIdx.x * 64, m0 = blockIdx.y * 128;
    const float* bias = (z == 0) ? bq : (z == 1) ? bk : bv;

    float c[8][4];
#pragma unroll
    for (int i = 0; i < 8; i++)
#pragma unroll
        for (int j = 0; j < 4; j++) c[i][j] = 0.f;

    split_mainloop<64, 1, 1, 3>(g_Xh + (size_t)m0 * Hh, nullptr, Hh,
                                g_Wh[z] + (size_t)n0 * Hh, nullptr, Hh,
                                16, smem, c);

    const int lane = threadIdx.x & 31, wid = threadIdx.x >> 5;
    const int g = lane >> 2, t = lane & 3;
    const int m_base = (wid & 3) * 32, n_base = (wid >> 2) * 32;
    const int h = n0 >> 6;
#pragma unroll
    for (int mt = 0; mt < 2; mt++)
#pragma unroll
        for (int nt = 0; nt < 4; nt++)
#pragma unroll
            for (int half = 0; half < 2; half++) {
                int m = m0 + m_base + mt * 16 + g + half * 8;
                int n = n0 + n_base + nt * 8 + 2 * t;
                float vx = c[mt * 4 + nt][half * 2 + 0] + bias[n];
                float vy = c[mt * 4 + nt][half * 2 + 1] + bias[n + 1];
                int d = n & 63;
                int bidx = m >> 11, srow = m & (Ss - 1);
                size_t base = (((size_t)(bidx * NHh + h)) * Ss + srow) * HDd + d;
                if (z == 2) {
                    *(float2*)(g_V + base) = make_float2(vx, vy);
                } else if (z == 0) {
                    float gs = g_gain[(size_t)m * NHh + h];
                    vx *= gs; vy *= gs;
                    *(__half2*)(g_Qh + base) =
                        __halves2half2(__float2half_rn(vx), __float2half_rn(vy));
                } else {
                    *(__half2*)(g_Kh + base) =
                        __halves2half2(__float2half_rn(vx), __float2half_rn(vy));
                }
            }
}

// ---------------------------------------------------------------------------
// Output projection: fp16 ctx @ o_w + o_b -> d_out[:B*S*H] (fp32). 2 MMAs.
// ---------------------------------------------------------------------------
__global__ __launch_bounds__(256, 2) void gemm_out(
    const float* __restrict__ bias, float* __restrict__ out)
{
    extern __shared__ char smem[];
    const int n0 = blockIdx.x * 64, m0 = blockIdx.y * 128;

    float c[8][4];
#pragma unroll
    for (int i = 0; i < 8; i++)
#pragma unroll
        for (int j = 0; j < 4; j++) c[i][j] = 0.f;

    split_mainloop<64, 1, 2, 3>(g_Ch + (size_t)m0 * Hh, nullptr, Hh,
                                g_Wh[3] + (size_t)n0 * Hh, g_Wl + (size_t)n0 * Hh, Hh,
                                16, smem, c);

    const int lane = threadIdx.x & 31, wid = threadIdx.x >> 5;
    const int g = lane >> 2, t = lane & 3;
    const int m_base = (wid & 3) * 32, n_base = (wid >> 2) * 32;
#pragma unroll
    for (int mt = 0; mt < 2; mt++)
#pragma unroll
        for (int nt = 0; nt < 4; nt++)
#pragma unroll
            for (int half = 0; half < 2; half++) {
                int m = m0 + m_base + mt * 16 + g + half * 8;
                int n = n0 + n_base + nt * 8 + 2 * t;
                float2 v = make_float2(c[mt * 4 + nt][half * 2] + bias[n],
                                       c[mt * 4 + nt][half * 2 + 1] + bias[n + 1]);
                *(float2*)(out + (size_t)m * Hh + n) = v;
            }
}

// ---------------------------------------------------------------------------
// Scores: 128 q-rows x 64 k-cols per block; 1-MMA (Qh*Kh).
// Upper tiles zero-fill; diagonal tiles mask per element.
// ---------------------------------------------------------------------------
__global__ __launch_bounds__(256, 2) void scores_mma(float* __restrict__ attn)
{
    extern __shared__ char smem[];
    const int kt = blockIdx.x, qt = blockIdx.y, bh = blockIdx.z;
    const int q0 = qt * 128, k0 = kt * 64;
    float* abase = attn + (size_t)bh * Ss * Ss;

    if (k0 > q0 + 127) {
        float4 z4 = make_float4(0.f, 0.f, 0.f, 0.f);
        for (int idx = threadIdx.x; idx < 128 * 16; idx += 256) {
            int row = idx >> 4, cc = idx & 15;
            *(float4*)(abase + (size_t)(q0 + row) * Ss + k0 + cc * 4) = z4;
        }
        return;
    }

    float c[8][4];
#pragma unroll
    for (int i = 0; i < 8; i++)
#pragma unroll
        for (int j = 0; j < 4; j++) c[i][j] = 0.f;

    size_t qoff = ((size_t)bh * Ss + q0) * HDd;
    size_t koff = ((size_t)bh * Ss + k0) * HDd;
    split_mainloop<64, 1, 1, 2>(g_Qh + qoff, nullptr, HDd,
                                g_Kh + koff, nullptr, HDd, 1, smem, c);

    const int lane = threadIdx.x & 31, wid = threadIdx.x >> 5;
    const int g = lane >> 2, t = lane & 3;
    const int m_base = (wid & 3) * 32, n_base = (wid >> 2) * 32;
    const bool diag = (k0 + 63 > q0);
#pragma unroll
    for (int mt = 0; mt < 2; mt++)
#pragma unroll
        for (int nt = 0; nt < 4; nt++)
#pragma unroll
            for (int half = 0; half < 2; half++) {
                int gi = q0 + m_base + mt * 16 + g + half * 8;
                int gj = k0 + n_base + nt * 8 + 2 * t;
                float vx = c[mt * 4 + nt][half * 2];
                float vy = c[mt * 4 + nt][half * 2 + 1];
                if (diag) {
                    if (gj > gi) vx = 0.f;
                    if (gj + 1 > gi) vy = 0.f;
                }
                *(float2*)(abase + (size_t)gi * Ss + gj) = make_float2(vx, vy);
            }
}

// ---------------------------------------------------------------------------
// Softmax over j<=i. float4 loads/stores, shfl warp reductions, 2 barriers.
// Writes fp32 weights (d_out) + fp16 prob plane.
// ---------------------------------------------------------------------------
__global__ __launch_bounds__(256) void softmax_kernel(float* __restrict__ attn)
{
    int i = blockIdx.x, h = blockIdx.y, b = blockIdx.z;
    size_t roff = ((size_t)(b * NHh + h) * Ss + i) * Ss;
    float* row = attn + roff;
    __half* prh = g_Ph + roff;
    const int n = i + 1;
    const int n4 = n & ~3;
    const int tail = n - n4;
    const int tid = threadIdx.x, lane = tid & 31, wrp = tid >> 5;

    float vals[9];
    int cnt = 0;
    float mx = -INFINITY;
    for (int j = tid * 4; j < n4; j += 1024) {
        float4 v = *(const float4*)(row + j);
        vals[cnt++] = v.x; vals[cnt++] = v.y; vals[cnt++] = v.z; vals[cnt++] = v.w;
        mx = fmaxf(mx, fmaxf(fmaxf(v.x, v.y), fmaxf(v.z, v.w)));
    }
    if (tid < tail) {
        float s = row[n4 + tid];
        vals[cnt++] = s;
        mx = fmaxf(mx, s);
    }

#pragma unroll
    for (int o = 16; o; o >>= 1) mx = fmaxf(mx, __shfl_xor_sync(0xffffffffu, mx, o));
    __shared__ float rmax[8], rsum[8];
    if (lane == 0) rmax[wrp] = mx;
    __syncthreads();
    mx = rmax[0];
#pragma unroll
    for (int w = 1; w < 8; w++) mx = fmaxf(mx, rmax[w]);

    float sum = 0.f;
    for (int c2 = 0; c2 < cnt; c2++) {
        vals[c2] = __expf(vals[c2] - mx);
        sum += vals[c2];
    }
#pragma unroll
    for (int o = 16; o; o >>= 1) sum += __shfl_xor_sync(0xffffffffu, sum, o);
    if (lane == 0) rsum[wrp] = sum;
    __syncthreads();
    sum = 0.f;
#pragma unroll
    for (int w = 0; w < 8; w++) sum += rsum[w];
    float inv = 1.0f / sum;

    cnt = 0;
    for (int j = tid * 4; j < n4; j += 1024) {
        float4 v;
        v.x = vals[cnt++] * inv; v.y = vals[cnt++] * inv;
        v.z = vals[cnt++] * inv; v.w = vals[cnt++] * inv;
        *(float4*)(row + j) = v;
        *(__half2*)(prh + j)     = __halves2half2(__float2half_rn(v.x), __float2half_rn(v.y));
        *(__half2*)(prh + j + 2) = __halves2half2(__float2half_rn(v.z), __float2half_rn(v.w));
    }
    if (tid < tail) {
        float p = vals[cnt++] * inv;
        row[n4 + tid] = p;
        prh[n4 + tid] = __float2half_rn(p);
    }
}

// ---------------------------------------------------------------------------
// V transpose: g_V[bh][s][d] -> VTh[bh][d][s] (fp16 hi only)
// ---------------------------------------------------------------------------
__global__ __launch_bounds__(256) void vt_kernel()
{
    int bh = blockIdx.z;
    const float* V = g_V + (size_t)bh * Ss * HDd;
    __half* VTh = g_VTh + (size_t)bh * HDd * Ss;
    __shared__ float t[32][33];
    int s0 = blockIdx.x * 32, d0 = blockIdx.y * 32;
    int tx = threadIdx.x & 31, ty = threadIdx.x >> 5;
#pragma unroll
    for (int i = 0; i < 4; i++)
        t[ty + i * 8][tx] = V[(size_t)(s0 + ty + i * 8) * HDd + d0 + tx];
    __syncthreads();
#pragma unroll
    for (int i = 0; i < 4; i++)
        VTh[(size_t)(d0 + ty + i * 8) * Ss + s0 + tx] =
            __float2half_rn(t[tx][ty + i * 8]);
}

// ---------------------------------------------------------------------------
// PV: ctx = probs @ V (causal). Single-plane both sides -> 1 MMA per tile.
// ---------------------------------------------------------------------------
__global__ __launch_bounds__(256, 2) void pv_mma()
{
    extern __shared__ char smem[];
    const int qt = blockIdx.x, bh = blockIdx.y;
    const int q0 = qt * 128;
    const int b = bh >> 4, h = bh & 15;

    float c[8][4];
#pragma unroll
    for (int i = 0; i < 8; i++)
#pragma unroll
        for (int j = 0; j < 4; j++) c[i][j] = 0.f;

    size_t poff = ((size_t)bh * Ss + q0) * Ss;
    size_t voff = (size_t)bh * HDd * Ss;
    split_mainloop<64, 1, 1, 3>(g_Ph + poff, nullptr, Ss,
                                g_VTh + voff, nullptr, Ss,
                                (qt + 1) * 2, smem, c);

    const int lane = threadIdx.x & 31, wid = threadIdx.x >> 5;
    const int g = lane >> 2, t = lane & 3;
    const int m_base = (wid & 3) * 32, n_base = (wid >> 2) * 32;
#pragma unroll
    for (int mt = 0; mt < 2; mt++)
#pragma unroll
        for (int nt = 0; nt < 4; nt++)
#pragma unroll
            for (int half = 0; half < 2; half++) {
                int m = q0 + m_base + mt * 16 + g + half * 8;
                int d = n_base + nt * 8 + 2 * t;
                __half hx = __float2half_rn(c[mt * 4 + nt][half * 2]);
                __half hy = __float2half_rn(c[mt * 4 + nt][half * 2 + 1]);
                size_t base = ((size_t)b * Ss + m) * Hh + h * 64 + d;
                *(__half2*)(g_Ch + base) = __halves2half2(hx, hy);
            }
}

// ---------------------------------------------------------------------------
// Prep: X fp16 plane; weight transpose (+ lo plane for o_w only).
// ---------------------------------------------------------------------------
__global__ __launch_bounds__(256) void x_conv(const float* __restrict__ hs)
{
    size_t i = ((size_t)blockIdx.x * 256 + threadIdx.x) * 4;
    float4 v = *(const float4*)(hs + i);
    *(__half2*)(g_Xh + i)     = __halves2half2(__float2half_rn(v.x), __float2half_rn(v.y));
    *(__half2*)(g_Xh + i + 2) = __halves2half2(__float2half_rn(v.z), __float2half_rn(v.w));
}

__global__ __launch_bounds__(256) void wt_kernel(
    const float* __restrict__ qw, const float* __restrict__ kw,
    const float* __restrict__ vw, const float* __restrict__ ow)
{
    int w = blockIdx.z;
    const float* W = (w == 0) ? qw : (w == 1) ? kw : (w == 2) ? vw : ow;
    __half* WTh = g_Wh[w];
    __shared__ float t[32][33];
    int n0 = blockIdx.x * 32, k0 = blockIdx.y * 32;
    int tx = threadIdx.x & 31, ty = threadIdx.x >> 5;
#pragma unroll
    for (int i = 0; i < 4; i++)
        t[ty + i * 8][tx] = W[(size_t)(k0 + ty + i * 8) * Hh + n0 + tx];
    __syncthreads();
#pragma unroll
    for (int i = 0; i < 4; i++) {
        float x = t[tx][ty + i * 8];
        __half h, l;
        split_f(x, h, l);
        size_t idx = (size_t)(n0 + ty + i * 8) * Hh + k0 + tx;
        WTh[idx] = h;
        if (w == 3) g_Wl[idx] = l;
    }
}

// ---------------------------------------------------------------------------
// Per-(b,s) gating (1/sqrt(HD) folded)
// ---------------------------------------------------------------------------
__global__ __launch_bounds__(256) void gate_kernel(
    const float* __restrict__ hs, const float* __restrict__ pros,
    const float* __restrict__ pg_w, const float* __restrict__ pg_b,
    const float* __restrict__ mg_w, const float* __restrict__ mg_b)
{
    int bs = blockIdx.x;
    const float* x = hs + (size_t)bs * Hh;
    int tid = threadIdx.x, lane = tid & 31, wrp = tid >> 5;

    float part = 0.f;
    for (int i = tid; i < Hh; i += 256) part += x[i] * mg_w[i];
#pragma unroll
    for (int o = 16; o; o >>= 1) part += __shfl_xor_sync(0xffffffffu, part, o);
    __shared__ float red[8];
    if (lane == 0) red[wrp] = part;
    __syncthreads();
    float tot = 0.f;
#pragma unroll
    for (int w = 0; w < 8; w++) tot += red[w];
    float mem = 1.0f + 0.5f / (1.0f + __expf(-(tot + mg_b[0])));

    if (tid < NHh) {
        const float* p = pros + (size_t)bs * 4;
        float a = p[0] * pg_w[0 * NHh + tid] + p[1] * pg_w[1 * NHh + tid]
                + p[2] * pg_w[2 * NHh + tid] + p[3] * pg_w[3 * NHh + tid]
                + pg_b[tid];
        float pg = 1.0f + 1.0f / (1.0f + __expf(-a));
        g_gain[(size_t)bs * NHh + tid] = pg * mem * 0.125f;
    }
}

// ---------------------------------------------------------------------------
extern "C" void kernel_launch(void* const* d_in, const int* in_sizes, int n_in,
                              void* d_out, int out_size)
{
    const float* hs   = (const float*)d_in[0];
    const float* pros = (const float*)d_in[1];
    const float* q_w  = (const float*)d_in[2];
    const float* q_b  = (const float*)d_in[3];
    const float* k_w  = (const float*)d_in[4];
    const float* k_b  = (const float*)d_in[5];
    const float* v_w  = (const float*)d_in[6];
    const float* v_b  = (const float*)d_in[7];
    const float* o_w  = (const float*)d_in[8];
    const float* o_b  = (const float*)d_in[9];
    const float* pg_w = (const float*)d_in[10];
    const float* pg_b = (const float*)d_in[11];
    const float* mg_w = (const float*)d_in[12];
    const float* mg_b = (const float*)d_in[13];

    float* out  = (float*)d_out;
    float* attn = out + (size_t)Bb * Ss * Hh;

    static int attr_done = 0;
    if (!attr_done) {
        cudaFuncSetAttribute(gemm_qkv,   cudaFuncAttributeMaxDynamicSharedMemorySize, SMEM_QKV);
        cudaFuncSetAttribute(gemm_out,   cudaFuncAttributeMaxDynamicSharedMemorySize, SMEM_OUT);
        cudaFuncSetAttribute(scores_mma, cudaFuncAttributeMaxDynamicSharedMemorySize, SMEM_SC);
        cudaFuncSetAttribute(pv_mma,     cudaFuncAttributeMaxDynamicSharedMemorySize, SMEM_PV);
        attr_done = 1;
    }

    gate_kernel<<<Bb * Ss, 256>>>(hs, pros, pg_w, pg_b, mg_w, mg_b);
    x_conv<<<(Mtot * Hh) / (256 * 4), 256>>>(hs);
    wt_kernel<<<dim3(32, 32, 4), 256>>>(q_w, k_w, v_w, o_w);

    gemm_qkv<<<dim3(16, 32, 3), 256, SMEM_QKV>>>(q_b, k_b, v_b);
    vt_kernel<<<dim3(64, 2, 32), 256>>>();

    scores_mma<<<dim3(32, 16, 32), 256, SMEM_SC>>>(attn);
    softmax_kernel<<<dim3(Ss, NHh, Bb), 256>>>(attn);
    pv_mma<<<dim3(16, 32), 256, SMEM_PV>>>();

    gemm_out<<<dim3(16, 32), 256, SMEM_OUT>>>(o_b, out);
}

// round 13
// speedup vs baseline: 4.5193x; 1.0722x over previous
#include <cuda_runtime.h>
#include <cuda_fp16.h>
#include <math.h>
#include <stdint.h>

#define Bb  2
#define Ss  2048
#define Hh  1024
#define NHh 16
#define HDd 64
#define Mtot (Bb * Ss)          // 4096

// ---------------- scratch planes (__device__ globals; no allocs) -----------
__device__ __half g_Xh[(size_t)Mtot * Hh];            // fp16-rounded X
__device__ __half g_Wh[4][(size_t)Hh * Hh];           // transposed weights hi
__device__ __half g_Wl[(size_t)Hh * Hh];              // o_w lo plane only
__device__ __half g_Qh[(size_t)Bb * NHh * Ss * HDd];  // Q hi (gain folded)
__device__ __half g_Kh[(size_t)Bb * NHh * Ss * HDd];
__device__ float  g_V [(size_t)Bb * NHh * Ss * HDd];
__device__ __half g_VTh[(size_t)Bb * NHh * HDd * Ss];
__device__ __half g_Ph[(size_t)Bb * NHh * Ss * Ss];   // prob hi plane (pad stays 0)
__device__ __half g_Ch[(size_t)Mtot * Hh];            // fp16 ctx
__device__ float  g_gain[(size_t)Bb * Ss * NHh];

// ---------------- helpers ---------------------------------------------------
__device__ __forceinline__ uint32_t smem_u32(const void* p) {
    uint32_t a;
    asm("{ .reg .u64 t; cvta.to.shared.u64 t, %1; cvt.u32.u64 %0, t; }" : "=r"(a) : "l"(p));
    return a;
}
__device__ __forceinline__ void split_f(float x, __half& h, __half& l) {
    h = __float2half_rn(x);
    l = __float2half_rn(x - __half2float(h));
}
__device__ __forceinline__ void ldsm4(uint32_t* r, uint32_t addr) {
    asm volatile("ldmatrix.sync.aligned.m8n8.x4.shared.b16 {%0,%1,%2,%3}, [%4];"
        : "=r"(r[0]), "=r"(r[1]), "=r"(r[2]), "=r"(r[3]) : "r"(addr));
}
__device__ __forceinline__ void mma16(float* c, const uint32_t* a, const uint32_t* b) {
    asm volatile("mma.sync.aligned.m16n8k16.row.col.f32.f16.f16.f32 "
        "{%0,%1,%2,%3},{%4,%5,%6,%7},{%8,%9},{%0,%1,%2,%3};"
        : "+f"(c[0]), "+f"(c[1]), "+f"(c[2]), "+f"(c[3])
        : "r"(a[0]), "r"(a[1]), "r"(a[2]), "r"(a[3]), "r"(b[0]), "r"(b[1]));
}
__device__ __forceinline__ void cpa16(uint32_t dst, const void* src) {
    asm volatile("cp.async.cg.shared.global [%0], [%1], 16;" :: "r"(dst), "l"(src));
}
template<int N>
__device__ __forceinline__ void cp_wait() {
    asm volatile("cp.async.wait_group %0;" :: "n"(N < 0 ? 0 : N));
}

// ---------------------------------------------------------------------------
// Split-fp16 tensor-core mainloop.
// AP/BP = #planes for A/B. MMAs: A0*B0 [+ A0*B1 if BP=2] [+ A1*B0 if AP=2].
// NS = pipeline stages, ONE __syncthreads per k-chunk.
// C[128 x BN] += A[128 x 64*nkc] @ Bt[BN x 64*nkc]^T, K-major planes.
// 8 warps: 4 M x 2 N; warp tile = 32 x (BN/2).
// ---------------------------------------------------------------------------
template<int BN, int AP, int BP, int NS>
__device__ __forceinline__ void split_mainloop(
    const __half* __restrict__ Ah, const __half* __restrict__ Al, int ldA,
    const __half* __restrict__ Bh, const __half* __restrict__ Bl, int ldB,
    int nkc, char* smem, float (*cacc)[4])
{
    constexpr int NT = BN / 16;
    constexpr int APL = 128 * 128;       // bytes per A plane
    constexpr int BPL = BN * 128;        // bytes per B plane
    constexpr int BUF = AP * APL + BP * BPL;

    const int tid = threadIdx.x, lane = tid & 31, wid = tid >> 5;
    const int m_base = (wid & 3) * 32;
    const int n_base = (wid >> 2) * (BN / 2);
    uint32_t sbase = smem_u32(smem);

    auto load = [&](int kc, int b) {
        uint32_t s0 = sbase + b * BUF;
        for (int idx = tid; idx < 1024; idx += 256) {
            int row = idx >> 3, ch = idx & 7;
            uint32_t off = row * 128 + ((ch ^ (row & 7)) << 4);
            cpa16(s0 + off, Ah + (size_t)row * ldA + kc * 64 + ch * 8);
            if (AP == 2)
                cpa16(s0 + APL + off, Al + (size_t)row * ldA + kc * 64 + ch * 8);
        }
        for (int idx = tid; idx < BN * 8; idx += 256) {
            int row = idx >> 3, ch = idx & 7;
            uint32_t off = row * 128 + ((ch ^ (row & 7)) << 4);
            cpa16(s0 + AP * APL + off, Bh + (size_t)row * ldB + kc * 64 + ch * 8);
            if (BP == 2)
                cpa16(s0 + AP * APL + BPL + off, Bl + (size_t)row * ldB + kc * 64 + ch * 8);
        }
        asm volatile("cp.async.commit_group;");
    };

#pragma unroll
    for (int s = 0; s < NS - 1; s++)
        if (s < nkc) load(s, s);

    for (int kc = 0; kc < nkc; kc++) {
        int b = kc % NS;
        if (kc + NS - 1 < nkc) cp_wait<NS - 2>();
        else                   cp_wait<0>();
        __syncthreads();
        if (kc + NS - 1 < nkc) load(kc + NS - 1, (kc + NS - 1) % NS);
        uint32_t s0 = sbase + b * BUF;
#pragma unroll
        for (int ks = 0; ks < 4; ks++) {
            uint32_t a[AP][2][4];
            {
                int row = m_base + (lane & 7) + ((lane >> 3) & 1) * 8;
                int ch  = ks * 2 + (lane >> 4);
#pragma unroll
                for (int mt = 0; mt < 2; mt++) {
                    int r2 = row + mt * 16;
                    uint32_t off = r2 * 128 + ((ch ^ (r2 & 7)) << 4);
                    ldsm4(a[0][mt], s0 + off);
                    if (AP == 2) ldsm4(a[1][mt], s0 + APL + off);
                }
            }
            uint32_t bf[BP][NT][2];
            {
                int row = n_base + (lane & 7) + ((lane >> 4) << 3);
                int ch  = ks * 2 + ((lane >> 3) & 1);
#pragma unroll
                for (int np = 0; np < NT / 2; np++) {
                    int r2 = row + np * 16;
                    uint32_t off = r2 * 128 + ((ch ^ (r2 & 7)) << 4);
                    uint32_t t[4];
                    ldsm4(t, s0 + AP * APL + off);
                    bf[0][2 * np][0] = t[0]; bf[0][2 * np][1] = t[1];
                    bf[0][2 * np + 1][0] = t[2]; bf[0][2 * np + 1][1] = t[3];
                    if (BP == 2) {
                        ldsm4(t, s0 + AP * APL + BPL + off);
                        bf[1][2 * np][0] = t[0]; bf[1][2 * np][1] = t[1];
                        bf[1][2 * np + 1][0] = t[2]; bf[1][2 * np + 1][1] = t[3];
                    }
                }
            }
#pragma unroll
            for (int mt = 0; mt < 2; mt++)
#pragma unroll
                for (int nt = 0; nt < NT; nt++) {
                    float* c = cacc[mt * NT + nt];
                    mma16(c, a[0][mt], bf[0][nt]);
                    if (BP == 2) mma16(c, a[0][mt], bf[1][nt]);
                    if (AP == 2) mma16(c, a[1][mt], bf[0][nt]);
                }
        }
    }
}

#define BUF_N128_B1 (128 * 128 + 128 * 128)       // 32 KB
#define BUF_N128_B2 (128 * 128 + 2 * 128 * 128)   // 48 KB
#define BUF_N64_B1  (128 * 128 + 64 * 128)        // 24 KB
#define SMEM_QKV (3 * BUF_N128_B1)                // 96 KB
#define SMEM_OUT (2 * BUF_N128_B2)                // 96 KB
#define SMEM_SC  (BUF_N128_B1)                    // 32 KB (nkc=1)
#define SMEM_PV  (3 * BUF_N64_B1)                 // 72 KB

// ---------------------------------------------------------------------------
// QKV projection (z selects Q/K/V). BM=128, BN=128 (two heads per block).
// Plain fp16 GEMM (1 MMA/tile). Q gain folded; V emits fp32.
// ---------------------------------------------------------------------------
__global__ __launch_bounds__(256, 2) void gemm_qkv(
    const float* __restrict__ bq, const float* __restrict__ bk,
    const float* __restrict__ bv)
{
    extern __shared__ char smem[];
    const int z = blockIdx.z;
    const int n0 = blockIdx.x * 128, m0 = blockIdx.y * 128;
    const float* bias = (z == 0) ? bq : (z == 1) ? bk : bv;

    float c[16][4];
#pragma unroll
    for (int i = 0; i < 16; i++)
#pragma unroll
        for (int j = 0; j < 4; j++) c[i][j] = 0.f;

    split_mainloop<128, 1, 1, 3>(g_Xh + (size_t)m0 * Hh, nullptr, Hh,
                                 g_Wh[z] + (size_t)n0 * Hh, nullptr, Hh,
                                 16, smem, c);

    const int lane = threadIdx.x & 31, wid = threadIdx.x >> 5;
    const int g = lane >> 2, t = lane & 3;
    const int m_base = (wid & 3) * 32, n_base = (wid >> 2) * 64;
#pragma unroll
    for (int mt = 0; mt < 2; mt++)
#pragma unroll
        for (int nt = 0; nt < 8; nt++)
#pragma unroll
            for (int half = 0; half < 2; half++) {
                int m = m0 + m_base + mt * 16 + g + half * 8;
                int n = n0 + n_base + nt * 8 + 2 * t;
                float vx = c[mt * 8 + nt][half * 2 + 0] + bias[n];
                float vy = c[mt * 8 + nt][half * 2 + 1] + bias[n + 1];
                int h = n >> 6, d = n & 63;
                int bidx = m >> 11, srow = m & (Ss - 1);
                size_t base = (((size_t)(bidx * NHh + h)) * Ss + srow) * HDd + d;
                if (z == 2) {
                    *(float2*)(g_V + base) = make_float2(vx, vy);
                } else if (z == 0) {
                    float gs = g_gain[(size_t)m * NHh + h];
                    vx *= gs; vy *= gs;
                    *(__half2*)(g_Qh + base) =
                        __halves2half2(__float2half_rn(vx), __float2half_rn(vy));
                } else {
                    *(__half2*)(g_Kh + base) =
                        __halves2half2(__float2half_rn(vx), __float2half_rn(vy));
                }
            }
}

// ---------------------------------------------------------------------------
// Output projection: fp16 ctx @ o_w + o_b -> d_out[:B*S*H] (fp32). 2 MMAs.
// BN=128, NS=2.
// ---------------------------------------------------------------------------
__global__ __launch_bounds__(256, 2) void gemm_out(
    const float* __restrict__ bias, float* __restrict__ out)
{
    extern __shared__ char smem[];
    const int n0 = blockIdx.x * 128, m0 = blockIdx.y * 128;

    float c[16][4];
#pragma unroll
    for (int i = 0; i < 16; i++)
#pragma unroll
        for (int j = 0; j < 4; j++) c[i][j] = 0.f;

    split_mainloop<128, 1, 2, 2>(g_Ch + (size_t)m0 * Hh, nullptr, Hh,
                                 g_Wh[3] + (size_t)n0 * Hh, g_Wl + (size_t)n0 * Hh, Hh,
                                 16, smem, c);

    const int lane = threadIdx.x & 31, wid = threadIdx.x >> 5;
    const int g = lane >> 2, t = lane & 3;
    const int m_base = (wid & 3) * 32, n_base = (wid >> 2) * 64;
#pragma unroll
    for (int mt = 0; mt < 2; mt++)
#pragma unroll
        for (int nt = 0; nt < 8; nt++)
#pragma unroll
            for (int half = 0; half < 2; half++) {
                int m = m0 + m_base + mt * 16 + g + half * 8;
                int n = n0 + n_base + nt * 8 + 2 * t;
                float2 v = make_float2(c[mt * 8 + nt][half * 2] + bias[n],
                                       c[mt * 8 + nt][half * 2 + 1] + bias[n + 1]);
                *(float2*)(out + (size_t)m * Hh + n) = v;
            }
}

// ---------------------------------------------------------------------------
// Scores: 128 q-rows x 128 k-cols per block; 1-MMA (Qh*Kh).
// kt > qt tiles zero-fill; diagonal tile masks per element.
// ---------------------------------------------------------------------------
__global__ __launch_bounds__(256, 2) void scores_mma(float* __restrict__ attn)
{
    extern __shared__ char smem[];
    const int kt = blockIdx.x, qt = blockIdx.y, bh = blockIdx.z;
    const int q0 = qt * 128, k0 = kt * 128;
    float* abase = attn + (size_t)bh * Ss * Ss;

    if (kt > qt) {
        float4 z4 = make_float4(0.f, 0.f, 0.f, 0.f);
        for (int idx = threadIdx.x; idx < 128 * 32; idx += 256) {
            int row = idx >> 5, cc = idx & 31;
            *(float4*)(abase + (size_t)(q0 + row) * Ss + k0 + cc * 4) = z4;
        }
        return;
    }

    float c[16][4];
#pragma unroll
    for (int i = 0; i < 16; i++)
#pragma unroll
        for (int j = 0; j < 4; j++) c[i][j] = 0.f;

    size_t qoff = ((size_t)bh * Ss + q0) * HDd;
    size_t koff = ((size_t)bh * Ss + k0) * HDd;
    split_mainloop<128, 1, 1, 2>(g_Qh + qoff, nullptr, HDd,
                                 g_Kh + koff, nullptr, HDd, 1, smem, c);

    const int lane = threadIdx.x & 31, wid = threadIdx.x >> 5;
    const int g = lane >> 2, t = lane & 3;
    const int m_base = (wid & 3) * 32, n_base = (wid >> 2) * 64;
    const bool diag = (kt == qt);
#pragma unroll
    for (int mt = 0; mt < 2; mt++)
#pragma unroll
        for (int nt = 0; nt < 8; nt++)
#pragma unroll
            for (int half = 0; half < 2; half++) {
                int gi = q0 + m_base + mt * 16 + g + half * 8;
                int gj = k0 + n_base + nt * 8 + 2 * t;
                float vx = c[mt * 8 + nt][half * 2];
                float vy = c[mt * 8 + nt][half * 2 + 1];
                if (diag) {
                    if (gj > gi) vx = 0.f;
                    if (gj + 1 > gi) vy = 0.f;
                }
                *(float2*)(abase + (size_t)gi * Ss + gj) = make_float2(vx, vy);
            }
}

// ---------------------------------------------------------------------------
// Softmax over j<=i. float4 loads/stores, shfl warp reductions, 2 barriers.
// Writes fp32 weights (d_out) + fp16 prob plane.
// ---------------------------------------------------------------------------
__global__ __launch_bounds__(256) void softmax_kernel(float* __restrict__ attn)
{
    int i = blockIdx.x, h = blockIdx.y, b = blockIdx.z;
    size_t roff = ((size_t)(b * NHh + h) * Ss + i) * Ss;
    float* row = attn + roff;
    __half* prh = g_Ph + roff;
    const int n = i + 1;
    const int n4 = n & ~3;
    const int tail = n - n4;
    const int tid = threadIdx.x, lane = tid & 31, wrp = tid >> 5;

    float vals[9];
    int cnt = 0;
    float mx = -INFINITY;
    for (int j = tid * 4; j < n4; j += 1024) {
        float4 v = *(const float4*)(row + j);
        vals[cnt++] = v.x; vals[cnt++] = v.y; vals[cnt++] = v.z; vals[cnt++] = v.w;
        mx = fmaxf(mx, fmaxf(fmaxf(v.x, v.y), fmaxf(v.z, v.w)));
    }
    if (tid < tail) {
        float s = row[n4 + tid];
        vals[cnt++] = s;
        mx = fmaxf(mx, s);
    }

#pragma unroll
    for (int o = 16; o; o >>= 1) mx = fmaxf(mx, __shfl_xor_sync(0xffffffffu, mx, o));
    __shared__ float rmax[8], rsum[8];
    if (lane == 0) rmax[wrp] = mx;
    __syncthreads();
    mx = rmax[0];
#pragma unroll
    for (int w = 1; w < 8; w++) mx = fmaxf(mx, rmax[w]);

    float sum = 0.f;
    for (int c2 = 0; c2 < cnt; c2++) {
        vals[c2] = __expf(vals[c2] - mx);
        sum += vals[c2];
    }
#pragma unroll
    for (int o = 16; o; o >>= 1) sum += __shfl_xor_sync(0xffffffffu, sum, o);
    if (lane == 0) rsum[wrp] = sum;
    __syncthreads();
    sum = 0.f;
#pragma unroll
    for (int w = 0; w < 8; w++) sum += rsum[w];
    float inv = 1.0f / sum;

    cnt = 0;
    for (int j = tid * 4; j < n4; j += 1024) {
        float4 v;
        v.x = vals[cnt++] * inv; v.y = vals[cnt++] * inv;
        v.z = vals[cnt++] * inv; v.w = vals[cnt++] * inv;
        *(float4*)(row + j) = v;
        *(__half2*)(prh + j)     = __halves2half2(__float2half_rn(v.x), __float2half_rn(v.y));
        *(__half2*)(prh + j + 2) = __halves2half2(__float2half_rn(v.z), __float2half_rn(v.w));
    }
    if (tid < tail) {
        float p = vals[cnt++] * inv;
        row[n4 + tid] = p;
        prh[n4 + tid] = __float2half_rn(p);
    }
}

// ---------------------------------------------------------------------------
// V transpose: g_V[bh][s][d] -> VTh[bh][d][s] (fp16 hi only)
// ---------------------------------------------------------------------------
__global__ __launch_bounds__(256) void vt_kernel()
{
    int bh = blockIdx.z;
    const float* V = g_V + (size_t)bh * Ss * HDd;
    __half* VTh = g_VTh + (size_t)bh * HDd * Ss;
    __shared__ float t[32][33];
    int s0 = blockIdx.x * 32, d0 = blockIdx.y * 32;
    int tx = threadIdx.x & 31, ty = threadIdx.x >> 5;
#pragma unroll
    for (int i = 0; i < 4; i++)
        t[ty + i * 8][tx] = V[(size_t)(s0 + ty + i * 8) * HDd + d0 + tx];
    __syncthreads();
#pragma unroll
    for (int i = 0; i < 4; i++)
        VTh[(size_t)(d0 + ty + i * 8) * Ss + s0 + tx] =
            __float2half_rn(t[tx][ty + i * 8]);
}

// ---------------------------------------------------------------------------
// PV: ctx = probs @ V (causal). Single-plane both sides -> 1 MMA per tile.
// ---------------------------------------------------------------------------
__global__ __launch_bounds__(256, 2) void pv_mma()
{
    extern __shared__ char smem[];
    const int qt = blockIdx.x, bh = blockIdx.y;
    const int q0 = qt * 128;
    const int b = bh >> 4, h = bh & 15;

    float c[8][4];
#pragma unroll
    for (int i = 0; i < 8; i++)
#pragma unroll
        for (int j = 0; j < 4; j++) c[i][j] = 0.f;

    size_t poff = ((size_t)bh * Ss + q0) * Ss;
    size_t voff = (size_t)bh * HDd * Ss;
    split_mainloop<64, 1, 1, 3>(g_Ph + poff, nullptr, Ss,
                                g_VTh + voff, nullptr, Ss,
                                (qt + 1) * 2, smem, c);

    const int lane = threadIdx.x & 31, wid = threadIdx.x >> 5;
    const int g = lane >> 2, t = lane & 3;
    const int m_base = (wid & 3) * 32, n_base = (wid >> 2) * 32;
#pragma unroll
    for (int mt = 0; mt < 2; mt++)
#pragma unroll
        for (int nt = 0; nt < 4; nt++)
#pragma unroll
            for (int half = 0; half < 2; half++) {
                int m = q0 + m_base + mt * 16 + g + half * 8;
                int d = n_base + nt * 8 + 2 * t;
                __half hx = __float2half_rn(c[mt * 4 + nt][half * 2]);
                __half hy = __float2half_rn(c[mt * 4 + nt][half * 2 + 1]);
                size_t base = ((size_t)b * Ss + m) * Hh + h * 64 + d;
                *(__half2*)(g_Ch + base) = __halves2half2(hx, hy);
            }
}

// ---------------------------------------------------------------------------
// Prep: X fp16 plane; weight transpose (+ lo plane for o_w only).
// ---------------------------------------------------------------------------
__global__ __launch_bounds__(256) void x_conv(const float* __restrict__ hs)
{
    size_t i = ((size_t)blockIdx.x * 256 + threadIdx.x) * 4;
    float4 v = *(const float4*)(hs + i);
    *(__half2*)(g_Xh + i)     = __halves2half2(__float2half_rn(v.x), __float2half_rn(v.y));
    *(__half2*)(g_Xh + i + 2) = __halves2half2(__float2half_rn(v.z), __float2half_rn(v.w));
}

__global__ __launch_bounds__(256) void wt_kernel(
    const float* __restrict__ qw, const float* __restrict__ kw,
    const float* __restrict__ vw, const float* __restrict__ ow)
{
    int w = blockIdx.z;
    const float* W = (w == 0) ? qw : (w == 1) ? kw : (w == 2) ? vw : ow;
    __half* WTh = g_Wh[w];
    __shared__ float t[32][33];
    int n0 = blockIdx.x * 32, k0 = blockIdx.y * 32;
    int tx = threadIdx.x & 31, ty = threadIdx.x >> 5;
#pragma unroll
    for (int i = 0; i < 4; i++)
        t[ty + i * 8][tx] = W[(size_t)(k0 + ty + i * 8) * Hh + n0 + tx];
    __syncthreads();
#pragma unroll
    for (int i = 0; i < 4; i++) {
        float x = t[tx][ty + i * 8];
        __half h, l;
        split_f(x, h, l);
        size_t idx = (size_t)(n0 + ty + i * 8) * Hh + k0 + tx;
        WTh[idx] = h;
        if (w == 3) g_Wl[idx] = l;
    }
}

// ---------------------------------------------------------------------------
// Per-(b,s) gating (1/sqrt(HD) folded)
// ---------------------------------------------------------------------------
__global__ __launch_bounds__(256) void gate_kernel(
    const float* __restrict__ hs, const float* __restrict__ pros,
    const float* __restrict__ pg_w, const float* __restrict__ pg_b,
    const float* __restrict__ mg_w, const float* __restrict__ mg_b)
{
    int bs = blockIdx.x;
    const float* x = hs + (size_t)bs * Hh;
    int tid = threadIdx.x, lane = tid & 31, wrp = tid >> 5;

    float part = 0.f;
    for (int i = tid; i < Hh; i += 256) part += x[i] * mg_w[i];
#pragma unroll
    for (int o = 16; o; o >>= 1) part += __shfl_xor_sync(0xffffffffu, part, o);
    __shared__ float red[8];
    if (lane == 0) red[wrp] = part;
    __syncthreads();
    float tot = 0.f;
#pragma unroll
    for (int w = 0; w < 8; w++) tot += red[w];
    float mem = 1.0f + 0.5f / (1.0f + __expf(-(tot + mg_b[0])));

    if (tid < NHh) {
        const float* p = pros + (size_t)bs * 4;
        float a = p[0] * pg_w[0 * NHh + tid] + p[1] * pg_w[1 * NHh + tid]
                + p[2] * pg_w[2 * NHh + tid] + p[3] * pg_w[3 * NHh + tid]
                + pg_b[tid];
        float pg = 1.0f + 1.0f / (1.0f + __expf(-a));
        g_gain[(size_t)bs * NHh + tid] = pg * mem * 0.125f;
    }
}

// ---------------------------------------------------------------------------
extern "C" void kernel_launch(void* const* d_in, const int* in_sizes, int n_in,
                              void* d_out, int out_size)
{
    const float* hs   = (const float*)d_in[0];
    const float* pros = (const float*)d_in[1];
    const float* q_w  = (const float*)d_in[2];
    const float* q_b  = (const float*)d_in[3];
    const float* k_w  = (const float*)d_in[4];
    const float* k_b  = (const float*)d_in[5];
    const float* v_w  = (const float*)d_in[6];
    const float* v_b  = (const float*)d_in[7];
    const float* o_w  = (const float*)d_in[8];
    const float* o_b  = (const float*)d_in[9];
    const float* pg_w = (const float*)d_in[10];
    const float* pg_b = (const float*)d_in[11];
    const float* mg_w = (const float*)d_in[12];
    const float* mg_b = (const float*)d_in[13];

    float* out  = (float*)d_out;
    float* attn = out + (size_t)Bb * Ss * Hh;

    static int attr_done = 0;
    if (!attr_done) {
        cudaFuncSetAttribute(gemm_qkv,   cudaFuncAttributeMaxDynamicSharedMemorySize, SMEM_QKV);
        cudaFuncSetAttribute(gemm_out,   cudaFuncAttributeMaxDynamicSharedMemorySize, SMEM_OUT);
        cudaFuncSetAttribute(scores_mma, cudaFuncAttributeMaxDynamicSharedMemorySize, SMEM_SC);
        cudaFuncSetAttribute(pv_mma,     cudaFuncAttributeMaxDynamicSharedMemorySize, SMEM_PV);
        attr_done = 1;
    }

    gate_kernel<<<Bb * Ss, 256>>>(hs, pros, pg_w, pg_b, mg_w, mg_b);
    x_conv<<<(Mtot * Hh) / (256 * 4), 256>>>(hs);
    wt_kernel<<<dim3(32, 32, 4), 256>>>(q_w, k_w, v_w, o_w);

    gemm_qkv<<<dim3(8, 32, 3), 256, SMEM_QKV>>>(q_b, k_b, v_b);
    vt_kernel<<<dim3(64, 2, 32), 256>>>();

    scores_mma<<<dim3(16, 16, 32), 256, SMEM_SC>>>(attn);
    softmax_kernel<<<dim3(Ss, NHh, Bb), 256>>>(attn);
    pv_mma<<<dim3(16, 32), 256, SMEM_PV>>>();

    gemm_out<<<dim3(8, 32), 256, SMEM_OUT>>>(o_b, out);
}